// round 3
// baseline (speedup 1.0000x reference)
#include <cuda_runtime.h>
#include <math_constants.h>

// Problem constants
#define Bq 4
#define Tq 2048
#define Cq 1024
#define Hq 16
#define Dq 64
#define BHq (Bq*Hq)

// Scratch (device globals: allocation-free, harness-sanctioned)
__device__ float g_q[(size_t)BHq*Tq*Dq];          // 32 MB  [BH, T, D]
__device__ float g_k[(size_t)BHq*Tq*Dq];          // 32 MB
__device__ float g_v[(size_t)BHq*Tq*Dq];          // 32 MB
__device__ float g_s[(size_t)BHq*Tq*Tq];          // 1 GB   [BH, T, T]
__device__ float g_ctx[(size_t)Bq*Tq*Cq];         // 32 MB  [B, T, C]
__device__ int   g_len[Bq];

// ---------------------------------------------------------------------------
// Length kernel: robust to padding_mask being bool(u8), int32, or float32.
// mask[b, t] = (t < len[b]) with len >= T/2, so mask[1] == 1 always:
//   u8 layout   -> byte[1] == 1
//   int32 layout-> byte[1] == 0, first word == 1
//   f32 layout  -> byte[1] == 0, first word == 0x3F800000
// ---------------------------------------------------------------------------
__global__ void len_kernel(const unsigned char* __restrict__ mraw) {
    __shared__ int code;
    __shared__ int partial[256];
    if (threadIdx.x == 0) {
        if (mraw[1] == 1) code = 0;                       // u8 / bool
        else if (((const int*)mraw)[0] == 1) code = 1;    // int32
        else code = 2;                                    // float32
    }
    __syncthreads();
    const int c = code;
    const int b = blockIdx.x;
    int cnt = 0;
    for (int t = threadIdx.x; t < Tq; t += blockDim.x) {
        int idx = b * Tq + t;
        bool m;
        if (c == 0)      m = mraw[idx] != 0;
        else if (c == 1) m = ((const int*)mraw)[idx] != 0;
        else             m = ((const float*)mraw)[idx] != 0.0f;
        cnt += m ? 1 : 0;
    }
    partial[threadIdx.x] = cnt;
    __syncthreads();
    for (int s = 128; s > 0; s >>= 1) {
        if (threadIdx.x < s) partial[threadIdx.x] += partial[threadIdx.x + s];
        __syncthreads();
    }
    if (threadIdx.x == 0) g_len[b] = partial[0];
}

// ---------------------------------------------------------------------------
// Generic register-blocked SGEMM.
//   MODE 0: C = x @ w_qkv, epilogue scatters into g_q/g_k/g_v [BH,T,D]
//   MODE 1: per-z (bh): S = 0.125 * Q @ K^T   (B transposed / NT)
//   MODE 2: per-z (bh): O = P @ V, epilogue writes g_ctx [B,T,C]
//   MODE 3: out = g_ctx @ w_out + b_out
// A is MxK row-major. B is KxN row-major unless BT (then NxK row-major).
// All dims divide tile sizes exactly for this problem.
// ---------------------------------------------------------------------------
template<int MODE, int BM, int BN, int BK, int TM, int TN, bool BT>
__global__ void __launch_bounds__((BM/TM)*(BN/TN))
gemm_kernel(const float* __restrict__ Ag, const float* __restrict__ Bg,
            float* __restrict__ Cg, const float* __restrict__ bias,
            int M, int N, int K)
{
    constexpr int THREADS = (BM/TM)*(BN/TN);
    __shared__ float As[BK][BM];
    __shared__ float Bs[BK][BN];

    const int z = blockIdx.z;
    const float* A;
    const float* Bm;
    if (MODE == 0)      { A = Ag;                         Bm = Bg; }
    else if (MODE == 1) { A = g_q + (size_t)z*Tq*Dq;      Bm = g_k + (size_t)z*Tq*Dq; }
    else if (MODE == 2) { A = g_s + (size_t)z*Tq*Tq;      Bm = g_v + (size_t)z*Tq*Dq; }
    else                { A = g_ctx;                      Bm = Bg; }

    const int lda = K;
    const int ldb = BT ? K : N;

    const int tid     = threadIdx.x;
    const int block_m = blockIdx.y * BM;
    const int block_n = blockIdx.x * BN;
    const int tx = tid % (BN/TN);
    const int ty = tid / (BN/TN);

    float acc[TM][TN];
    #pragma unroll
    for (int i = 0; i < TM; i++)
        #pragma unroll
        for (int j = 0; j < TN; j++) acc[i][j] = 0.0f;

    for (int k0 = 0; k0 < K; k0 += BK) {
        // --- load A tile (transposed into smem) ---
        constexpr int AF4 = BM*BK/4;
        #pragma unroll
        for (int i = tid; i < AF4; i += THREADS) {
            int r = i / (BK/4);
            int c = i % (BK/4);
            float4 v = *(const float4*)(A + (size_t)(block_m + r)*lda + k0 + c*4);
            As[c*4+0][r] = v.x; As[c*4+1][r] = v.y;
            As[c*4+2][r] = v.z; As[c*4+3][r] = v.w;
        }
        // --- load B tile ---
        constexpr int BF4 = BK*BN/4;
        if (!BT) {
            #pragma unroll
            for (int i = tid; i < BF4; i += THREADS) {
                int r = i / (BN/4);
                int c = i % (BN/4);
                *(float4*)&Bs[r][c*4] =
                    *(const float4*)(Bm + (size_t)(k0 + r)*ldb + block_n + c*4);
            }
        } else {
            #pragma unroll
            for (int i = tid; i < BF4; i += THREADS) {
                int r = i / (BK/4);   // n within tile
                int c = i % (BK/4);   // k quad
                float4 v = *(const float4*)(Bm + (size_t)(block_n + r)*ldb + k0 + c*4);
                Bs[c*4+0][r] = v.x; Bs[c*4+1][r] = v.y;
                Bs[c*4+2][r] = v.z; Bs[c*4+3][r] = v.w;
            }
        }
        __syncthreads();

        // --- compute ---
        #pragma unroll
        for (int kk = 0; kk < BK; kk++) {
            float a[TM], b[TN];
            #pragma unroll
            for (int i = 0; i < TM/4; i++) {
                float4 v = *(const float4*)&As[kk][ty*TM + i*4];
                a[i*4+0]=v.x; a[i*4+1]=v.y; a[i*4+2]=v.z; a[i*4+3]=v.w;
            }
            #pragma unroll
            for (int j = 0; j < TN/4; j++) {
                float4 v = *(const float4*)&Bs[kk][tx*TN + j*4];
                b[j*4+0]=v.x; b[j*4+1]=v.y; b[j*4+2]=v.z; b[j*4+3]=v.w;
            }
            #pragma unroll
            for (int i = 0; i < TM; i++)
                #pragma unroll
                for (int j = 0; j < TN; j++)
                    acc[i][j] = fmaf(a[i], b[j], acc[i][j]);
        }
        __syncthreads();
    }

    // --- epilogue ---
    #pragma unroll
    for (int i = 0; i < TM; i++) {
        int m = block_m + ty*TM + i;
        #pragma unroll
        for (int j = 0; j < TN; j++) {
            int n = block_n + tx*TN + j;
            float v = acc[i][j];
            if (MODE == 0) {
                int bb = m / Tq, t = m % Tq;
                int part = n >> 10, hh = (n & 1023) >> 6, d = n & 63;
                size_t idx = ((size_t)(bb*Hq + hh)*Tq + t)*Dq + d;
                float* dst = (part == 0) ? g_q : (part == 1) ? g_k : g_v;
                dst[idx] = v;
            } else if (MODE == 1) {
                g_s[(size_t)z*Tq*Tq + (size_t)m*Tq + n] = v * 0.125f;  // D^-0.5
            } else if (MODE == 2) {
                int bb = z / Hq, hh = z % Hq;
                g_ctx[((size_t)(bb*Tq + m))*Cq + hh*Dq + n] = v;
            } else {
                Cg[(size_t)m*N + n] = v + bias[n];
            }
        }
    }
}

// ---------------------------------------------------------------------------
// Row softmax over keys with padding mask: masked keys -> probability 0.
// One block (256 threads) per (bh, q) row of length T = 2048.
// ---------------------------------------------------------------------------
__global__ void softmax_kernel() {
    const int row = blockIdx.x;          // [0, BH*T)
    const int bh  = row / Tq;
    const int b   = bh / Hq;
    const int len = g_len[b];
    float* p = g_s + (size_t)row * Tq;
    const int tid = threadIdx.x;
    constexpr int PER = Tq / 256;        // 8

    float vals[PER];
    float mx = -CUDART_INF_F;
    #pragma unroll
    for (int i = 0; i < PER; i++) {
        int n = tid + i*256;
        float x = (n < len) ? p[n] : -CUDART_INF_F;
        vals[i] = x;
        mx = fmaxf(mx, x);
    }
    __shared__ float red[8];
    #pragma unroll
    for (int o = 16; o > 0; o >>= 1) mx = fmaxf(mx, __shfl_xor_sync(0xffffffffu, mx, o));
    if ((tid & 31) == 0) red[tid >> 5] = mx;
    __syncthreads();
    float rowmax = fmaxf(fmaxf(fmaxf(red[0],red[1]), fmaxf(red[2],red[3])),
                         fmaxf(fmaxf(red[4],red[5]), fmaxf(red[6],red[7])));
    __syncthreads();

    float sum = 0.0f;
    #pragma unroll
    for (int i = 0; i < PER; i++) {
        int n = tid + i*256;
        float e = (n < len) ? __expf(vals[i] - rowmax) : 0.0f;
        vals[i] = e;
        sum += e;
    }
    #pragma unroll
    for (int o = 16; o > 0; o >>= 1) sum += __shfl_xor_sync(0xffffffffu, sum, o);
    if ((tid & 31) == 0) red[tid >> 5] = sum;
    __syncthreads();
    float tot = (red[0]+red[1])+(red[2]+red[3])+(red[4]+red[5])+(red[6]+red[7]);
    float inv = 1.0f / tot;
    #pragma unroll
    for (int i = 0; i < PER; i++)
        p[tid + i*256] = vals[i] * inv;
}

// ---------------------------------------------------------------------------
extern "C" void kernel_launch(void* const* d_in, const int* in_sizes, int n_in,
                              void* d_out, int out_size)
{
    const float*         x     = (const float*)d_in[0];
    const unsigned char* mask  = (const unsigned char*)d_in[1];
    const float*         w_qkv = (const float*)d_in[2];
    const float*         w_out = (const float*)d_in[3];
    const float*         b_out = (const float*)d_in[4];
    float*               out   = (float*)d_out;

    // 1. lengths from padding mask (dtype-robust)
    len_kernel<<<Bq, 256>>>(mask);

    // 2. QKV projection: [8192,1024] @ [1024,3072] -> Q/K/V [BH,T,D]
    gemm_kernel<0,128,128,8,8,8,false>
        <<<dim3(3*Cq/128, Bq*Tq/128), 256>>>(x, w_qkv, nullptr, nullptr,
                                             Bq*Tq, 3*Cq, Cq);

    // 3. Scores: per bh, S = 0.125 * Q @ K^T   [2048,2048], K-dim 64 (NT)
    gemm_kernel<1,128,128,8,8,8,true>
        <<<dim3(Tq/128, Tq/128, BHq), 256>>>(nullptr, nullptr, nullptr, nullptr,
                                             Tq, Tq, Dq);

    // 4. Masked row softmax
    softmax_kernel<<<BHq*Tq, 256>>>();

    // 5. PV: per bh, O = P @ V  [2048,64], K-dim 2048 -> g_ctx [B,T,C]
    gemm_kernel<2,128,64,8,8,4,false>
        <<<dim3(1, Tq/128, BHq), 256>>>(nullptr, nullptr, nullptr, nullptr,
                                        Tq, Dq, Tq);

    // 6. Output projection + bias: [8192,1024] @ [1024,1024] + b
    gemm_kernel<3,128,128,8,8,8,false>
        <<<dim3(Cq/128, Bq*Tq/128), 256>>>(nullptr, w_out, out, b_out,
                                           Bq*Tq, Cq, Cq);
}

// round 4
// speedup vs baseline: 1.7022x; 1.7022x over previous
#include <cuda_runtime.h>
#include <cuda_bf16.h>
#include <math_constants.h>
#include <stdint.h>

// Problem constants
#define Bq 4
#define Tq 2048
#define Cq 1024
#define Hq 16
#define Dq 64
#define BHq (Bq*Hq)

// Scratch (device globals: allocation-free, harness-sanctioned)
__device__ float g_q[(size_t)BHq*Tq*Dq];          // 32 MB  [BH, T, D]
__device__ float g_k[(size_t)BHq*Tq*Dq];          // 32 MB
__device__ float g_v[(size_t)BHq*Tq*Dq];          // 32 MB
__device__ float g_s[(size_t)BHq*Tq*Tq];          // 1 GB   [BH, T, T]
__device__ float g_ctx[(size_t)Bq*Tq*Cq];         // 32 MB  [B, T, C]
__device__ int   g_len[Bq];

// ---------------------------------------------------------------------------
// Length kernel: robust to padding_mask being bool(u8), int32, or float32.
// ---------------------------------------------------------------------------
__global__ void len_kernel(const unsigned char* __restrict__ mraw) {
    __shared__ int code;
    __shared__ int partial[256];
    if (threadIdx.x == 0) {
        if (mraw[1] == 1) code = 0;                       // u8 / bool
        else if (((const int*)mraw)[0] == 1) code = 1;    // int32
        else code = 2;                                    // float32
    }
    __syncthreads();
    const int c = code;
    const int b = blockIdx.x;
    int cnt = 0;
    for (int t = threadIdx.x; t < Tq; t += blockDim.x) {
        int idx = b * Tq + t;
        bool m;
        if (c == 0)      m = mraw[idx] != 0;
        else if (c == 1) m = ((const int*)mraw)[idx] != 0;
        else             m = ((const float*)mraw)[idx] != 0.0f;
        cnt += m ? 1 : 0;
    }
    partial[threadIdx.x] = cnt;
    __syncthreads();
    for (int s = 128; s > 0; s >>= 1) {
        if (threadIdx.x < s) partial[threadIdx.x] += partial[threadIdx.x + s];
        __syncthreads();
    }
    if (threadIdx.x == 0) g_len[b] = partial[0];
}

// ---------------------------------------------------------------------------
// mma.sync.m16n8k16 bf16 with fp32 accumulate
// ---------------------------------------------------------------------------
__device__ __forceinline__ void mma16816(float* d, const uint32_t* a, const uint32_t* b) {
    asm volatile(
        "mma.sync.aligned.m16n8k16.row.col.f32.bf16.bf16.f32 "
        "{%0,%1,%2,%3}, {%4,%5,%6,%7}, {%8,%9}, {%0,%1,%2,%3};\n"
        : "+f"(d[0]), "+f"(d[1]), "+f"(d[2]), "+f"(d[3])
        : "r"(a[0]), "r"(a[1]), "r"(a[2]), "r"(a[3]),
          "r"(b[0]), "r"(b[1]));
}

__device__ __forceinline__ void split_bf16(float x, __nv_bfloat16& hi, __nv_bfloat16& lo) {
    hi = __float2bfloat16(x);
    lo = __float2bfloat16(x - __bfloat162float(hi));
}

// ---------------------------------------------------------------------------
// Tensor-core split-bf16 GEMM (3-pass: AhBh + AhBl + AlBh ~= fp32 accuracy).
//   MODE 0: C = x @ w_qkv, epilogue scatters into g_q/g_k/g_v [BH,T,D]
//   MODE 1: per-z (bh): S = 0.125 * Q @ K^T   (B source n-major)
//   MODE 2: per-z (bh): O = P @ V, epilogue writes g_ctx [B,T,C]
//   MODE 3: out = g_ctx @ w_out + b_out
// A is MxK row-major. B source is KxN row-major unless B_NMAJOR (then NxK).
// BK = 32. 8 warps, warp grid WARPS_M x WARPS_N.
// ---------------------------------------------------------------------------
template<int MODE, int BM, int BN, int WARPS_M, int WARPS_N, bool B_NMAJOR>
__global__ void __launch_bounds__(256)
mma_gemm(const float* __restrict__ Ag, const float* __restrict__ Bg,
         float* __restrict__ Cg, const float* __restrict__ bias,
         int M, int N, int K)
{
    constexpr int BK  = 32;
    constexpr int WTM = BM / WARPS_M;        // 64
    constexpr int WTN = BN / WARPS_N;        // 32 (16 for mode2)
    constexpr int MT  = WTM / 16;
    constexpr int NT  = WTN / 8;
    constexpr int PITCH = 34;                // bf16 elems per row (odd-word pad)

    __shared__ __nv_bfloat16 As_hi[BM][PITCH];
    __shared__ __nv_bfloat16 As_lo[BM][PITCH];
    __shared__ __nv_bfloat16 Bs_hi[BN][PITCH];
    __shared__ __nv_bfloat16 Bs_lo[BN][PITCH];

    const int z = blockIdx.z;
    const float* A;
    const float* Bm;
    if (MODE == 0)      { A = Ag;                         Bm = Bg; }
    else if (MODE == 1) { A = g_q + (size_t)z*Tq*Dq;      Bm = g_k + (size_t)z*Tq*Dq; }
    else if (MODE == 2) { A = g_s + (size_t)z*Tq*Tq;      Bm = g_v + (size_t)z*Tq*Dq; }
    else                { A = g_ctx;                      Bm = Bg; }

    const int lda = K;
    const int ldb = B_NMAJOR ? K : N;

    const int tid  = threadIdx.x;
    const int lane = tid & 31;
    const int warp = tid >> 5;
    const int wm   = warp / WARPS_N;
    const int wn   = warp % WARPS_N;
    const int block_m = blockIdx.y * BM;
    const int block_n = blockIdx.x * BN;

    float acc[MT][NT][4];
    #pragma unroll
    for (int i = 0; i < MT; i++)
        #pragma unroll
        for (int j = 0; j < NT; j++)
            #pragma unroll
            for (int r = 0; r < 4; r++) acc[i][j][r] = 0.0f;

    for (int k0 = 0; k0 < K; k0 += BK) {
        // ---- fill A tile (row-major source, split to hi/lo bf16) ----
        #pragma unroll
        for (int i = tid; i < BM * (BK/4); i += 256) {
            int r = i >> 3, c = i & 7;
            float4 v = *(const float4*)(A + (size_t)(block_m + r)*lda + k0 + c*4);
            __nv_bfloat16 h0,h1,h2,h3,l0,l1,l2,l3;
            split_bf16(v.x, h0, l0); split_bf16(v.y, h1, l1);
            split_bf16(v.z, h2, l2); split_bf16(v.w, h3, l3);
            *(__nv_bfloat162*)&As_hi[r][c*4]   = __halves2bfloat162(h0, h1);
            *(__nv_bfloat162*)&As_hi[r][c*4+2] = __halves2bfloat162(h2, h3);
            *(__nv_bfloat162*)&As_lo[r][c*4]   = __halves2bfloat162(l0, l1);
            *(__nv_bfloat162*)&As_lo[r][c*4+2] = __halves2bfloat162(l2, l3);
        }
        // ---- fill B tile ----
        if (B_NMAJOR) {
            #pragma unroll
            for (int i = tid; i < BN * (BK/4); i += 256) {
                int r = i >> 3, c = i & 7;
                float4 v = *(const float4*)(Bm + (size_t)(block_n + r)*ldb + k0 + c*4);
                __nv_bfloat16 h0,h1,h2,h3,l0,l1,l2,l3;
                split_bf16(v.x, h0, l0); split_bf16(v.y, h1, l1);
                split_bf16(v.z, h2, l2); split_bf16(v.w, h3, l3);
                *(__nv_bfloat162*)&Bs_hi[r][c*4]   = __halves2bfloat162(h0, h1);
                *(__nv_bfloat162*)&Bs_hi[r][c*4+2] = __halves2bfloat162(h2, h3);
                *(__nv_bfloat162*)&Bs_lo[r][c*4]   = __halves2bfloat162(l0, l1);
                *(__nv_bfloat162*)&Bs_lo[r][c*4+2] = __halves2bfloat162(l2, l3);
            }
        } else {
            // source [k][n] row-major: transpose into Bs[n][k]
            #pragma unroll
            for (int i = tid; i < (BK*BN)/4; i += 256) {
                int r = i / (BN/4), c = i % (BN/4);
                float4 v = *(const float4*)(Bm + (size_t)(k0 + r)*ldb + block_n + c*4);
                int n = c*4;
                __nv_bfloat16 h, l;
                split_bf16(v.x, h, l); Bs_hi[n  ][r] = h; Bs_lo[n  ][r] = l;
                split_bf16(v.y, h, l); Bs_hi[n+1][r] = h; Bs_lo[n+1][r] = l;
                split_bf16(v.z, h, l); Bs_hi[n+2][r] = h; Bs_lo[n+2][r] = l;
                split_bf16(v.w, h, l); Bs_hi[n+3][r] = h; Bs_lo[n+3][r] = l;
            }
        }
        __syncthreads();

        // ---- compute: 2 k16 steps per BK=32 ----
        #pragma unroll
        for (int ks = 0; ks < 2; ks++) {
            const int kb = ks*16 + (lane & 3)*2;
            uint32_t ahi[MT][4], alo[MT][4], bhi[NT][2], blo[NT][2];
            #pragma unroll
            for (int mt = 0; mt < MT; mt++) {
                int m = wm*WTM + mt*16 + (lane >> 2);
                ahi[mt][0] = *(const uint32_t*)&As_hi[m  ][kb];
                ahi[mt][1] = *(const uint32_t*)&As_hi[m+8][kb];
                ahi[mt][2] = *(const uint32_t*)&As_hi[m  ][kb+8];
                ahi[mt][3] = *(const uint32_t*)&As_hi[m+8][kb+8];
                alo[mt][0] = *(const uint32_t*)&As_lo[m  ][kb];
                alo[mt][1] = *(const uint32_t*)&As_lo[m+8][kb];
                alo[mt][2] = *(const uint32_t*)&As_lo[m  ][kb+8];
                alo[mt][3] = *(const uint32_t*)&As_lo[m+8][kb+8];
            }
            #pragma unroll
            for (int nt = 0; nt < NT; nt++) {
                int n = wn*WTN + nt*8 + (lane >> 2);
                bhi[nt][0] = *(const uint32_t*)&Bs_hi[n][kb];
                bhi[nt][1] = *(const uint32_t*)&Bs_hi[n][kb+8];
                blo[nt][0] = *(const uint32_t*)&Bs_lo[n][kb];
                blo[nt][1] = *(const uint32_t*)&Bs_lo[n][kb+8];
            }
            #pragma unroll
            for (int mt = 0; mt < MT; mt++)
                #pragma unroll
                for (int nt = 0; nt < NT; nt++) {
                    mma16816(acc[mt][nt], ahi[mt], bhi[nt]);
                    mma16816(acc[mt][nt], ahi[mt], blo[nt]);
                    mma16816(acc[mt][nt], alo[mt], bhi[nt]);
                }
        }
        __syncthreads();
    }

    // ---- epilogue: each thread owns (m, n), (m, n+1) float2 pairs ----
    #pragma unroll
    for (int mt = 0; mt < MT; mt++) {
        #pragma unroll
        for (int nt = 0; nt < NT; nt++) {
            int m0 = block_m + wm*WTM + mt*16 + (lane >> 2);
            int n0 = block_n + wn*WTN + nt*8 + (lane & 3)*2;
            const float* cr = acc[mt][nt];
            #pragma unroll
            for (int half = 0; half < 2; half++) {
                int m = m0 + half*8;
                float v0 = cr[half*2], v1 = cr[half*2+1];
                if (MODE == 0) {
                    int bb = m / Tq, t = m % Tq;
                    int part = n0 >> 10, hh = (n0 & 1023) >> 6, d = n0 & 63;
                    size_t idx = ((size_t)(bb*Hq + hh)*Tq + t)*Dq + d;
                    float* dst = (part == 0) ? g_q : (part == 1) ? g_k : g_v;
                    *(float2*)&dst[idx] = make_float2(v0, v1);
                } else if (MODE == 1) {
                    *(float2*)&g_s[(size_t)z*Tq*Tq + (size_t)m*Tq + n0] =
                        make_float2(v0*0.125f, v1*0.125f);
                } else if (MODE == 2) {
                    int bb = z / Hq, hh = z % Hq;
                    *(float2*)&g_ctx[((size_t)(bb*Tq + m))*Cq + hh*Dq + n0] =
                        make_float2(v0, v1);
                } else {
                    *(float2*)&Cg[(size_t)m*N + n0] =
                        make_float2(v0 + bias[n0], v1 + bias[n0+1]);
                }
            }
        }
    }
}

// ---------------------------------------------------------------------------
// Row softmax over keys with padding mask (DRAM-bound, already at roofline).
// ---------------------------------------------------------------------------
__global__ void softmax_kernel() {
    const int row = blockIdx.x;          // [0, BH*T)
    const int bh  = row / Tq;
    const int b   = bh / Hq;
    const int len = g_len[b];
    float* p = g_s + (size_t)row * Tq;
    const int tid = threadIdx.x;
    constexpr int PER = Tq / 256;        // 8

    float vals[PER];
    float mx = -CUDART_INF_F;
    #pragma unroll
    for (int i = 0; i < PER; i++) {
        int n = tid + i*256;
        float x = (n < len) ? p[n] : -CUDART_INF_F;
        vals[i] = x;
        mx = fmaxf(mx, x);
    }
    __shared__ float red[8];
    #pragma unroll
    for (int o = 16; o > 0; o >>= 1) mx = fmaxf(mx, __shfl_xor_sync(0xffffffffu, mx, o));
    if ((tid & 31) == 0) red[tid >> 5] = mx;
    __syncthreads();
    float rowmax = fmaxf(fmaxf(fmaxf(red[0],red[1]), fmaxf(red[2],red[3])),
                         fmaxf(fmaxf(red[4],red[5]), fmaxf(red[6],red[7])));
    __syncthreads();

    float sum = 0.0f;
    #pragma unroll
    for (int i = 0; i < PER; i++) {
        int n = tid + i*256;
        float e = (n < len) ? __expf(vals[i] - rowmax) : 0.0f;
        vals[i] = e;
        sum += e;
    }
    #pragma unroll
    for (int o = 16; o > 0; o >>= 1) sum += __shfl_xor_sync(0xffffffffu, sum, o);
    if ((tid & 31) == 0) red[tid >> 5] = sum;
    __syncthreads();
    float tot = (red[0]+red[1])+(red[2]+red[3])+(red[4]+red[5])+(red[6]+red[7]);
    float inv = 1.0f / tot;
    #pragma unroll
    for (int i = 0; i < PER; i++)
        p[tid + i*256] = vals[i] * inv;
}

// ---------------------------------------------------------------------------
extern "C" void kernel_launch(void* const* d_in, const int* in_sizes, int n_in,
                              void* d_out, int out_size)
{
    const float*         x     = (const float*)d_in[0];
    const unsigned char* mask  = (const unsigned char*)d_in[1];
    const float*         w_qkv = (const float*)d_in[2];
    const float*         w_out = (const float*)d_in[3];
    const float*         b_out = (const float*)d_in[4];
    float*               out   = (float*)d_out;

    // 1. lengths from padding mask (dtype-robust)
    len_kernel<<<Bq, 256>>>(mask);

    // 2. QKV projection: [8192,1024] @ [1024,3072] -> Q/K/V [BH,T,D]
    mma_gemm<0,128,128,2,4,false>
        <<<dim3(3*Cq/128, Bq*Tq/128), 256>>>(x, w_qkv, nullptr, nullptr,
                                             Bq*Tq, 3*Cq, Cq);

    // 3. Scores: per bh, S = 0.125 * Q @ K^T   [2048,2048], K-dim 64
    mma_gemm<1,128,128,2,4,true>
        <<<dim3(Tq/128, Tq/128, BHq), 256>>>(nullptr, nullptr, nullptr, nullptr,
                                             Tq, Tq, Dq);

    // 4. Masked row softmax
    softmax_kernel<<<BHq*Tq, 256>>>();

    // 5. PV: per bh, O = P @ V  [2048,64], K-dim 2048 -> g_ctx [B,T,C]
    mma_gemm<2,128,64,2,4,false>
        <<<dim3(1, Tq/128, BHq), 256>>>(nullptr, nullptr, nullptr, nullptr,
                                        Tq, Dq, Tq);

    // 6. Output projection + bias: [8192,1024] @ [1024,1024] + b
    mma_gemm<3,128,128,2,4,false>
        <<<dim3(Cq/128, Bq*Tq/128), 256>>>(nullptr, w_out, out, b_out,
                                           Bq*Tq, Cq, Cq);
}

// round 6
// speedup vs baseline: 1.9690x; 1.1567x over previous
#include <cuda_runtime.h>
#include <cuda_bf16.h>
#include <math_constants.h>
#include <stdint.h>

// Problem constants
#define Bq 4
#define Tq 2048
#define Cq 1024
#define Hq 16
#define Dq 64
#define BHq (Bq*Hq)

#define LOG2E 1.4426950408889634f

// ---------------------------------------------------------------------------
// Scratch (device globals: allocation-free, harness-sanctioned).
// INVARIANT: these symbols are ONLY referenced from device code (host code
// cannot take a __device__ symbol's address — that was the R5 bug).
// ---------------------------------------------------------------------------
__device__ __nv_bfloat16 g_xh[(size_t)Bq*Tq*Cq];        // x split
__device__ __nv_bfloat16 g_xl[(size_t)Bq*Tq*Cq];
__device__ __nv_bfloat16 g_wqh[(size_t)Cq*3*Cq];        // w_qkv split
__device__ __nv_bfloat16 g_wql[(size_t)Cq*3*Cq];
__device__ __nv_bfloat16 g_woh[(size_t)Cq*Cq];          // w_out split
__device__ __nv_bfloat16 g_wol[(size_t)Cq*Cq];
__device__ __nv_bfloat16 g_qh[(size_t)BHq*Tq*Dq];       // Q/K/V split [BH,T,D]
__device__ __nv_bfloat16 g_ql[(size_t)BHq*Tq*Dq];
__device__ __nv_bfloat16 g_kh[(size_t)BHq*Tq*Dq];
__device__ __nv_bfloat16 g_kl[(size_t)BHq*Tq*Dq];
__device__ __nv_bfloat16 g_vh[(size_t)BHq*Tq*Dq];
__device__ __nv_bfloat16 g_vl[(size_t)BHq*Tq*Dq];
__device__ __nv_bfloat16 g_ctxh[(size_t)Bq*Tq*Cq];      // attention output split
__device__ __nv_bfloat16 g_ctxl[(size_t)Bq*Tq*Cq];
__device__ int g_len[Bq];

// ---------------------------------------------------------------------------
__device__ __forceinline__ void mma16816(float* d, const uint32_t* a, const uint32_t* b) {
    asm volatile(
        "mma.sync.aligned.m16n8k16.row.col.f32.bf16.bf16.f32 "
        "{%0,%1,%2,%3}, {%4,%5,%6,%7}, {%8,%9}, {%0,%1,%2,%3};\n"
        : "+f"(d[0]), "+f"(d[1]), "+f"(d[2]), "+f"(d[3])
        : "r"(a[0]), "r"(a[1]), "r"(a[2]), "r"(a[3]),
          "r"(b[0]), "r"(b[1]));
}

// pack two fp32 into bf16x2 hi and lo words (low half = first arg)
__device__ __forceinline__ void pack_split2(float a, float b, uint32_t& hi, uint32_t& lo) {
    __nv_bfloat16 ha = __float2bfloat16(a), hb = __float2bfloat16(b);
    __nv_bfloat16 la = __float2bfloat16(a - __bfloat162float(ha));
    __nv_bfloat16 lb = __float2bfloat16(b - __bfloat162float(hb));
    __nv_bfloat162 h2 = __halves2bfloat162(ha, hb);
    __nv_bfloat162 l2 = __halves2bfloat162(la, lb);
    hi = *reinterpret_cast<uint32_t*>(&h2);
    lo = *reinterpret_cast<uint32_t*>(&l2);
}

// ---------------------------------------------------------------------------
// Split fp32 array -> bf16 hi/lo arrays. Destination chosen in DEVICE code.
//   WHICH 0: x -> g_xh/g_xl      WHICH 1: w_qkv -> g_wqh/g_wql
//   WHICH 2: w_out -> g_woh/g_wol
// ---------------------------------------------------------------------------
template<int WHICH>
__global__ void split_kernel(const float* __restrict__ src, size_t n) {
    __nv_bfloat16* dh = (WHICH == 0) ? g_xh : (WHICH == 1) ? g_wqh : g_woh;
    __nv_bfloat16* dl = (WHICH == 0) ? g_xl : (WHICH == 1) ? g_wql : g_wol;
    size_t i = ((size_t)blockIdx.x * blockDim.x + threadIdx.x) * 4;
    if (i >= n) return;
    float4 v = *(const float4*)(src + i);
    uint32_t h0, l0, h1, l1;
    pack_split2(v.x, v.y, h0, l0);
    pack_split2(v.z, v.w, h1, l1);
    *(uint32_t*)(dh + i)     = h0;
    *(uint32_t*)(dh + i + 2) = h1;
    *(uint32_t*)(dl + i)     = l0;
    *(uint32_t*)(dl + i + 2) = l1;
}

// ---------------------------------------------------------------------------
// Length kernel: robust to padding_mask being bool(u8), int32, or float32.
// ---------------------------------------------------------------------------
__global__ void len_kernel(const unsigned char* __restrict__ mraw) {
    __shared__ int code;
    __shared__ int partial[256];
    if (threadIdx.x == 0) {
        if (mraw[1] == 1) code = 0;
        else if (((const int*)mraw)[0] == 1) code = 1;
        else code = 2;
    }
    __syncthreads();
    const int c = code;
    const int b = blockIdx.x;
    int cnt = 0;
    for (int t = threadIdx.x; t < Tq; t += blockDim.x) {
        int idx = b * Tq + t;
        bool m;
        if (c == 0)      m = mraw[idx] != 0;
        else if (c == 1) m = ((const int*)mraw)[idx] != 0;
        else             m = ((const float*)mraw)[idx] != 0.0f;
        cnt += m ? 1 : 0;
    }
    partial[threadIdx.x] = cnt;
    __syncthreads();
    for (int s = 128; s > 0; s >>= 1) {
        if (threadIdx.x < s) partial[threadIdx.x] += partial[threadIdx.x + s];
        __syncthreads();
    }
    if (threadIdx.x == 0) g_len[b] = partial[0];
}

// ---------------------------------------------------------------------------
// Split-bf16 tensor-core GEMM. A/B operands selected from g_* in device code.
//   MODE 0: qkv = x @ w_qkv   (A=g_x, B=g_wq), epilogue -> g_{q,k,v}{h,l}
//   MODE 3: out = ctx @ w_out + b_out (A=g_ctx, B=g_wo), fp32 out to Cg
// A row-major [M][K] hi/lo; B row-major [K][N] hi/lo.
// BM=BN=128, BK=32, 8 warps (2x4), warp tile 64x32. 3-pass split MMA.
// ---------------------------------------------------------------------------
template<int MODE>
__global__ void __launch_bounds__(256)
mma_gemm_bf(float* __restrict__ Cg, const float* __restrict__ bias,
            int M, int N, int K)
{
    constexpr int BK = 32, PITCH = 40;
    __shared__ __nv_bfloat16 Ash[128*PITCH], Asl[128*PITCH];
    __shared__ __nv_bfloat16 Bsh[128*PITCH], Bsl[128*PITCH];

    const __nv_bfloat16* Agh = (MODE == 0) ? g_xh : g_ctxh;
    const __nv_bfloat16* Agl = (MODE == 0) ? g_xl : g_ctxl;
    const __nv_bfloat16* Bgh = (MODE == 0) ? g_wqh : g_woh;
    const __nv_bfloat16* Bgl = (MODE == 0) ? g_wql : g_wol;

    const int tid  = threadIdx.x;
    const int lane = tid & 31;
    const int warp = tid >> 5;
    const int wm   = warp >> 2;       // 0..1
    const int wn   = warp & 3;        // 0..3
    const int r4   = lane >> 2;
    const int c2   = (lane & 3) * 2;
    const int bm   = blockIdx.y * 128;
    const int bn   = blockIdx.x * 128;

    float acc[4][4][4];
    #pragma unroll
    for (int i = 0; i < 4; i++)
        #pragma unroll
        for (int j = 0; j < 4; j++)
            #pragma unroll
            for (int r = 0; r < 4; r++) acc[i][j][r] = 0.0f;

    for (int k0 = 0; k0 < K; k0 += BK) {
        // A tile: 128x32, uint4 = 8 bf16, 512 chunks
        #pragma unroll
        for (int i = tid; i < 512; i += 256) {
            int r = i >> 2, c = (i & 3) * 8;
            *(uint4*)&Ash[r*PITCH + c] = *(const uint4*)&Agh[(size_t)(bm + r)*K + k0 + c];
            *(uint4*)&Asl[r*PITCH + c] = *(const uint4*)&Agl[(size_t)(bm + r)*K + k0 + c];
        }
        // B tile: transpose [k][n] -> Bs[n][k]
        #pragma unroll
        for (int i = tid; i < 512; i += 256) {
            int r = i >> 4, g = (i & 15) * 8;
            uint4 rawh = *(const uint4*)&Bgh[(size_t)(k0 + r)*N + bn + g];
            uint4 rawl = *(const uint4*)&Bgl[(size_t)(k0 + r)*N + bn + g];
            const __nv_bfloat16* ph = (const __nv_bfloat16*)&rawh;
            const __nv_bfloat16* pl = (const __nv_bfloat16*)&rawl;
            #pragma unroll
            for (int j = 0; j < 8; j++) {
                Bsh[(g + j)*PITCH + r] = ph[j];
                Bsl[(g + j)*PITCH + r] = pl[j];
            }
        }
        __syncthreads();

        #pragma unroll
        for (int ks = 0; ks < 2; ks++) {
            const int kb = ks*16 + c2;
            uint32_t ah[4][4], al[4][4], bh[4][2], bl[4][2];
            #pragma unroll
            for (int mt = 0; mt < 4; mt++) {
                int m = wm*64 + mt*16 + r4;
                ah[mt][0] = *(const uint32_t*)&Ash[m*PITCH + kb];
                ah[mt][1] = *(const uint32_t*)&Ash[(m+8)*PITCH + kb];
                ah[mt][2] = *(const uint32_t*)&Ash[m*PITCH + kb + 8];
                ah[mt][3] = *(const uint32_t*)&Ash[(m+8)*PITCH + kb + 8];
                al[mt][0] = *(const uint32_t*)&Asl[m*PITCH + kb];
                al[mt][1] = *(const uint32_t*)&Asl[(m+8)*PITCH + kb];
                al[mt][2] = *(const uint32_t*)&Asl[m*PITCH + kb + 8];
                al[mt][3] = *(const uint32_t*)&Asl[(m+8)*PITCH + kb + 8];
            }
            #pragma unroll
            for (int nt = 0; nt < 4; nt++) {
                int n = wn*32 + nt*8 + r4;
                bh[nt][0] = *(const uint32_t*)&Bsh[n*PITCH + kb];
                bh[nt][1] = *(const uint32_t*)&Bsh[n*PITCH + kb + 8];
                bl[nt][0] = *(const uint32_t*)&Bsl[n*PITCH + kb];
                bl[nt][1] = *(const uint32_t*)&Bsl[n*PITCH + kb + 8];
            }
            #pragma unroll
            for (int mt = 0; mt < 4; mt++)
                #pragma unroll
                for (int nt = 0; nt < 4; nt++) {
                    mma16816(acc[mt][nt], ah[mt], bh[nt]);
                    mma16816(acc[mt][nt], ah[mt], bl[nt]);
                    mma16816(acc[mt][nt], al[mt], bh[nt]);
                }
        }
        __syncthreads();
    }

    // epilogue
    #pragma unroll
    for (int mt = 0; mt < 4; mt++) {
        #pragma unroll
        for (int nt = 0; nt < 4; nt++) {
            int m0 = bm + wm*64 + mt*16 + r4;
            int n0 = bn + wn*32 + nt*8 + c2;
            const float* cr = acc[mt][nt];
            #pragma unroll
            for (int half = 0; half < 2; half++) {
                int m = m0 + half*8;
                float v0 = cr[half*2], v1 = cr[half*2+1];
                if (MODE == 0) {
                    int bb = m / Tq, t = m % Tq;
                    int part = n0 >> 10, hh = (n0 & 1023) >> 6, d = n0 & 63;
                    size_t idx = ((size_t)(bb*Hq + hh)*Tq + t)*Dq + d;
                    __nv_bfloat16* dsth = (part == 0) ? g_qh : (part == 1) ? g_kh : g_vh;
                    __nv_bfloat16* dstl = (part == 0) ? g_ql : (part == 1) ? g_kl : g_vl;
                    uint32_t hi, lo;
                    pack_split2(v0, v1, hi, lo);
                    *(uint32_t*)(dsth + idx) = hi;
                    *(uint32_t*)(dstl + idx) = lo;
                } else {
                    *(float2*)&Cg[(size_t)m*N + n0] =
                        make_float2(v0 + bias[n0], v1 + bias[n0+1]);
                }
            }
        }
    }
}

// ---------------------------------------------------------------------------
// Fused flash attention: per (q-tile 128, bh) CTA. 8 warps, warp = 16 q rows.
// Streams 128-wide kv tiles; skips tiles fully beyond len.
// S = 0.125 * Q K^T (3-pass split), online softmax in registers,
// P re-packed as A fragments (C->A register identity), O += P V (3-pass).
// Dynamic smem: K hi/lo [128][72], V^T hi/lo [64][136].
// ---------------------------------------------------------------------------
#define KS_PITCH 72
#define VS_PITCH 136
#define KS_ELEMS (128*KS_PITCH)      // 9216
#define VS_ELEMS (64*VS_PITCH)       // 8704
#define FLASH_SMEM ((2*KS_ELEMS + 2*VS_ELEMS) * 2)  // 71680 bytes

__global__ void __launch_bounds__(256, 1) flash_kernel() {
    extern __shared__ __nv_bfloat16 smf[];
    __nv_bfloat16* Ksh = smf;
    __nv_bfloat16* Ksl = smf + KS_ELEMS;
    __nv_bfloat16* Vsh = smf + 2*KS_ELEMS;
    __nv_bfloat16* Vsl = smf + 2*KS_ELEMS + VS_ELEMS;

    const int tid  = threadIdx.x;
    const int lane = tid & 31;
    const int warp = tid >> 5;
    const int r4   = lane >> 2;
    const int c2   = (lane & 3) * 2;
    const int bh   = blockIdx.y;
    const int b    = bh >> 4;
    const int q0   = blockIdx.x * 128;
    const int qrow = q0 + warp * 16;
    const int len  = g_len[b];
    const int ntiles = (len + 127) >> 7;

    const size_t base = (size_t)bh * Tq * Dq;

    // Q fragments, persistent in registers (A operand, K-dim = D = 64)
    uint32_t qh[4][4], ql[4][4];
    #pragma unroll
    for (int ks = 0; ks < 4; ks++) {
        int kc = ks*16 + c2;
        qh[ks][0] = *(const uint32_t*)&g_qh[base + (size_t)(qrow + r4    )*Dq + kc];
        qh[ks][1] = *(const uint32_t*)&g_qh[base + (size_t)(qrow + r4 + 8)*Dq + kc];
        qh[ks][2] = *(const uint32_t*)&g_qh[base + (size_t)(qrow + r4    )*Dq + kc + 8];
        qh[ks][3] = *(const uint32_t*)&g_qh[base + (size_t)(qrow + r4 + 8)*Dq + kc + 8];
        ql[ks][0] = *(const uint32_t*)&g_ql[base + (size_t)(qrow + r4    )*Dq + kc];
        ql[ks][1] = *(const uint32_t*)&g_ql[base + (size_t)(qrow + r4 + 8)*Dq + kc];
        ql[ks][2] = *(const uint32_t*)&g_ql[base + (size_t)(qrow + r4    )*Dq + kc + 8];
        ql[ks][3] = *(const uint32_t*)&g_ql[base + (size_t)(qrow + r4 + 8)*Dq + kc + 8];
    }

    float Oacc[8][4];
    #pragma unroll
    for (int i = 0; i < 8; i++)
        #pragma unroll
        for (int j = 0; j < 4; j++) Oacc[i][j] = 0.0f;
    float m_run[2] = {-CUDART_INF_F, -CUDART_INF_F};
    float l_run[2] = {0.0f, 0.0f};

    for (int kt = 0; kt < ntiles; kt++) {
        const int kv0 = kt * 128;
        __syncthreads();
        // stage K tile [128][64] hi/lo (row-major, pitch 72)
        #pragma unroll
        for (int i = tid; i < 1024; i += 256) {
            int r = i >> 3, c = (i & 7) * 8;
            *(uint4*)&Ksh[r*KS_PITCH + c] = *(const uint4*)&g_kh[base + (size_t)(kv0 + r)*Dq + c];
            *(uint4*)&Ksl[r*KS_PITCH + c] = *(const uint4*)&g_kl[base + (size_t)(kv0 + r)*Dq + c];
        }
        // stage V^T tile: Vs[d][kv], kv pairs packed
        #pragma unroll
        for (int i = tid; i < 4096; i += 256) {
            int kv = (i >> 6) * 2, d = i & 63;
            __nv_bfloat162 vh = __halves2bfloat162(
                g_vh[base + (size_t)(kv0 + kv)*Dq + d],
                g_vh[base + (size_t)(kv0 + kv + 1)*Dq + d]);
            __nv_bfloat162 vl = __halves2bfloat162(
                g_vl[base + (size_t)(kv0 + kv)*Dq + d],
                g_vl[base + (size_t)(kv0 + kv + 1)*Dq + d]);
            *(uint32_t*)&Vsh[d*VS_PITCH + kv] = *reinterpret_cast<uint32_t*>(&vh);
            *(uint32_t*)&Vsl[d*VS_PITCH + kv] = *reinterpret_cast<uint32_t*>(&vl);
        }
        __syncthreads();

        // ---- S = Q K^T ----
        float S[16][4];
        #pragma unroll
        for (int nt = 0; nt < 16; nt++)
            #pragma unroll
            for (int j = 0; j < 4; j++) S[nt][j] = 0.0f;
        #pragma unroll
        for (int ks = 0; ks < 4; ks++) {
            const int kb = ks*16 + c2;
            #pragma unroll
            for (int nt = 0; nt < 16; nt++) {
                int n = nt*8 + r4;
                uint32_t bhf[2], blf[2];
                bhf[0] = *(const uint32_t*)&Ksh[n*KS_PITCH + kb];
                bhf[1] = *(const uint32_t*)&Ksh[n*KS_PITCH + kb + 8];
                blf[0] = *(const uint32_t*)&Ksl[n*KS_PITCH + kb];
                blf[1] = *(const uint32_t*)&Ksl[n*KS_PITCH + kb + 8];
                mma16816(S[nt], qh[ks], bhf);
                mma16816(S[nt], qh[ks], blf);
                mma16816(S[nt], ql[ks], bhf);
            }
        }

        // ---- scale + mask + row max ----
        float rmax[2] = {-CUDART_INF_F, -CUDART_INF_F};
        #pragma unroll
        for (int nt = 0; nt < 16; nt++) {
            #pragma unroll
            for (int j = 0; j < 4; j++) {
                int kv = kv0 + nt*8 + c2 + (j & 1);
                float s = S[nt][j] * 0.125f;
                s = (kv < len) ? s : -CUDART_INF_F;
                S[nt][j] = s;
                rmax[j >> 1] = fmaxf(rmax[j >> 1], s);
            }
        }
        #pragma unroll
        for (int j = 0; j < 2; j++) {
            rmax[j] = fmaxf(rmax[j], __shfl_xor_sync(0xffffffffu, rmax[j], 1));
            rmax[j] = fmaxf(rmax[j], __shfl_xor_sync(0xffffffffu, rmax[j], 2));
        }

        float m_new[2], alpha[2];
        #pragma unroll
        for (int j = 0; j < 2; j++) {
            m_new[j] = fmaxf(m_run[j], rmax[j]);
            alpha[j] = exp2f((m_run[j] - m_new[j]) * LOG2E);
            m_run[j] = m_new[j];
        }

        // ---- exponentiate + row sum ----
        float rsum[2] = {0.0f, 0.0f};
        #pragma unroll
        for (int nt = 0; nt < 16; nt++) {
            #pragma unroll
            for (int j = 0; j < 4; j++) {
                float p = exp2f((S[nt][j] - m_new[j >> 1]) * LOG2E);
                S[nt][j] = p;
                rsum[j >> 1] += p;
            }
        }
        #pragma unroll
        for (int j = 0; j < 2; j++) {
            rsum[j] += __shfl_xor_sync(0xffffffffu, rsum[j], 1);
            rsum[j] += __shfl_xor_sync(0xffffffffu, rsum[j], 2);
            l_run[j] = l_run[j] * alpha[j] + rsum[j];
        }
        #pragma unroll
        for (int i = 0; i < 8; i++) {
            Oacc[i][0] *= alpha[0]; Oacc[i][1] *= alpha[0];
            Oacc[i][2] *= alpha[1]; Oacc[i][3] *= alpha[1];
        }

        // ---- O += P V  (P fragments built from S C-frags in registers) ----
        #pragma unroll
        for (int kk = 0; kk < 8; kk++) {
            uint32_t pah[4], pal[4];
            pack_split2(S[2*kk  ][0], S[2*kk  ][1], pah[0], pal[0]);
            pack_split2(S[2*kk  ][2], S[2*kk  ][3], pah[1], pal[1]);
            pack_split2(S[2*kk+1][0], S[2*kk+1][1], pah[2], pal[2]);
            pack_split2(S[2*kk+1][2], S[2*kk+1][3], pah[3], pal[3]);
            const int kb = kk*16 + c2;
            #pragma unroll
            for (int ntd = 0; ntd < 8; ntd++) {
                int n = ntd*8 + r4;
                uint32_t bhf[2], blf[2];
                bhf[0] = *(const uint32_t*)&Vsh[n*VS_PITCH + kb];
                bhf[1] = *(const uint32_t*)&Vsh[n*VS_PITCH + kb + 8];
                blf[0] = *(const uint32_t*)&Vsl[n*VS_PITCH + kb];
                blf[1] = *(const uint32_t*)&Vsl[n*VS_PITCH + kb + 8];
                mma16816(Oacc[ntd], pah, bhf);
                mma16816(Oacc[ntd], pah, blf);
                mma16816(Oacc[ntd], pal, bhf);
            }
        }
    }

    // ---- finalize: O /= l, write ctx hi/lo bf16 [B,T,C] ----
    const float inv0 = 1.0f / l_run[0];
    const float inv1 = 1.0f / l_run[1];
    const int hh = bh & 15;
    const size_t base0 = ((size_t)(b*Tq + qrow + r4    ))*Cq + hh*Dq;
    const size_t base1 = ((size_t)(b*Tq + qrow + r4 + 8))*Cq + hh*Dq;
    #pragma unroll
    for (int ntd = 0; ntd < 8; ntd++) {
        int d0 = ntd*8 + c2;
        uint32_t hi, lo;
        pack_split2(Oacc[ntd][0]*inv0, Oacc[ntd][1]*inv0, hi, lo);
        *(uint32_t*)(g_ctxh + base0 + d0) = hi;
        *(uint32_t*)(g_ctxl + base0 + d0) = lo;
        pack_split2(Oacc[ntd][2]*inv1, Oacc[ntd][3]*inv1, hi, lo);
        *(uint32_t*)(g_ctxh + base1 + d0) = hi;
        *(uint32_t*)(g_ctxl + base1 + d0) = lo;
    }
}

// ---------------------------------------------------------------------------
extern "C" void kernel_launch(void* const* d_in, const int* in_sizes, int n_in,
                              void* d_out, int out_size)
{
    const float*         x     = (const float*)d_in[0];
    const unsigned char* mask  = (const unsigned char*)d_in[1];
    const float*         w_qkv = (const float*)d_in[2];
    const float*         w_out = (const float*)d_in[3];
    const float*         b_out = (const float*)d_in[4];
    float*               out   = (float*)d_out;

    // 0. pre-split operands to bf16 hi/lo (destinations selected device-side)
    split_kernel<0><<<(Bq*Tq*Cq)/1024, 256>>>(x, (size_t)Bq*Tq*Cq);
    split_kernel<1><<<(Cq*3*Cq)/1024, 256>>>(w_qkv, (size_t)Cq*3*Cq);
    split_kernel<2><<<(Cq*Cq)/1024, 256>>>(w_out, (size_t)Cq*Cq);

    // 1. lengths
    len_kernel<<<Bq, 256>>>(mask);

    // 2. QKV projection -> Q/K/V hi/lo [BH,T,D]
    mma_gemm_bf<0><<<dim3(3*Cq/128, Bq*Tq/128), 256>>>(
        nullptr, nullptr, Bq*Tq, 3*Cq, Cq);

    // 3. fused flash attention -> ctx hi/lo
    cudaFuncSetAttribute(flash_kernel,
                         cudaFuncAttributeMaxDynamicSharedMemorySize, FLASH_SMEM);
    flash_kernel<<<dim3(Tq/128, BHq), 256, FLASH_SMEM>>>();

    // 4. output projection + bias
    mma_gemm_bf<3><<<dim3(Cq/128, Bq*Tq/128), 256>>>(
        out, b_out, Bq*Tq, Cq, Cq);
}

// round 9
// speedup vs baseline: 3.8501x; 1.9553x over previous
#include <cuda_runtime.h>
#include <cuda_bf16.h>
#include <math_constants.h>
#include <stdint.h>

// Problem constants
#define Bq 4
#define Tq 2048
#define Cq 1024
#define Hq 16
#define Dq 64
#define BHq (Bq*Hq)

#define LOG2E 1.4426950408889634f

// ---------------------------------------------------------------------------
// Scratch (device globals, allocation-free). ONLY referenced from device code.
// Weights stored TRANSPOSED: [N][K] so GEMM B staging = vectorized row copies.
// ---------------------------------------------------------------------------
__device__ __nv_bfloat16 g_xh[(size_t)Bq*Tq*Cq];        // x split [M][K]
__device__ __nv_bfloat16 g_xl[(size_t)Bq*Tq*Cq];
__device__ __nv_bfloat16 g_wqh[(size_t)3*Cq*Cq];        // w_qkv^T split [3C][C]
__device__ __nv_bfloat16 g_wql[(size_t)3*Cq*Cq];
__device__ __nv_bfloat16 g_woh[(size_t)Cq*Cq];          // w_out^T split [C][C]
__device__ __nv_bfloat16 g_wol[(size_t)Cq*Cq];
__device__ __nv_bfloat16 g_qh[(size_t)BHq*Tq*Dq];       // Q/K/V split [BH][T][D]
__device__ __nv_bfloat16 g_ql[(size_t)BHq*Tq*Dq];
__device__ __nv_bfloat16 g_kh[(size_t)BHq*Tq*Dq];
__device__ __nv_bfloat16 g_kl[(size_t)BHq*Tq*Dq];
__device__ __nv_bfloat16 g_vh[(size_t)BHq*Tq*Dq];
__device__ __nv_bfloat16 g_vl[(size_t)BHq*Tq*Dq];
__device__ __nv_bfloat16 g_ctxh[(size_t)Bq*Tq*Cq];      // attention out split
__device__ __nv_bfloat16 g_ctxl[(size_t)Bq*Tq*Cq];
__device__ int g_len[Bq];

// ---------------------------------------------------------------------------
__device__ __forceinline__ void mma16816(float* d, const uint32_t* a, const uint32_t* b) {
    asm volatile(
        "mma.sync.aligned.m16n8k16.row.col.f32.bf16.bf16.f32 "
        "{%0,%1,%2,%3}, {%4,%5,%6,%7}, {%8,%9}, {%0,%1,%2,%3};\n"
        : "+f"(d[0]), "+f"(d[1]), "+f"(d[2]), "+f"(d[3])
        : "r"(a[0]), "r"(a[1]), "r"(a[2]), "r"(a[3]),
          "r"(b[0]), "r"(b[1]));
}

__device__ __forceinline__ void ldmx4(uint32_t& d0, uint32_t& d1, uint32_t& d2,
                                      uint32_t& d3, uint32_t addr) {
    asm volatile("ldmatrix.sync.aligned.m8n8.x4.shared.b16 {%0,%1,%2,%3}, [%4];"
        : "=r"(d0), "=r"(d1), "=r"(d2), "=r"(d3) : "r"(addr));
}
__device__ __forceinline__ void ldmx4t(uint32_t& d0, uint32_t& d1, uint32_t& d2,
                                       uint32_t& d3, uint32_t addr) {
    asm volatile("ldmatrix.sync.aligned.m8n8.x4.trans.shared.b16 {%0,%1,%2,%3}, [%4];"
        : "=r"(d0), "=r"(d1), "=r"(d2), "=r"(d3) : "r"(addr));
}

__device__ __forceinline__ void cp16(uint32_t dst, const void* src) {
    asm volatile("cp.async.cg.shared.global [%0], [%1], 16;\n" :: "r"(dst), "l"(src));
}
__device__ __forceinline__ void cp_commit() {
    asm volatile("cp.async.commit_group;\n");
}
template<int N>
__device__ __forceinline__ void cp_wait() {
    asm volatile("cp.async.wait_group %0;\n" :: "n"(N));
}

// pack two fp32 into bf16x2 hi and lo words (low half = first arg)
__device__ __forceinline__ void pack_split2(float a, float b, uint32_t& hi, uint32_t& lo) {
    __nv_bfloat16 ha = __float2bfloat16(a), hb = __float2bfloat16(b);
    __nv_bfloat16 la = __float2bfloat16(a - __bfloat162float(ha));
    __nv_bfloat16 lb = __float2bfloat16(b - __bfloat162float(hb));
    __nv_bfloat162 h2 = __halves2bfloat162(ha, hb);
    __nv_bfloat162 l2 = __halves2bfloat162(la, lb);
    hi = *reinterpret_cast<uint32_t*>(&h2);
    lo = *reinterpret_cast<uint32_t*>(&l2);
}

// ---------------------------------------------------------------------------
// x split (linear, no transpose): x -> g_xh/g_xl
// ---------------------------------------------------------------------------
__global__ void xsplit_kernel(const float* __restrict__ src, size_t n) {
    size_t i = ((size_t)blockIdx.x * blockDim.x + threadIdx.x) * 4;
    if (i >= n) return;
    float4 v = *(const float4*)(src + i);
    uint32_t h0, l0, h1, l1;
    pack_split2(v.x, v.y, h0, l0);
    pack_split2(v.z, v.w, h1, l1);
    *(uint32_t*)(g_xh + i)     = h0;
    *(uint32_t*)(g_xh + i + 2) = h1;
    *(uint32_t*)(g_xl + i)     = l0;
    *(uint32_t*)(g_xl + i + 2) = l1;
}

// ---------------------------------------------------------------------------
// Weight transpose + split: src [K=1024][N] fp32 -> dst [N][1024] bf16 hi/lo.
// 32x32 tiles, 256 threads, both sides coalesced.
//   WHICH 1: w_qkv -> g_wqh/g_wql    WHICH 2: w_out -> g_woh/g_wol
// ---------------------------------------------------------------------------
template<int WHICH>
__global__ void wsplit_kernel(const float* __restrict__ src, int N) {
    __shared__ float t32[32][33];
    __nv_bfloat16* dh = (WHICH == 1) ? g_wqh : g_woh;
    __nv_bfloat16* dl = (WHICH == 1) ? g_wql : g_wol;
    const int k0 = blockIdx.y * 32, n0 = blockIdx.x * 32;
    const int tid = threadIdx.x;
    const int r0 = tid >> 5, c = tid & 31;
    #pragma unroll
    for (int rr = 0; rr < 4; rr++)
        t32[r0 + rr*8][c] = src[(size_t)(k0 + r0 + rr*8)*N + n0 + c];
    __syncthreads();
    const int n = tid >> 3, kq = (tid & 7) * 4;
    float v0 = t32[kq  ][n], v1 = t32[kq+1][n];
    float v2 = t32[kq+2][n], v3 = t32[kq+3][n];
    uint32_t h0, l0, h1, l1;
    pack_split2(v0, v1, h0, l0);
    pack_split2(v2, v3, h1, l1);
    size_t idx = (size_t)(n0 + n)*Cq + k0 + kq;
    *(uint2*)(dh + idx) = make_uint2(h0, h1);
    *(uint2*)(dl + idx) = make_uint2(l0, l1);
}

// ---------------------------------------------------------------------------
// Length kernel: robust to padding_mask being bool(u8), int32, or float32.
// ---------------------------------------------------------------------------
__global__ void len_kernel(const unsigned char* __restrict__ mraw) {
    __shared__ int code;
    __shared__ int partial[256];
    if (threadIdx.x == 0) {
        if (mraw[1] == 1) code = 0;
        else if (((const int*)mraw)[0] == 1) code = 1;
        else code = 2;
    }
    __syncthreads();
    const int c = code;
    const int b = blockIdx.x;
    int cnt = 0;
    for (int t = threadIdx.x; t < Tq; t += blockDim.x) {
        int idx = b * Tq + t;
        bool m;
        if (c == 0)      m = mraw[idx] != 0;
        else if (c == 1) m = ((const int*)mraw)[idx] != 0;
        else             m = ((const float*)mraw)[idx] != 0.0f;
        cnt += m ? 1 : 0;
    }
    partial[threadIdx.x] = cnt;
    __syncthreads();
    for (int s = 128; s > 0; s >>= 1) {
        if (threadIdx.x < s) partial[threadIdx.x] += partial[threadIdx.x + s];
        __syncthreads();
    }
    if (threadIdx.x == 0) g_len[b] = partial[0];
}

// ---------------------------------------------------------------------------
// Split-bf16 tensor-core GEMM, cp.async 2-stage double buffered.
// A [M][K] row-major hi/lo. B [N][K] row-major hi/lo (pre-transposed weights).
//   MODE 0: qkv = x @ w_qkv^T_layout, epilogue -> g_{q,k,v}{h,l}
//   MODE 3: out = ctx @ w_out + b_out (fp32 out to Cg)
// BM=BN=128, BK=32, 8 warps (2x4), warp tile 64x32. 3-pass split MMA.
// Dyn smem: 2 stages x (Ah,Al,Bh,Bl)[128][40] = 81920 B.
// ---------------------------------------------------------------------------
#define GP 40                        // smem pitch (bf16)
#define G_ARR (128*GP)               // 5120 elems per array
#define G_STAGE (4*G_ARR)            // 20480 elems per stage
#define GEMM_SMEM (2*G_STAGE*2)      // 81920 bytes

template<int MODE>
__global__ void __launch_bounds__(256)
mma_gemm_bf(float* __restrict__ Cg, const float* __restrict__ bias,
            int M, int N, int K)
{
    extern __shared__ __nv_bfloat16 smg[];

    const __nv_bfloat16* Agh = (MODE == 0) ? g_xh : g_ctxh;
    const __nv_bfloat16* Agl = (MODE == 0) ? g_xl : g_ctxl;
    const __nv_bfloat16* Bgh = (MODE == 0) ? g_wqh : g_woh;
    const __nv_bfloat16* Bgl = (MODE == 0) ? g_wql : g_wol;

    const int tid  = threadIdx.x;
    const int lane = tid & 31;
    const int warp = tid >> 5;
    const int wm   = warp >> 2;
    const int wn   = warp & 3;
    const int r4   = lane >> 2;
    const int c2   = (lane & 3) * 2;
    const int bm   = blockIdx.y * 128;
    const int bn   = blockIdx.x * 128;

    const uint32_t sb = (uint32_t)__cvta_generic_to_shared(smg);

    // cp.async staging: 2048 chunks of 16B per stage, 8 per thread
    auto issue = [&](int s, int k0) {
        #pragma unroll
        for (int i = tid; i < 2048; i += 256) {
            int arr = i >> 9, j = i & 511, r = j >> 2, c = j & 3;
            const __nv_bfloat16* src =
                (arr == 0) ? Agh + (size_t)(bm + r)*K + k0 + c*8 :
                (arr == 1) ? Agl + (size_t)(bm + r)*K + k0 + c*8 :
                (arr == 2) ? Bgh + (size_t)(bn + r)*K + k0 + c*8 :
                             Bgl + (size_t)(bn + r)*K + k0 + c*8;
            uint32_t dst = sb + (s*G_STAGE + arr*G_ARR + r*GP + c*8)*2;
            cp16(dst, src);
        }
        cp_commit();
    };

    float acc[4][4][4];
    #pragma unroll
    for (int i = 0; i < 4; i++)
        #pragma unroll
        for (int j = 0; j < 4; j++)
            #pragma unroll
            for (int r = 0; r < 4; r++) acc[i][j][r] = 0.0f;

    const int NS = K / 32;
    issue(0, 0);

    for (int s = 0; s < NS; s++) {
        if (s + 1 < NS) { issue((s + 1) & 1, (s + 1) * 32); cp_wait<1>(); }
        else            { cp_wait<0>(); }
        __syncthreads();

        const __nv_bfloat16* Ash = smg + (s & 1)*G_STAGE;
        const __nv_bfloat16* Asl = Ash + G_ARR;
        const __nv_bfloat16* Bsh = Ash + 2*G_ARR;
        const __nv_bfloat16* Bsl = Ash + 3*G_ARR;

        #pragma unroll
        for (int ks = 0; ks < 2; ks++) {
            const int kb = ks*16 + c2;
            uint32_t ah[4][4], al[4][4], bh[4][2], bl[4][2];
            #pragma unroll
            for (int mt = 0; mt < 4; mt++) {
                int m = wm*64 + mt*16 + r4;
                ah[mt][0] = *(const uint32_t*)&Ash[m*GP + kb];
                ah[mt][1] = *(const uint32_t*)&Ash[(m+8)*GP + kb];
                ah[mt][2] = *(const uint32_t*)&Ash[m*GP + kb + 8];
                ah[mt][3] = *(const uint32_t*)&Ash[(m+8)*GP + kb + 8];
                al[mt][0] = *(const uint32_t*)&Asl[m*GP + kb];
                al[mt][1] = *(const uint32_t*)&Asl[(m+8)*GP + kb];
                al[mt][2] = *(const uint32_t*)&Asl[m*GP + kb + 8];
                al[mt][3] = *(const uint32_t*)&Asl[(m+8)*GP + kb + 8];
            }
            #pragma unroll
            for (int nt = 0; nt < 4; nt++) {
                int n = wn*32 + nt*8 + r4;
                bh[nt][0] = *(const uint32_t*)&Bsh[n*GP + kb];
                bh[nt][1] = *(const uint32_t*)&Bsh[n*GP + kb + 8];
                bl[nt][0] = *(const uint32_t*)&Bsl[n*GP + kb];
                bl[nt][1] = *(const uint32_t*)&Bsl[n*GP + kb + 8];
            }
            #pragma unroll
            for (int mt = 0; mt < 4; mt++)
                #pragma unroll
                for (int nt = 0; nt < 4; nt++) {
                    mma16816(acc[mt][nt], ah[mt], bh[nt]);
                    mma16816(acc[mt][nt], ah[mt], bl[nt]);
                    mma16816(acc[mt][nt], al[mt], bh[nt]);
                }
        }
        __syncthreads();
    }

    // epilogue
    #pragma unroll
    for (int mt = 0; mt < 4; mt++) {
        #pragma unroll
        for (int nt = 0; nt < 4; nt++) {
            int m0 = bm + wm*64 + mt*16 + r4;
            int n0 = bn + wn*32 + nt*8 + c2;
            const float* cr = acc[mt][nt];
            #pragma unroll
            for (int half = 0; half < 2; half++) {
                int m = m0 + half*8;
                float v0 = cr[half*2], v1 = cr[half*2+1];
                if (MODE == 0) {
                    int bb = m / Tq, t = m % Tq;
                    int part = n0 >> 10, hh = (n0 & 1023) >> 6, d = n0 & 63;
                    size_t idx = ((size_t)(bb*Hq + hh)*Tq + t)*Dq + d;
                    __nv_bfloat16* dsth = (part == 0) ? g_qh : (part == 1) ? g_kh : g_vh;
                    __nv_bfloat16* dstl = (part == 0) ? g_ql : (part == 1) ? g_kl : g_vl;
                    uint32_t hi, lo;
                    pack_split2(v0, v1, hi, lo);
                    *(uint32_t*)(dsth + idx) = hi;
                    *(uint32_t*)(dstl + idx) = lo;
                } else {
                    *(float2*)&Cg[(size_t)m*N + n0] =
                        make_float2(v0 + bias[n0], v1 + bias[n0+1]);
                }
            }
        }
    }
}

// ---------------------------------------------------------------------------
// Fused flash attention, cp.async 2-stage double buffered kv tiles.
// Per (q-tile 128, bh) CTA, 8 warps, warp = 16 q rows. Skips masked tiles.
// K and V both staged row-major [kv][d]; B-fragments via ldmatrix:
//   QK^T: non-trans x4 on K tiles; PV: trans x4 on V tiles.
// Dyn smem: 2 stages x (Kh,Kl,Vh,Vl)[128][72] = 147456 B.
// ---------------------------------------------------------------------------
#define FP 72                         // smem pitch (bf16)
#define F_ARR (128*FP)                // 9216 elems
#define F_STAGE (4*F_ARR)             // 36864 elems
#define FLASH_SMEM (2*F_STAGE*2)      // 147456 bytes

__global__ void __launch_bounds__(256, 1) flash_kernel() {
    extern __shared__ __nv_bfloat16 smf[];

    const int tid  = threadIdx.x;
    const int lane = tid & 31;
    const int warp = tid >> 5;
    const int r4   = lane >> 2;
    const int c2   = (lane & 3) * 2;
    const int bh   = blockIdx.y;
    const int b    = bh >> 4;
    const int qrow = blockIdx.x * 128 + warp * 16;
    const int len  = g_len[b];
    const int ntiles = (len + 127) >> 7;

    const size_t base = (size_t)bh * Tq * Dq;
    const uint32_t sb = (uint32_t)__cvta_generic_to_shared(smf);

    // per-thread ldmatrix byte offsets
    const uint32_t lk = ((((lane & 7) + ((lane >> 4) << 3)) * FP + ((lane >> 3) & 1) * 8)) * 2;
    const uint32_t lv = (((lane & 15) * FP + ((lane >> 4) << 3))) * 2;

    auto issue = [&](int s, int kv0) {
        #pragma unroll
        for (int i = tid; i < 4096; i += 256) {
            int arr = i >> 10, j = i & 1023, r = j >> 3, c = j & 7;
            const __nv_bfloat16* src =
                (arr == 0) ? g_kh + base + (size_t)(kv0 + r)*Dq + c*8 :
                (arr == 1) ? g_kl + base + (size_t)(kv0 + r)*Dq + c*8 :
                (arr == 2) ? g_vh + base + (size_t)(kv0 + r)*Dq + c*8 :
                             g_vl + base + (size_t)(kv0 + r)*Dq + c*8;
            uint32_t dst = sb + (s*F_STAGE + arr*F_ARR + r*FP + c*8)*2;
            cp16(dst, src);
        }
        cp_commit();
    };

    // Q fragments, persistent in registers (A operand, K-dim = D = 64)
    uint32_t qh[4][4], ql[4][4];
    #pragma unroll
    for (int ks = 0; ks < 4; ks++) {
        int kc = ks*16 + c2;
        qh[ks][0] = *(const uint32_t*)&g_qh[base + (size_t)(qrow + r4    )*Dq + kc];
        qh[ks][1] = *(const uint32_t*)&g_qh[base + (size_t)(qrow + r4 + 8)*Dq + kc];
        qh[ks][2] = *(const uint32_t*)&g_qh[base + (size_t)(qrow + r4    )*Dq + kc + 8];
        qh[ks][3] = *(const uint32_t*)&g_qh[base + (size_t)(qrow + r4 + 8)*Dq + kc + 8];
        ql[ks][0] = *(const uint32_t*)&g_ql[base + (size_t)(qrow + r4    )*Dq + kc];
        ql[ks][1] = *(const uint32_t*)&g_ql[base + (size_t)(qrow + r4 + 8)*Dq + kc];
        ql[ks][2] = *(const uint32_t*)&g_ql[base + (size_t)(qrow + r4    )*Dq + kc + 8];
        ql[ks][3] = *(const uint32_t*)&g_ql[base + (size_t)(qrow + r4 + 8)*Dq + kc + 8];
    }

    float Oacc[8][4];
    #pragma unroll
    for (int i = 0; i < 8; i++)
        #pragma unroll
        for (int j = 0; j < 4; j++) Oacc[i][j] = 0.0f;
    float m_run[2] = {-CUDART_INF_F, -CUDART_INF_F};
    float l_run[2] = {0.0f, 0.0f};

    issue(0, 0);

    for (int kt = 0; kt < ntiles; kt++) {
        const int kv0 = kt * 128;
        if (kt + 1 < ntiles) { issue((kt + 1) & 1, kv0 + 128); cp_wait<1>(); }
        else                 { cp_wait<0>(); }
        __syncthreads();

        const uint32_t stg = sb + (kt & 1)*F_STAGE*2;
        const uint32_t Khb = stg;
        const uint32_t Klb = stg + F_ARR*2;
        const uint32_t Vhb = stg + 2*F_ARR*2;
        const uint32_t Vlb = stg + 3*F_ARR*2;

        // ---- S = Q K^T ----
        float S[16][4];
        #pragma unroll
        for (int nt = 0; nt < 16; nt++)
            #pragma unroll
            for (int j = 0; j < 4; j++) S[nt][j] = 0.0f;
        #pragma unroll
        for (int ks = 0; ks < 4; ks++) {
            #pragma unroll
            for (int np = 0; np < 8; np++) {          // nt pairs
                const uint32_t off = (np*16*FP + ks*16)*2;
                uint32_t h0,h1,h2,h3, l0,l1,l2,l3;
                ldmx4(h0, h1, h2, h3, Khb + lk + off);
                ldmx4(l0, l1, l2, l3, Klb + lk + off);
                uint32_t bh0[2] = {h0, h1}, bh1[2] = {h2, h3};
                uint32_t bl0[2] = {l0, l1}, bl1[2] = {l2, l3};
                mma16816(S[2*np  ], qh[ks], bh0);
                mma16816(S[2*np  ], qh[ks], bl0);
                mma16816(S[2*np  ], ql[ks], bh0);
                mma16816(S[2*np+1], qh[ks], bh1);
                mma16816(S[2*np+1], qh[ks], bl1);
                mma16816(S[2*np+1], ql[ks], bh1);
            }
        }

        // ---- scale + mask + row max ----
        float rmax[2] = {-CUDART_INF_F, -CUDART_INF_F};
        #pragma unroll
        for (int nt = 0; nt < 16; nt++) {
            #pragma unroll
            for (int j = 0; j < 4; j++) {
                int kv = kv0 + nt*8 + c2 + (j & 1);
                float s = S[nt][j] * 0.125f;
                s = (kv < len) ? s : -CUDART_INF_F;
                S[nt][j] = s;
                rmax[j >> 1] = fmaxf(rmax[j >> 1], s);
            }
        }
        #pragma unroll
        for (int j = 0; j < 2; j++) {
            rmax[j] = fmaxf(rmax[j], __shfl_xor_sync(0xffffffffu, rmax[j], 1));
            rmax[j] = fmaxf(rmax[j], __shfl_xor_sync(0xffffffffu, rmax[j], 2));
        }

        float m_new[2], alpha[2];
        #pragma unroll
        for (int j = 0; j < 2; j++) {
            m_new[j] = fmaxf(m_run[j], rmax[j]);
            alpha[j] = exp2f((m_run[j] - m_new[j]) * LOG2E);
            m_run[j] = m_new[j];
        }

        // ---- exponentiate + row sum ----
        float rsum[2] = {0.0f, 0.0f};
        #pragma unroll
        for (int nt = 0; nt < 16; nt++) {
            #pragma unroll
            for (int j = 0; j < 4; j++) {
                float p = exp2f((S[nt][j] - m_new[j >> 1]) * LOG2E);
                S[nt][j] = p;
                rsum[j >> 1] += p;
            }
        }
        #pragma unroll
        for (int j = 0; j < 2; j++) {
            rsum[j] += __shfl_xor_sync(0xffffffffu, rsum[j], 1);
            rsum[j] += __shfl_xor_sync(0xffffffffu, rsum[j], 2);
            l_run[j] = l_run[j] * alpha[j] + rsum[j];
        }
        #pragma unroll
        for (int i = 0; i < 8; i++) {
            Oacc[i][0] *= alpha[0]; Oacc[i][1] *= alpha[0];
            Oacc[i][2] *= alpha[1]; Oacc[i][3] *= alpha[1];
        }

        // ---- O += P V : P frags from S in registers, V frags via ldmatrix.trans
        #pragma unroll
        for (int kk = 0; kk < 8; kk++) {
            uint32_t pah[4], pal[4];
            pack_split2(S[2*kk  ][0], S[2*kk  ][1], pah[0], pal[0]);
            pack_split2(S[2*kk  ][2], S[2*kk  ][3], pah[1], pal[1]);
            pack_split2(S[2*kk+1][0], S[2*kk+1][1], pah[2], pal[2]);
            pack_split2(S[2*kk+1][2], S[2*kk+1][3], pah[3], pal[3]);
            #pragma unroll
            for (int dp = 0; dp < 4; dp++) {          // d-block pairs
                const uint32_t off = (kk*16*FP + dp*16)*2;
                uint32_t h0,h1,h2,h3, l0,l1,l2,l3;
                ldmx4t(h0, h1, h2, h3, Vhb + lv + off);
                ldmx4t(l0, l1, l2, l3, Vlb + lv + off);
                uint32_t bh0[2] = {h0, h1}, bh1[2] = {h2, h3};
                uint32_t bl0[2] = {l0, l1}, bl1[2] = {l2, l3};
                mma16816(Oacc[2*dp  ], pah, bh0);
                mma16816(Oacc[2*dp  ], pah, bl0);
                mma16816(Oacc[2*dp  ], pal, bh0);
                mma16816(Oacc[2*dp+1], pah, bh1);
                mma16816(Oacc[2*dp+1], pah, bl1);
                mma16816(Oacc[2*dp+1], pal, bh1);
            }
        }
        __syncthreads();
    }

    // ---- finalize: O /= l, write ctx hi/lo bf16 [B,T,C] ----
    const float inv0 = 1.0f / l_run[0];
    const float inv1 = 1.0f / l_run[1];
    const int hh = bh & 15;
    const size_t base0 = ((size_t)(b*Tq + qrow + r4    ))*Cq + hh*Dq;
    const size_t base1 = ((size_t)(b*Tq + qrow + r4 + 8))*Cq + hh*Dq;
    #pragma unroll
    for (int ntd = 0; ntd < 8; ntd++) {
        int d0 = ntd*8 + c2;
        uint32_t hi, lo;
        pack_split2(Oacc[ntd][0]*inv0, Oacc[ntd][1]*inv0, hi, lo);
        *(uint32_t*)(g_ctxh + base0 + d0) = hi;
        *(uint32_t*)(g_ctxl + base0 + d0) = lo;
        pack_split2(Oacc[ntd][2]*inv1, Oacc[ntd][3]*inv1, hi, lo);
        *(uint32_t*)(g_ctxh + base1 + d0) = hi;
        *(uint32_t*)(g_ctxl + base1 + d0) = lo;
    }
}

// ---------------------------------------------------------------------------
extern "C" void kernel_launch(void* const* d_in, const int* in_sizes, int n_in,
                              void* d_out, int out_size)
{
    const float*         x     = (const float*)d_in[0];
    const unsigned char* mask  = (const unsigned char*)d_in[1];
    const float*         w_qkv = (const float*)d_in[2];
    const float*         w_out = (const float*)d_in[3];
    const float*         b_out = (const float*)d_in[4];
    float*               out   = (float*)d_out;

    // 0. pre-split x (linear) and weights (transposed to [N][K])
    xsplit_kernel<<<(Bq*Tq*Cq)/1024, 256>>>(x, (size_t)Bq*Tq*Cq);
    wsplit_kernel<1><<<dim3(3*Cq/32, Cq/32), 256>>>(w_qkv, 3*Cq);
    wsplit_kernel<2><<<dim3(Cq/32, Cq/32), 256>>>(w_out, Cq);

    // 1. lengths
    len_kernel<<<Bq, 256>>>(mask);

    // 2. QKV projection -> Q/K/V hi/lo [BH,T,D]
    cudaFuncSetAttribute(mma_gemm_bf<0>,
                         cudaFuncAttributeMaxDynamicSharedMemorySize, GEMM_SMEM);
    mma_gemm_bf<0><<<dim3(3*Cq/128, Bq*Tq/128), 256, GEMM_SMEM>>>(
        nullptr, nullptr, Bq*Tq, 3*Cq, Cq);

    // 3. fused flash attention -> ctx hi/lo
    cudaFuncSetAttribute(flash_kernel,
                         cudaFuncAttributeMaxDynamicSharedMemorySize, FLASH_SMEM);
    flash_kernel<<<dim3(Tq/128, BHq), 256, FLASH_SMEM>>>();

    // 4. output projection + bias
    cudaFuncSetAttribute(mma_gemm_bf<3>,
                         cudaFuncAttributeMaxDynamicSharedMemorySize, GEMM_SMEM);
    mma_gemm_bf<3><<<dim3(Cq/128, Bq*Tq/128), 256, GEMM_SMEM>>>(
        out, b_out, Bq*Tq, Cq, Cq);
}

// round 10
// speedup vs baseline: 4.2484x; 1.1034x over previous
#include <cuda_runtime.h>
#include <cuda_bf16.h>
#include <math_constants.h>
#include <stdint.h>

// Problem constants
#define Bq 4
#define Tq 2048
#define Cq 1024
#define Hq 16
#define Dq 64
#define BHq (Bq*Hq)

#define LOG2E 1.4426950408889634f

// ---------------------------------------------------------------------------
// Scratch (device globals, allocation-free). ONLY referenced from device code.
// Weights stored TRANSPOSED: [N][K] so GEMM B staging = vectorized row copies.
// ---------------------------------------------------------------------------
__device__ __nv_bfloat16 g_xh[(size_t)Bq*Tq*Cq];        // x split [M][K]
__device__ __nv_bfloat16 g_xl[(size_t)Bq*Tq*Cq];
__device__ __nv_bfloat16 g_wqh[(size_t)3*Cq*Cq];        // w_qkv^T split [3C][C]
__device__ __nv_bfloat16 g_wql[(size_t)3*Cq*Cq];
__device__ __nv_bfloat16 g_woh[(size_t)Cq*Cq];          // w_out^T split [C][C]
__device__ __nv_bfloat16 g_wol[(size_t)Cq*Cq];
__device__ __nv_bfloat16 g_qh[(size_t)BHq*Tq*Dq];       // Q/K/V split [BH][T][D]
__device__ __nv_bfloat16 g_ql[(size_t)BHq*Tq*Dq];
__device__ __nv_bfloat16 g_kh[(size_t)BHq*Tq*Dq];
__device__ __nv_bfloat16 g_kl[(size_t)BHq*Tq*Dq];
__device__ __nv_bfloat16 g_vh[(size_t)BHq*Tq*Dq];
__device__ __nv_bfloat16 g_vl[(size_t)BHq*Tq*Dq];
__device__ __nv_bfloat16 g_ctxh[(size_t)Bq*Tq*Cq];      // attention out split
__device__ __nv_bfloat16 g_ctxl[(size_t)Bq*Tq*Cq];
__device__ int g_len[Bq];

// ---------------------------------------------------------------------------
__device__ __forceinline__ void mma16816(float* d, const uint32_t* a, const uint32_t* b) {
    asm volatile(
        "mma.sync.aligned.m16n8k16.row.col.f32.bf16.bf16.f32 "
        "{%0,%1,%2,%3}, {%4,%5,%6,%7}, {%8,%9}, {%0,%1,%2,%3};\n"
        : "+f"(d[0]), "+f"(d[1]), "+f"(d[2]), "+f"(d[3])
        : "r"(a[0]), "r"(a[1]), "r"(a[2]), "r"(a[3]),
          "r"(b[0]), "r"(b[1]));
}

__device__ __forceinline__ void ldmx4(uint32_t& d0, uint32_t& d1, uint32_t& d2,
                                      uint32_t& d3, uint32_t addr) {
    asm volatile("ldmatrix.sync.aligned.m8n8.x4.shared.b16 {%0,%1,%2,%3}, [%4];"
        : "=r"(d0), "=r"(d1), "=r"(d2), "=r"(d3) : "r"(addr));
}
__device__ __forceinline__ void ldmx4t(uint32_t& d0, uint32_t& d1, uint32_t& d2,
                                       uint32_t& d3, uint32_t addr) {
    asm volatile("ldmatrix.sync.aligned.m8n8.x4.trans.shared.b16 {%0,%1,%2,%3}, [%4];"
        : "=r"(d0), "=r"(d1), "=r"(d2), "=r"(d3) : "r"(addr));
}

__device__ __forceinline__ void cp16(uint32_t dst, const void* src) {
    asm volatile("cp.async.cg.shared.global [%0], [%1], 16;\n" :: "r"(dst), "l"(src));
}
__device__ __forceinline__ void cp_commit() {
    asm volatile("cp.async.commit_group;\n");
}
template<int N>
__device__ __forceinline__ void cp_wait() {
    asm volatile("cp.async.wait_group %0;\n" :: "n"(N));
}

// pack two fp32 into bf16x2 hi and lo words (low half = first arg)
__device__ __forceinline__ void pack_split2(float a, float b, uint32_t& hi, uint32_t& lo) {
    __nv_bfloat16 ha = __float2bfloat16(a), hb = __float2bfloat16(b);
    __nv_bfloat16 la = __float2bfloat16(a - __bfloat162float(ha));
    __nv_bfloat16 lb = __float2bfloat16(b - __bfloat162float(hb));
    __nv_bfloat162 h2 = __halves2bfloat162(ha, hb);
    __nv_bfloat162 l2 = __halves2bfloat162(la, lb);
    hi = *reinterpret_cast<uint32_t*>(&h2);
    lo = *reinterpret_cast<uint32_t*>(&l2);
}

// ---------------------------------------------------------------------------
// x split (linear, no transpose): x -> g_xh/g_xl
// ---------------------------------------------------------------------------
__global__ void xsplit_kernel(const float* __restrict__ src, size_t n) {
    size_t i = ((size_t)blockIdx.x * blockDim.x + threadIdx.x) * 4;
    if (i >= n) return;
    float4 v = *(const float4*)(src + i);
    uint32_t h0, l0, h1, l1;
    pack_split2(v.x, v.y, h0, l0);
    pack_split2(v.z, v.w, h1, l1);
    *(uint32_t*)(g_xh + i)     = h0;
    *(uint32_t*)(g_xh + i + 2) = h1;
    *(uint32_t*)(g_xl + i)     = l0;
    *(uint32_t*)(g_xl + i + 2) = l1;
}

// ---------------------------------------------------------------------------
// Weight transpose + split: src [K=1024][N] fp32 -> dst [N][1024] bf16 hi/lo.
//   WHICH 1: w_qkv -> g_wqh/g_wql    WHICH 2: w_out -> g_woh/g_wol
// ---------------------------------------------------------------------------
template<int WHICH>
__global__ void wsplit_kernel(const float* __restrict__ src, int N) {
    __shared__ float t32[32][33];
    __nv_bfloat16* dh = (WHICH == 1) ? g_wqh : g_woh;
    __nv_bfloat16* dl = (WHICH == 1) ? g_wql : g_wol;
    const int k0 = blockIdx.y * 32, n0 = blockIdx.x * 32;
    const int tid = threadIdx.x;
    const int r0 = tid >> 5, c = tid & 31;
    #pragma unroll
    for (int rr = 0; rr < 4; rr++)
        t32[r0 + rr*8][c] = src[(size_t)(k0 + r0 + rr*8)*N + n0 + c];
    __syncthreads();
    const int n = tid >> 3, kq = (tid & 7) * 4;
    float v0 = t32[kq  ][n], v1 = t32[kq+1][n];
    float v2 = t32[kq+2][n], v3 = t32[kq+3][n];
    uint32_t h0, l0, h1, l1;
    pack_split2(v0, v1, h0, l0);
    pack_split2(v2, v3, h1, l1);
    size_t idx = (size_t)(n0 + n)*Cq + k0 + kq;
    *(uint2*)(dh + idx) = make_uint2(h0, h1);
    *(uint2*)(dl + idx) = make_uint2(l0, l1);
}

// ---------------------------------------------------------------------------
// Length kernel: robust to padding_mask being bool(u8), int32, or float32.
// ---------------------------------------------------------------------------
__global__ void len_kernel(const unsigned char* __restrict__ mraw) {
    __shared__ int code;
    __shared__ int partial[256];
    if (threadIdx.x == 0) {
        if (mraw[1] == 1) code = 0;
        else if (((const int*)mraw)[0] == 1) code = 1;
        else code = 2;
    }
    __syncthreads();
    const int c = code;
    const int b = blockIdx.x;
    int cnt = 0;
    for (int t = threadIdx.x; t < Tq; t += blockDim.x) {
        int idx = b * Tq + t;
        bool m;
        if (c == 0)      m = mraw[idx] != 0;
        else if (c == 1) m = ((const int*)mraw)[idx] != 0;
        else             m = ((const float*)mraw)[idx] != 0.0f;
        cnt += m ? 1 : 0;
    }
    partial[threadIdx.x] = cnt;
    __syncthreads();
    for (int s = 128; s > 0; s >>= 1) {
        if (threadIdx.x < s) partial[threadIdx.x] += partial[threadIdx.x + s];
        __syncthreads();
    }
    if (threadIdx.x == 0) g_len[b] = partial[0];
}

// ---------------------------------------------------------------------------
// Split-bf16 tensor-core GEMM, cp.async 3-stage pipeline, ldmatrix operands.
// A [M][K] row-major hi/lo. B [N][K] row-major hi/lo (pre-transposed weights).
//   MODE 0: qkv = x @ w_qkv, epilogue -> g_{q,k,v}{h,l}; skips K/V blocks
//           whose whole t-range is masked (stale values provably unread).
//   MODE 3: out = ctx @ w_out + b_out (fp32 out to Cg)
// BM=BN=128, BK=32, 8 warps (2x4), warp tile 64x32. 3-pass split MMA.
// Dyn smem: 3 stages x (Ah,Al,Bh,Bl)[128][40] = 122880 B.
// ---------------------------------------------------------------------------
#define GP 40                        // smem pitch (bf16)
#define G_ARR (128*GP)               // 5120 elems per array
#define G_STAGE (4*G_ARR)            // 20480 elems per stage
#define GEMM_SMEM (3*G_STAGE*2)      // 122880 bytes

template<int MODE>
__global__ void __launch_bounds__(256)
mma_gemm_bf(float* __restrict__ Cg, const float* __restrict__ bias,
            int M, int N, int K)
{
    extern __shared__ __nv_bfloat16 smg[];

    const int bm = blockIdx.y * 128;
    const int bn = blockIdx.x * 128;

    if (MODE == 0) {
        // K/V column parts: skip blocks fully beyond this batch's length.
        int part = bn >> 10;
        if (part >= 1 && (bm & (Tq - 1)) >= g_len[bm >> 11]) return;
    }

    const __nv_bfloat16* Agh = (MODE == 0) ? g_xh : g_ctxh;
    const __nv_bfloat16* Agl = (MODE == 0) ? g_xl : g_ctxl;
    const __nv_bfloat16* Bgh = (MODE == 0) ? g_wqh : g_woh;
    const __nv_bfloat16* Bgl = (MODE == 0) ? g_wql : g_wol;

    const int tid  = threadIdx.x;
    const int lane = tid & 31;
    const int warp = tid >> 5;
    const int wm   = warp >> 2;
    const int wn   = warp & 3;
    const int r4   = lane >> 2;
    const int c2   = (lane & 3) * 2;

    const uint32_t sb = (uint32_t)__cvta_generic_to_shared(smg);

    // ldmatrix per-lane byte offsets
    //  A (a0..a3 frag): lanes 0-15 -> rows m+0..15 col k0, lanes 16-31 -> col k0+8
    const uint32_t la = ((lane & 15) * GP + (lane >> 4) * 8) * 2;
    //  B (two n8-frag pairs): d0/d1 = rows n0..7 (k0,k0+8), d2/d3 = rows n8..15
    const uint32_t lb = (((lane & 7) + ((lane >> 4) << 3)) * GP + ((lane >> 3) & 1) * 8) * 2;

    // cp.async staging: 2048 chunks of 16B per stage, 8 per thread
    auto issue = [&](int st, int k0) {
        #pragma unroll
        for (int i = tid; i < 2048; i += 256) {
            int arr = i >> 9, j = i & 511, r = j >> 2, c = j & 3;
            const __nv_bfloat16* src =
                (arr == 0) ? Agh + (size_t)(bm + r)*K + k0 + c*8 :
                (arr == 1) ? Agl + (size_t)(bm + r)*K + k0 + c*8 :
                (arr == 2) ? Bgh + (size_t)(bn + r)*K + k0 + c*8 :
                             Bgl + (size_t)(bn + r)*K + k0 + c*8;
            uint32_t dst = sb + (st*G_STAGE + arr*G_ARR + r*GP + c*8)*2;
            cp16(dst, src);
        }
        cp_commit();
    };

    float acc[4][4][4];
    #pragma unroll
    for (int i = 0; i < 4; i++)
        #pragma unroll
        for (int j = 0; j < 4; j++)
            #pragma unroll
            for (int r = 0; r < 4; r++) acc[i][j][r] = 0.0f;

    const int NS = K / 32;
    issue(0, 0);
    issue(1, 32);

    for (int s = 0; s < NS; s++) {
        if (s + 1 < NS) cp_wait<1>(); else cp_wait<0>();
        __syncthreads();
        if (s + 2 < NS) issue((s + 2) % 3, (s + 2) * 32);

        const uint32_t stg = sb + (s % 3)*G_STAGE*2;
        const uint32_t Ahb = stg;
        const uint32_t Alb = stg + G_ARR*2;
        const uint32_t Bhb = stg + 2*G_ARR*2;
        const uint32_t Blb = stg + 3*G_ARR*2;

        #pragma unroll
        for (int ks = 0; ks < 2; ks++) {
            uint32_t ah[4][4], al[4][4], bh[4][2], bl[4][2];
            #pragma unroll
            for (int mt = 0; mt < 4; mt++) {
                const uint32_t off = ((wm*64 + mt*16)*GP + ks*16)*2;
                ldmx4(ah[mt][0], ah[mt][1], ah[mt][2], ah[mt][3], Ahb + la + off);
                ldmx4(al[mt][0], al[mt][1], al[mt][2], al[mt][3], Alb + la + off);
            }
            #pragma unroll
            for (int np = 0; np < 2; np++) {
                const uint32_t off = ((wn*32 + np*16)*GP + ks*16)*2;
                uint32_t d0, d1, d2, d3;
                ldmx4(d0, d1, d2, d3, Bhb + lb + off);
                bh[2*np][0] = d0; bh[2*np][1] = d1;
                bh[2*np+1][0] = d2; bh[2*np+1][1] = d3;
                ldmx4(d0, d1, d2, d3, Blb + lb + off);
                bl[2*np][0] = d0; bl[2*np][1] = d1;
                bl[2*np+1][0] = d2; bl[2*np+1][1] = d3;
            }
            #pragma unroll
            for (int mt = 0; mt < 4; mt++)
                #pragma unroll
                for (int nt = 0; nt < 4; nt++) {
                    mma16816(acc[mt][nt], ah[mt], bh[nt]);
                    mma16816(acc[mt][nt], ah[mt], bl[nt]);
                    mma16816(acc[mt][nt], al[mt], bh[nt]);
                }
        }
        __syncthreads();
    }

    // epilogue
    #pragma unroll
    for (int mt = 0; mt < 4; mt++) {
        #pragma unroll
        for (int nt = 0; nt < 4; nt++) {
            int m0 = bm + wm*64 + mt*16 + r4;
            int n0 = bn + wn*32 + nt*8 + c2;
            const float* cr = acc[mt][nt];
            #pragma unroll
            for (int half = 0; half < 2; half++) {
                int m = m0 + half*8;
                float v0 = cr[half*2], v1 = cr[half*2+1];
                if (MODE == 0) {
                    int bb = m / Tq, t = m % Tq;
                    int part = n0 >> 10, hh = (n0 & 1023) >> 6, d = n0 & 63;
                    size_t idx = ((size_t)(bb*Hq + hh)*Tq + t)*Dq + d;
                    __nv_bfloat16* dsth = (part == 0) ? g_qh : (part == 1) ? g_kh : g_vh;
                    __nv_bfloat16* dstl = (part == 0) ? g_ql : (part == 1) ? g_kl : g_vl;
                    uint32_t hi, lo;
                    pack_split2(v0, v1, hi, lo);
                    *(uint32_t*)(dsth + idx) = hi;
                    *(uint32_t*)(dstl + idx) = lo;
                } else {
                    *(float2*)&Cg[(size_t)m*N + n0] =
                        make_float2(v0 + bias[n0], v1 + bias[n0+1]);
                }
            }
        }
    }
}

// ---------------------------------------------------------------------------
// Fused flash attention, cp.async 2-stage double buffered kv tiles.
// Per (q-tile 128, bh) CTA, 8 warps, warp = 16 q rows. Skips masked tiles.
// K and V both staged row-major [kv][d]; B-fragments via ldmatrix:
//   QK^T: non-trans x4 on K tiles; PV: trans x4 on V tiles.
// Dyn smem: 2 stages x (Kh,Kl,Vh,Vl)[128][72] = 147456 B.
// ---------------------------------------------------------------------------
#define FP 72                         // smem pitch (bf16)
#define F_ARR (128*FP)                // 9216 elems
#define F_STAGE (4*F_ARR)             // 36864 elems
#define FLASH_SMEM (2*F_STAGE*2)      // 147456 bytes

__global__ void __launch_bounds__(256, 1) flash_kernel() {
    extern __shared__ __nv_bfloat16 smf[];

    const int tid  = threadIdx.x;
    const int lane = tid & 31;
    const int warp = tid >> 5;
    const int r4   = lane >> 2;
    const int c2   = (lane & 3) * 2;
    const int bh   = blockIdx.y;
    const int b    = bh >> 4;
    const int qrow = blockIdx.x * 128 + warp * 16;
    const int len  = g_len[b];
    const int ntiles = (len + 127) >> 7;

    const size_t base = (size_t)bh * Tq * Dq;
    const uint32_t sb = (uint32_t)__cvta_generic_to_shared(smf);

    // per-thread ldmatrix byte offsets
    const uint32_t lk = ((((lane & 7) + ((lane >> 4) << 3)) * FP + ((lane >> 3) & 1) * 8)) * 2;
    const uint32_t lv = (((lane & 15) * FP + ((lane >> 4) << 3))) * 2;

    auto issue = [&](int s, int kv0) {
        #pragma unroll
        for (int i = tid; i < 4096; i += 256) {
            int arr = i >> 10, j = i & 1023, r = j >> 3, c = j & 7;
            const __nv_bfloat16* src =
                (arr == 0) ? g_kh + base + (size_t)(kv0 + r)*Dq + c*8 :
                (arr == 1) ? g_kl + base + (size_t)(kv0 + r)*Dq + c*8 :
                (arr == 2) ? g_vh + base + (size_t)(kv0 + r)*Dq + c*8 :
                             g_vl + base + (size_t)(kv0 + r)*Dq + c*8;
            uint32_t dst = sb + (s*F_STAGE + arr*F_ARR + r*FP + c*8)*2;
            cp16(dst, src);
        }
        cp_commit();
    };

    // Q fragments, persistent in registers (A operand, K-dim = D = 64)
    uint32_t qh[4][4], ql[4][4];
    #pragma unroll
    for (int ks = 0; ks < 4; ks++) {
        int kc = ks*16 + c2;
        qh[ks][0] = *(const uint32_t*)&g_qh[base + (size_t)(qrow + r4    )*Dq + kc];
        qh[ks][1] = *(const uint32_t*)&g_qh[base + (size_t)(qrow + r4 + 8)*Dq + kc];
        qh[ks][2] = *(const uint32_t*)&g_qh[base + (size_t)(qrow + r4    )*Dq + kc + 8];
        qh[ks][3] = *(const uint32_t*)&g_qh[base + (size_t)(qrow + r4 + 8)*Dq + kc + 8];
        ql[ks][0] = *(const uint32_t*)&g_ql[base + (size_t)(qrow + r4    )*Dq + kc];
        ql[ks][1] = *(const uint32_t*)&g_ql[base + (size_t)(qrow + r4 + 8)*Dq + kc];
        ql[ks][2] = *(const uint32_t*)&g_ql[base + (size_t)(qrow + r4    )*Dq + kc + 8];
        ql[ks][3] = *(const uint32_t*)&g_ql[base + (size_t)(qrow + r4 + 8)*Dq + kc + 8];
    }

    float Oacc[8][4];
    #pragma unroll
    for (int i = 0; i < 8; i++)
        #pragma unroll
        for (int j = 0; j < 4; j++) Oacc[i][j] = 0.0f;
    float m_run[2] = {-CUDART_INF_F, -CUDART_INF_F};
    float l_run[2] = {0.0f, 0.0f};

    issue(0, 0);

    for (int kt = 0; kt < ntiles; kt++) {
        const int kv0 = kt * 128;
        if (kt + 1 < ntiles) { issue((kt + 1) & 1, kv0 + 128); cp_wait<1>(); }
        else                 { cp_wait<0>(); }
        __syncthreads();

        const uint32_t stg = sb + (kt & 1)*F_STAGE*2;
        const uint32_t Khb = stg;
        const uint32_t Klb = stg + F_ARR*2;
        const uint32_t Vhb = stg + 2*F_ARR*2;
        const uint32_t Vlb = stg + 3*F_ARR*2;

        // ---- S = Q K^T ----
        float S[16][4];
        #pragma unroll
        for (int nt = 0; nt < 16; nt++)
            #pragma unroll
            for (int j = 0; j < 4; j++) S[nt][j] = 0.0f;
        #pragma unroll
        for (int ks = 0; ks < 4; ks++) {
            #pragma unroll
            for (int np = 0; np < 8; np++) {          // nt pairs
                const uint32_t off = (np*16*FP + ks*16)*2;
                uint32_t h0,h1,h2,h3, l0,l1,l2,l3;
                ldmx4(h0, h1, h2, h3, Khb + lk + off);
                ldmx4(l0, l1, l2, l3, Klb + lk + off);
                uint32_t bh0[2] = {h0, h1}, bh1[2] = {h2, h3};
                uint32_t bl0[2] = {l0, l1}, bl1[2] = {l2, l3};
                mma16816(S[2*np  ], qh[ks], bh0);
                mma16816(S[2*np  ], qh[ks], bl0);
                mma16816(S[2*np  ], ql[ks], bh0);
                mma16816(S[2*np+1], qh[ks], bh1);
                mma16816(S[2*np+1], qh[ks], bl1);
                mma16816(S[2*np+1], ql[ks], bh1);
            }
        }

        // ---- scale + mask + row max ----
        float rmax[2] = {-CUDART_INF_F, -CUDART_INF_F};
        #pragma unroll
        for (int nt = 0; nt < 16; nt++) {
            #pragma unroll
            for (int j = 0; j < 4; j++) {
                int kv = kv0 + nt*8 + c2 + (j & 1);
                float s = S[nt][j] * 0.125f;
                s = (kv < len) ? s : -CUDART_INF_F;
                S[nt][j] = s;
                rmax[j >> 1] = fmaxf(rmax[j >> 1], s);
            }
        }
        #pragma unroll
        for (int j = 0; j < 2; j++) {
            rmax[j] = fmaxf(rmax[j], __shfl_xor_sync(0xffffffffu, rmax[j], 1));
            rmax[j] = fmaxf(rmax[j], __shfl_xor_sync(0xffffffffu, rmax[j], 2));
        }

        float m_new[2], alpha[2];
        #pragma unroll
        for (int j = 0; j < 2; j++) {
            m_new[j] = fmaxf(m_run[j], rmax[j]);
            alpha[j] = exp2f((m_run[j] - m_new[j]) * LOG2E);
            m_run[j] = m_new[j];
        }

        // ---- exponentiate + row sum ----
        float rsum[2] = {0.0f, 0.0f};
        #pragma unroll
        for (int nt = 0; nt < 16; nt++) {
            #pragma unroll
            for (int j = 0; j < 4; j++) {
                float p = exp2f((S[nt][j] - m_new[j >> 1]) * LOG2E);
                S[nt][j] = p;
                rsum[j >> 1] += p;
            }
        }
        #pragma unroll
        for (int j = 0; j < 2; j++) {
            rsum[j] += __shfl_xor_sync(0xffffffffu, rsum[j], 1);
            rsum[j] += __shfl_xor_sync(0xffffffffu, rsum[j], 2);
            l_run[j] = l_run[j] * alpha[j] + rsum[j];
        }
        #pragma unroll
        for (int i = 0; i < 8; i++) {
            Oacc[i][0] *= alpha[0]; Oacc[i][1] *= alpha[0];
            Oacc[i][2] *= alpha[1]; Oacc[i][3] *= alpha[1];
        }

        // ---- O += P V : P frags from S in registers, V frags via ldmatrix.trans
        #pragma unroll
        for (int kk = 0; kk < 8; kk++) {
            uint32_t pah[4], pal[4];
            pack_split2(S[2*kk  ][0], S[2*kk  ][1], pah[0], pal[0]);
            pack_split2(S[2*kk  ][2], S[2*kk  ][3], pah[1], pal[1]);
            pack_split2(S[2*kk+1][0], S[2*kk+1][1], pah[2], pal[2]);
            pack_split2(S[2*kk+1][2], S[2*kk+1][3], pah[3], pal[3]);
            #pragma unroll
            for (int dp = 0; dp < 4; dp++) {          // d-block pairs
                const uint32_t off = (kk*16*FP + dp*16)*2;
                uint32_t h0,h1,h2,h3, l0,l1,l2,l3;
                ldmx4t(h0, h1, h2, h3, Vhb + lv + off);
                ldmx4t(l0, l1, l2, l3, Vlb + lv + off);
                uint32_t bh0[2] = {h0, h1}, bh1[2] = {h2, h3};
                uint32_t bl0[2] = {l0, l1}, bl1[2] = {l2, l3};
                mma16816(Oacc[2*dp  ], pah, bh0);
                mma16816(Oacc[2*dp  ], pah, bl0);
                mma16816(Oacc[2*dp  ], pal, bh0);
                mma16816(Oacc[2*dp+1], pah, bh1);
                mma16816(Oacc[2*dp+1], pah, bl1);
                mma16816(Oacc[2*dp+1], pal, bh1);
            }
        }
        __syncthreads();
    }

    // ---- finalize: O /= l, write ctx hi/lo bf16 [B,T,C] ----
    const float inv0 = 1.0f / l_run[0];
    const float inv1 = 1.0f / l_run[1];
    const int hh = bh & 15;
    const size_t base0 = ((size_t)(b*Tq + qrow + r4    ))*Cq + hh*Dq;
    const size_t base1 = ((size_t)(b*Tq + qrow + r4 + 8))*Cq + hh*Dq;
    #pragma unroll
    for (int ntd = 0; ntd < 8; ntd++) {
        int d0 = ntd*8 + c2;
        uint32_t hi, lo;
        pack_split2(Oacc[ntd][0]*inv0, Oacc[ntd][1]*inv0, hi, lo);
        *(uint32_t*)(g_ctxh + base0 + d0) = hi;
        *(uint32_t*)(g_ctxl + base0 + d0) = lo;
        pack_split2(Oacc[ntd][2]*inv1, Oacc[ntd][3]*inv1, hi, lo);
        *(uint32_t*)(g_ctxh + base1 + d0) = hi;
        *(uint32_t*)(g_ctxl + base1 + d0) = lo;
    }
}

// ---------------------------------------------------------------------------
extern "C" void kernel_launch(void* const* d_in, const int* in_sizes, int n_in,
                              void* d_out, int out_size)
{
    const float*         x     = (const float*)d_in[0];
    const unsigned char* mask  = (const unsigned char*)d_in[1];
    const float*         w_qkv = (const float*)d_in[2];
    const float*         w_out = (const float*)d_in[3];
    const float*         b_out = (const float*)d_in[4];
    float*               out   = (float*)d_out;

    // 0. pre-split x (linear) and weights (transposed to [N][K])
    xsplit_kernel<<<(Bq*Tq*Cq)/1024, 256>>>(x, (size_t)Bq*Tq*Cq);
    wsplit_kernel<1><<<dim3(3*Cq/32, Cq/32), 256>>>(w_qkv, 3*Cq);
    wsplit_kernel<2><<<dim3(Cq/32, Cq/32), 256>>>(w_out, Cq);

    // 1. lengths (before QKV GEMM: it reads g_len for block skipping)
    len_kernel<<<Bq, 256>>>(mask);

    // 2. QKV projection -> Q/K/V hi/lo [BH,T,D]
    cudaFuncSetAttribute(mma_gemm_bf<0>,
                         cudaFuncAttributeMaxDynamicSharedMemorySize, GEMM_SMEM);
    mma_gemm_bf<0><<<dim3(3*Cq/128, Bq*Tq/128), 256, GEMM_SMEM>>>(
        nullptr, nullptr, Bq*Tq, 3*Cq, Cq);

    // 3. fused flash attention -> ctx hi/lo
    cudaFuncSetAttribute(flash_kernel,
                         cudaFuncAttributeMaxDynamicSharedMemorySize, FLASH_SMEM);
    flash_kernel<<<dim3(Tq/128, BHq), 256, FLASH_SMEM>>>();

    // 4. output projection + bias
    cudaFuncSetAttribute(mma_gemm_bf<3>,
                         cudaFuncAttributeMaxDynamicSharedMemorySize, GEMM_SMEM);
    mma_gemm_bf<3><<<dim3(Cq/128, Bq*Tq/128), 256, GEMM_SMEM>>>(
        out, b_out, Bq*Tq, Cq, Cq);
}

// round 12
// speedup vs baseline: 4.2905x; 1.0099x over previous
#include <cuda_runtime.h>
#include <cuda_bf16.h>
#include <math_constants.h>
#include <stdint.h>

// Problem constants
#define Bq 4
#define Tq 2048
#define Cq 1024
#define Hq 16
#define Dq 64
#define BHq (Bq*Hq)

#define LOG2E 1.4426950408889634f

// ---------------------------------------------------------------------------
// Scratch (device globals, allocation-free). ONLY referenced from device code.
// Weights stored TRANSPOSED: [N][K] so GEMM B staging = vectorized row copies.
// ---------------------------------------------------------------------------
__device__ __nv_bfloat16 g_xh[(size_t)Bq*Tq*Cq];        // x split [M][K]
__device__ __nv_bfloat16 g_xl[(size_t)Bq*Tq*Cq];
__device__ __nv_bfloat16 g_wqh[(size_t)3*Cq*Cq];        // w_qkv^T split [3C][C]
__device__ __nv_bfloat16 g_wql[(size_t)3*Cq*Cq];
__device__ __nv_bfloat16 g_woh[(size_t)Cq*Cq];          // w_out^T split [C][C]
__device__ __nv_bfloat16 g_wol[(size_t)Cq*Cq];
__device__ __nv_bfloat16 g_qh[(size_t)BHq*Tq*Dq];       // Q/K/V split [BH][T][D]
__device__ __nv_bfloat16 g_ql[(size_t)BHq*Tq*Dq];
__device__ __nv_bfloat16 g_kh[(size_t)BHq*Tq*Dq];
__device__ __nv_bfloat16 g_kl[(size_t)BHq*Tq*Dq];
__device__ __nv_bfloat16 g_vh[(size_t)BHq*Tq*Dq];
__device__ __nv_bfloat16 g_vl[(size_t)BHq*Tq*Dq];
__device__ __nv_bfloat16 g_ctxh[(size_t)Bq*Tq*Cq];      // attention out split
__device__ __nv_bfloat16 g_ctxl[(size_t)Bq*Tq*Cq];
__device__ int g_len[Bq];

// ---------------------------------------------------------------------------
__device__ __forceinline__ void mma16816(float* d, const uint32_t* a, const uint32_t* b) {
    asm volatile(
        "mma.sync.aligned.m16n8k16.row.col.f32.bf16.bf16.f32 "
        "{%0,%1,%2,%3}, {%4,%5,%6,%7}, {%8,%9}, {%0,%1,%2,%3};\n"
        : "+f"(d[0]), "+f"(d[1]), "+f"(d[2]), "+f"(d[3])
        : "r"(a[0]), "r"(a[1]), "r"(a[2]), "r"(a[3]),
          "r"(b[0]), "r"(b[1]));
}

__device__ __forceinline__ void ldmx4(uint32_t& d0, uint32_t& d1, uint32_t& d2,
                                      uint32_t& d3, uint32_t addr) {
    asm volatile("ldmatrix.sync.aligned.m8n8.x4.shared.b16 {%0,%1,%2,%3}, [%4];"
        : "=r"(d0), "=r"(d1), "=r"(d2), "=r"(d3) : "r"(addr));
}
__device__ __forceinline__ void ldmx4t(uint32_t& d0, uint32_t& d1, uint32_t& d2,
                                       uint32_t& d3, uint32_t addr) {
    asm volatile("ldmatrix.sync.aligned.m8n8.x4.trans.shared.b16 {%0,%1,%2,%3}, [%4];"
        : "=r"(d0), "=r"(d1), "=r"(d2), "=r"(d3) : "r"(addr));
}

__device__ __forceinline__ void cp16(uint32_t dst, const void* src) {
    asm volatile("cp.async.cg.shared.global [%0], [%1], 16;\n" :: "r"(dst), "l"(src));
}
__device__ __forceinline__ void cp_commit() {
    asm volatile("cp.async.commit_group;\n");
}
template<int N>
__device__ __forceinline__ void cp_wait() {
    asm volatile("cp.async.wait_group %0;\n" :: "n"(N));
}

// pack two fp32 into bf16x2 hi and lo words (low half = first arg)
__device__ __forceinline__ void pack_split2(float a, float b, uint32_t& hi, uint32_t& lo) {
    __nv_bfloat16 ha = __float2bfloat16(a), hb = __float2bfloat16(b);
    __nv_bfloat16 la = __float2bfloat16(a - __bfloat162float(ha));
    __nv_bfloat16 lb = __float2bfloat16(b - __bfloat162float(hb));
    __nv_bfloat162 h2 = __halves2bfloat162(ha, hb);
    __nv_bfloat162 l2 = __halves2bfloat162(la, lb);
    hi = *reinterpret_cast<uint32_t*>(&h2);
    lo = *reinterpret_cast<uint32_t*>(&l2);
}

// ---------------------------------------------------------------------------
// x split (linear, no transpose): x -> g_xh/g_xl
// ---------------------------------------------------------------------------
__global__ void xsplit_kernel(const float* __restrict__ src, size_t n) {
    size_t i = ((size_t)blockIdx.x * blockDim.x + threadIdx.x) * 4;
    if (i >= n) return;
    float4 v = *(const float4*)(src + i);
    uint32_t h0, l0, h1, l1;
    pack_split2(v.x, v.y, h0, l0);
    pack_split2(v.z, v.w, h1, l1);
    *(uint32_t*)(g_xh + i)     = h0;
    *(uint32_t*)(g_xh + i + 2) = h1;
    *(uint32_t*)(g_xl + i)     = l0;
    *(uint32_t*)(g_xl + i + 2) = l1;
}

// ---------------------------------------------------------------------------
// Weight transpose + split: src [K=1024][N] fp32 -> dst [N][1024] bf16 hi/lo.
//   WHICH 1: w_qkv -> g_wqh/g_wql    WHICH 2: w_out -> g_woh/g_wol
// ---------------------------------------------------------------------------
template<int WHICH>
__global__ void wsplit_kernel(const float* __restrict__ src, int N) {
    __shared__ float t32[32][33];
    __nv_bfloat16* dh = (WHICH == 1) ? g_wqh : g_woh;
    __nv_bfloat16* dl = (WHICH == 1) ? g_wql : g_wol;
    const int k0 = blockIdx.y * 32, n0 = blockIdx.x * 32;
    const int tid = threadIdx.x;
    const int r0 = tid >> 5, c = tid & 31;
    #pragma unroll
    for (int rr = 0; rr < 4; rr++)
        t32[r0 + rr*8][c] = src[(size_t)(k0 + r0 + rr*8)*N + n0 + c];
    __syncthreads();
    const int n = tid >> 3, kq = (tid & 7) * 4;
    float v0 = t32[kq  ][n], v1 = t32[kq+1][n];
    float v2 = t32[kq+2][n], v3 = t32[kq+3][n];
    uint32_t h0, l0, h1, l1;
    pack_split2(v0, v1, h0, l0);
    pack_split2(v2, v3, h1, l1);
    size_t idx = (size_t)(n0 + n)*Cq + k0 + kq;
    *(uint2*)(dh + idx) = make_uint2(h0, h1);
    *(uint2*)(dl + idx) = make_uint2(l0, l1);
}

// ---------------------------------------------------------------------------
// Length kernel: robust to padding_mask being bool(u8), int32, or float32.
// ---------------------------------------------------------------------------
__global__ void len_kernel(const unsigned char* __restrict__ mraw) {
    __shared__ int code;
    __shared__ int partial[256];
    if (threadIdx.x == 0) {
        if (mraw[1] == 1) code = 0;
        else if (((const int*)mraw)[0] == 1) code = 1;
        else code = 2;
    }
    __syncthreads();
    const int c = code;
    const int b = blockIdx.x;
    int cnt = 0;
    for (int t = threadIdx.x; t < Tq; t += blockDim.x) {
        int idx = b * Tq + t;
        bool m;
        if (c == 0)      m = mraw[idx] != 0;
        else if (c == 1) m = ((const int*)mraw)[idx] != 0;
        else             m = ((const float*)mraw)[idx] != 0.0f;
        cnt += m ? 1 : 0;
    }
    partial[threadIdx.x] = cnt;
    __syncthreads();
    for (int s = 128; s > 0; s >>= 1) {
        if (threadIdx.x < s) partial[threadIdx.x] += partial[threadIdx.x + s];
        __syncthreads();
    }
    if (threadIdx.x == 0) g_len[b] = partial[0];
}

// ---------------------------------------------------------------------------
// Split-bf16 tensor-core GEMM, cp.async 3-stage pipeline, ldmatrix operands.
// (unchanged from R10 — proven at 1104.6 us / rel_err 2.074725e-05)
//   MODE 0: qkv = x @ w_qkv, epilogue -> g_{q,k,v}{h,l}; skips K/V blocks
//           whose whole t-range is masked.
//   MODE 3: out = ctx @ w_out + b_out (fp32 out to Cg)
// ---------------------------------------------------------------------------
#define GP 40                        // smem pitch (bf16)
#define G_ARR (128*GP)               // 5120 elems per array
#define G_STAGE (4*G_ARR)            // 20480 elems per stage
#define GEMM_SMEM (3*G_STAGE*2)      // 122880 bytes

template<int MODE>
__global__ void __launch_bounds__(256)
mma_gemm_bf(float* __restrict__ Cg, const float* __restrict__ bias,
            int M, int N, int K)
{
    extern __shared__ __nv_bfloat16 smg[];

    const int bm = blockIdx.y * 128;
    const int bn = blockIdx.x * 128;

    if (MODE == 0) {
        int part = bn >> 10;
        if (part >= 1 && (bm & (Tq - 1)) >= g_len[bm >> 11]) return;
    }

    const __nv_bfloat16* Agh = (MODE == 0) ? g_xh : g_ctxh;
    const __nv_bfloat16* Agl = (MODE == 0) ? g_xl : g_ctxl;
    const __nv_bfloat16* Bgh = (MODE == 0) ? g_wqh : g_woh;
    const __nv_bfloat16* Bgl = (MODE == 0) ? g_wql : g_wol;

    const int tid  = threadIdx.x;
    const int lane = tid & 31;
    const int warp = tid >> 5;
    const int wm   = warp >> 2;
    const int wn   = warp & 3;
    const int r4   = lane >> 2;
    const int c2   = (lane & 3) * 2;

    const uint32_t sb = (uint32_t)__cvta_generic_to_shared(smg);

    const uint32_t la = ((lane & 15) * GP + (lane >> 4) * 8) * 2;
    const uint32_t lb = (((lane & 7) + ((lane >> 4) << 3)) * GP + ((lane >> 3) & 1) * 8) * 2;

    auto issue = [&](int st, int k0) {
        #pragma unroll
        for (int i = tid; i < 2048; i += 256) {
            int arr = i >> 9, j = i & 511, r = j >> 2, c = j & 3;
            const __nv_bfloat16* src =
                (arr == 0) ? Agh + (size_t)(bm + r)*K + k0 + c*8 :
                (arr == 1) ? Agl + (size_t)(bm + r)*K + k0 + c*8 :
                (arr == 2) ? Bgh + (size_t)(bn + r)*K + k0 + c*8 :
                             Bgl + (size_t)(bn + r)*K + k0 + c*8;
            uint32_t dst = sb + (st*G_STAGE + arr*G_ARR + r*GP + c*8)*2;
            cp16(dst, src);
        }
        cp_commit();
    };

    float acc[4][4][4];
    #pragma unroll
    for (int i = 0; i < 4; i++)
        #pragma unroll
        for (int j = 0; j < 4; j++)
            #pragma unroll
            for (int r = 0; r < 4; r++) acc[i][j][r] = 0.0f;

    const int NS = K / 32;
    issue(0, 0);
    issue(1, 32);

    for (int s = 0; s < NS; s++) {
        if (s + 1 < NS) cp_wait<1>(); else cp_wait<0>();
        __syncthreads();
        if (s + 2 < NS) issue((s + 2) % 3, (s + 2) * 32);

        const uint32_t stg = sb + (s % 3)*G_STAGE*2;
        const uint32_t Ahb = stg;
        const uint32_t Alb = stg + G_ARR*2;
        const uint32_t Bhb = stg + 2*G_ARR*2;
        const uint32_t Blb = stg + 3*G_ARR*2;

        #pragma unroll
        for (int ks = 0; ks < 2; ks++) {
            uint32_t ah[4][4], al[4][4], bh[4][2], bl[4][2];
            #pragma unroll
            for (int mt = 0; mt < 4; mt++) {
                const uint32_t off = ((wm*64 + mt*16)*GP + ks*16)*2;
                ldmx4(ah[mt][0], ah[mt][1], ah[mt][2], ah[mt][3], Ahb + la + off);
                ldmx4(al[mt][0], al[mt][1], al[mt][2], al[mt][3], Alb + la + off);
            }
            #pragma unroll
            for (int np = 0; np < 2; np++) {
                const uint32_t off = ((wn*32 + np*16)*GP + ks*16)*2;
                uint32_t d0, d1, d2, d3;
                ldmx4(d0, d1, d2, d3, Bhb + lb + off);
                bh[2*np][0] = d0; bh[2*np][1] = d1;
                bh[2*np+1][0] = d2; bh[2*np+1][1] = d3;
                ldmx4(d0, d1, d2, d3, Blb + lb + off);
                bl[2*np][0] = d0; bl[2*np][1] = d1;
                bl[2*np+1][0] = d2; bl[2*np+1][1] = d3;
            }
            #pragma unroll
            for (int mt = 0; mt < 4; mt++)
                #pragma unroll
                for (int nt = 0; nt < 4; nt++) {
                    mma16816(acc[mt][nt], ah[mt], bh[nt]);
                    mma16816(acc[mt][nt], ah[mt], bl[nt]);
                    mma16816(acc[mt][nt], al[mt], bh[nt]);
                }
        }
        __syncthreads();
    }

    #pragma unroll
    for (int mt = 0; mt < 4; mt++) {
        #pragma unroll
        for (int nt = 0; nt < 4; nt++) {
            int m0 = bm + wm*64 + mt*16 + r4;
            int n0 = bn + wn*32 + nt*8 + c2;
            const float* cr = acc[mt][nt];
            #pragma unroll
            for (int half = 0; half < 2; half++) {
                int m = m0 + half*8;
                float v0 = cr[half*2], v1 = cr[half*2+1];
                if (MODE == 0) {
                    int bb = m / Tq, t = m % Tq;
                    int part = n0 >> 10, hh = (n0 & 1023) >> 6, d = n0 & 63;
                    size_t idx = ((size_t)(bb*Hq + hh)*Tq + t)*Dq + d;
                    __nv_bfloat16* dsth = (part == 0) ? g_qh : (part == 1) ? g_kh : g_vh;
                    __nv_bfloat16* dstl = (part == 0) ? g_ql : (part == 1) ? g_kl : g_vl;
                    uint32_t hi, lo;
                    pack_split2(v0, v1, hi, lo);
                    *(uint32_t*)(dsth + idx) = hi;
                    *(uint32_t*)(dstl + idx) = lo;
                } else {
                    *(float2*)&Cg[(size_t)m*N + n0] =
                        make_float2(v0 + bias[n0], v1 + bias[n0+1]);
                }
            }
        }
    }
}

// ---------------------------------------------------------------------------
// Fused flash attention. KV tile = 64 (was 128): smem 73.7KB -> 2 CTAs/SM so
// one CTA's softmax (MUFU/FFMA) overlaps the other's HMMA. Same math.
// Dyn smem: 2 stages x (Kh,Kl,Vh,Vl)[64][72] = 73728 B.
// ---------------------------------------------------------------------------
#define FP 72                         // smem pitch (bf16)
#define F_ARR (64*FP)                 // 4608 elems
#define F_STAGE (4*F_ARR)             // 18432 elems
#define FLASH_SMEM (2*F_STAGE*2)      // 73728 bytes

__global__ void __launch_bounds__(256, 2) flash_kernel() {
    extern __shared__ __nv_bfloat16 smf[];

    const int tid  = threadIdx.x;
    const int lane = tid & 31;
    const int warp = tid >> 5;
    const int r4   = lane >> 2;
    const int c2   = (lane & 3) * 2;
    const int bh   = blockIdx.y;
    const int b    = bh >> 4;
    const int qrow = blockIdx.x * 128 + warp * 16;
    const int len  = g_len[b];
    const int ntiles = (len + 63) >> 6;

    const size_t base = (size_t)bh * Tq * Dq;
    const uint32_t sb = (uint32_t)__cvta_generic_to_shared(smf);

    // per-thread ldmatrix byte offsets
    const uint32_t lk = ((((lane & 7) + ((lane >> 4) << 3)) * FP + ((lane >> 3) & 1) * 8)) * 2;
    const uint32_t lv = (((lane & 15) * FP + ((lane >> 4) << 3))) * 2;

    auto issue = [&](int s, int kv0) {
        #pragma unroll
        for (int i = tid; i < 2048; i += 256) {
            int arr = i >> 9, j = i & 511, r = j >> 3, c = j & 7;
            const __nv_bfloat16* src =
                (arr == 0) ? g_kh + base + (size_t)(kv0 + r)*Dq + c*8 :
                (arr == 1) ? g_kl + base + (size_t)(kv0 + r)*Dq + c*8 :
                (arr == 2) ? g_vh + base + (size_t)(kv0 + r)*Dq + c*8 :
                             g_vl + base + (size_t)(kv0 + r)*Dq + c*8;
            uint32_t dst = sb + (s*F_STAGE + arr*F_ARR + r*FP + c*8)*2;
            cp16(dst, src);
        }
        cp_commit();
    };

    // Q fragments, persistent in registers (A operand, K-dim = D = 64)
    uint32_t qh[4][4], ql[4][4];
    #pragma unroll
    for (int ks = 0; ks < 4; ks++) {
        int kc = ks*16 + c2;
        qh[ks][0] = *(const uint32_t*)&g_qh[base + (size_t)(qrow + r4    )*Dq + kc];
        qh[ks][1] = *(const uint32_t*)&g_qh[base + (size_t)(qrow + r4 + 8)*Dq + kc];
        qh[ks][2] = *(const uint32_t*)&g_qh[base + (size_t)(qrow + r4    )*Dq + kc + 8];
        qh[ks][3] = *(const uint32_t*)&g_qh[base + (size_t)(qrow + r4 + 8)*Dq + kc + 8];
        ql[ks][0] = *(const uint32_t*)&g_ql[base + (size_t)(qrow + r4    )*Dq + kc];
        ql[ks][1] = *(const uint32_t*)&g_ql[base + (size_t)(qrow + r4 + 8)*Dq + kc];
        ql[ks][2] = *(const uint32_t*)&g_ql[base + (size_t)(qrow + r4    )*Dq + kc + 8];
        ql[ks][3] = *(const uint32_t*)&g_ql[base + (size_t)(qrow + r4 + 8)*Dq + kc + 8];
    }

    float Oacc[8][4];
    #pragma unroll
    for (int i = 0; i < 8; i++)
        #pragma unroll
        for (int j = 0; j < 4; j++) Oacc[i][j] = 0.0f;
    float m_run[2] = {-CUDART_INF_F, -CUDART_INF_F};
    float l_run[2] = {0.0f, 0.0f};

    issue(0, 0);

    for (int kt = 0; kt < ntiles; kt++) {
        const int kv0 = kt * 64;
        if (kt + 1 < ntiles) { issue((kt + 1) & 1, kv0 + 64); cp_wait<1>(); }
        else                 { cp_wait<0>(); }
        __syncthreads();

        const uint32_t stg = sb + (kt & 1)*F_STAGE*2;
        const uint32_t Khb = stg;
        const uint32_t Klb = stg + F_ARR*2;
        const uint32_t Vhb = stg + 2*F_ARR*2;
        const uint32_t Vlb = stg + 3*F_ARR*2;

        // ---- S = Q K^T  (64 kv rows -> S[8][4]) ----
        float S[8][4];
        #pragma unroll
        for (int nt = 0; nt < 8; nt++)
            #pragma unroll
            for (int j = 0; j < 4; j++) S[nt][j] = 0.0f;
        #pragma unroll
        for (int ks = 0; ks < 4; ks++) {
            #pragma unroll
            for (int np = 0; np < 4; np++) {          // nt pairs
                const uint32_t off = (np*16*FP + ks*16)*2;
                uint32_t h0,h1,h2,h3, l0,l1,l2,l3;
                ldmx4(h0, h1, h2, h3, Khb + lk + off);
                ldmx4(l0, l1, l2, l3, Klb + lk + off);
                uint32_t bh0[2] = {h0, h1}, bh1[2] = {h2, h3};
                uint32_t bl0[2] = {l0, l1}, bl1[2] = {l2, l3};
                mma16816(S[2*np  ], qh[ks], bh0);
                mma16816(S[2*np  ], qh[ks], bl0);
                mma16816(S[2*np  ], ql[ks], bh0);
                mma16816(S[2*np+1], qh[ks], bh1);
                mma16816(S[2*np+1], qh[ks], bl1);
                mma16816(S[2*np+1], ql[ks], bh1);
            }
        }

        // ---- scale + mask + row max ----
        float rmax[2] = {-CUDART_INF_F, -CUDART_INF_F};
        #pragma unroll
        for (int nt = 0; nt < 8; nt++) {
            #pragma unroll
            for (int j = 0; j < 4; j++) {
                int kv = kv0 + nt*8 + c2 + (j & 1);
                float s = S[nt][j] * 0.125f;
                s = (kv < len) ? s : -CUDART_INF_F;
                S[nt][j] = s;
                rmax[j >> 1] = fmaxf(rmax[j >> 1], s);
            }
        }
        #pragma unroll
        for (int j = 0; j < 2; j++) {
            rmax[j] = fmaxf(rmax[j], __shfl_xor_sync(0xffffffffu, rmax[j], 1));
            rmax[j] = fmaxf(rmax[j], __shfl_xor_sync(0xffffffffu, rmax[j], 2));
        }

        float m_new[2], alpha[2];
        #pragma unroll
        for (int j = 0; j < 2; j++) {
            m_new[j] = fmaxf(m_run[j], rmax[j]);
            alpha[j] = exp2f((m_run[j] - m_new[j]) * LOG2E);
            m_run[j] = m_new[j];
        }

        // ---- exponentiate + row sum ----
        float rsum[2] = {0.0f, 0.0f};
        #pragma unroll
        for (int nt = 0; nt < 8; nt++) {
            #pragma unroll
            for (int j = 0; j < 4; j++) {
                float p = exp2f((S[nt][j] - m_new[j >> 1]) * LOG2E);
                S[nt][j] = p;
                rsum[j >> 1] += p;
            }
        }
        #pragma unroll
        for (int j = 0; j < 2; j++) {
            rsum[j] += __shfl_xor_sync(0xffffffffu, rsum[j], 1);
            rsum[j] += __shfl_xor_sync(0xffffffffu, rsum[j], 2);
            l_run[j] = l_run[j] * alpha[j] + rsum[j];
        }
        #pragma unroll
        for (int i = 0; i < 8; i++) {
            Oacc[i][0] *= alpha[0]; Oacc[i][1] *= alpha[0];
            Oacc[i][2] *= alpha[1]; Oacc[i][3] *= alpha[1];
        }

        // ---- O += P V : P frags from S in registers, V frags via ldmatrix.trans
        #pragma unroll
        for (int kk = 0; kk < 4; kk++) {              // 4 k16 steps (64 kv)
            uint32_t pah[4], pal[4];
            pack_split2(S[2*kk  ][0], S[2*kk  ][1], pah[0], pal[0]);
            pack_split2(S[2*kk  ][2], S[2*kk  ][3], pah[1], pal[1]);
            pack_split2(S[2*kk+1][0], S[2*kk+1][1], pah[2], pal[2]);
            pack_split2(S[2*kk+1][2], S[2*kk+1][3], pah[3], pal[3]);
            #pragma unroll
            for (int dp = 0; dp < 4; dp++) {          // d-block pairs
                const uint32_t off = (kk*16*FP + dp*16)*2;
                uint32_t h0,h1,h2,h3, l0,l1,l2,l3;
                ldmx4t(h0, h1, h2, h3, Vhb + lv + off);
                ldmx4t(l0, l1, l2, l3, Vlb + lv + off);
                uint32_t bh0[2] = {h0, h1}, bh1[2] = {h2, h3};
                uint32_t bl0[2] = {l0, l1}, bl1[2] = {l2, l3};
                mma16816(Oacc[2*dp  ], pah, bh0);
                mma16816(Oacc[2*dp  ], pah, bl0);
                mma16816(Oacc[2*dp  ], pal, bh0);
                mma16816(Oacc[2*dp+1], pah, bh1);
                mma16816(Oacc[2*dp+1], pah, bl1);
                mma16816(Oacc[2*dp+1], pal, bh1);
            }
        }
        __syncthreads();
    }

    // ---- finalize: O /= l, write ctx hi/lo bf16 [B,T,C] ----
    const float inv0 = 1.0f / l_run[0];
    const float inv1 = 1.0f / l_run[1];
    const int hh = bh & 15;
    const size_t base0 = ((size_t)(b*Tq + qrow + r4    ))*Cq + hh*Dq;
    const size_t base1 = ((size_t)(b*Tq + qrow + r4 + 8))*Cq + hh*Dq;
    #pragma unroll
    for (int ntd = 0; ntd < 8; ntd++) {
        int d0 = ntd*8 + c2;
        uint32_t hi, lo;
        pack_split2(Oacc[ntd][0]*inv0, Oacc[ntd][1]*inv0, hi, lo);
        *(uint32_t*)(g_ctxh + base0 + d0) = hi;
        *(uint32_t*)(g_ctxl + base0 + d0) = lo;
        pack_split2(Oacc[ntd][2]*inv1, Oacc[ntd][3]*inv1, hi, lo);
        *(uint32_t*)(g_ctxh + base1 + d0) = hi;
        *(uint32_t*)(g_ctxl + base1 + d0) = lo;
    }
}

// ---------------------------------------------------------------------------
extern "C" void kernel_launch(void* const* d_in, const int* in_sizes, int n_in,
                              void* d_out, int out_size)
{
    const float*         x     = (const float*)d_in[0];
    const unsigned char* mask  = (const unsigned char*)d_in[1];
    const float*         w_qkv = (const float*)d_in[2];
    const float*         w_out = (const float*)d_in[3];
    const float*         b_out = (const float*)d_in[4];
    float*               out   = (float*)d_out;

    // 0. pre-split x (linear) and weights (transposed to [N][K])
    xsplit_kernel<<<(Bq*Tq*Cq)/1024, 256>>>(x, (size_t)Bq*Tq*Cq);
    wsplit_kernel<1><<<dim3(3*Cq/32, Cq/32), 256>>>(w_qkv, 3*Cq);
    wsplit_kernel<2><<<dim3(Cq/32, Cq/32), 256>>>(w_out, Cq);

    // 1. lengths (QKV GEMM reads g_len for block skipping)
    len_kernel<<<Bq, 256>>>(mask);

    // 2. QKV projection -> Q/K/V hi/lo [BH,T,D]
    cudaFuncSetAttribute(mma_gemm_bf<0>,
                         cudaFuncAttributeMaxDynamicSharedMemorySize, GEMM_SMEM);
    mma_gemm_bf<0><<<dim3(3*Cq/128, Bq*Tq/128), 256, GEMM_SMEM>>>(
        nullptr, nullptr, Bq*Tq, 3*Cq, Cq);

    // 3. fused flash attention -> ctx hi/lo (2 CTAs/SM)
    cudaFuncSetAttribute(flash_kernel,
                         cudaFuncAttributeMaxDynamicSharedMemorySize, FLASH_SMEM);
    flash_kernel<<<dim3(Tq/128, BHq), 256, FLASH_SMEM>>>();

    // 4. output projection + bias
    cudaFuncSetAttribute(mma_gemm_bf<3>,
                         cudaFuncAttributeMaxDynamicSharedMemorySize, GEMM_SMEM);
    mma_gemm_bf<3><<<dim3(Cq/128, Bq*Tq/128), 256, GEMM_SMEM>>>(
        out, b_out, Bq*Tq, Cq, Cq);
}

// round 13
// speedup vs baseline: 4.6083x; 1.0741x over previous
#include <cuda_runtime.h>
#include <cuda_bf16.h>
#include <math_constants.h>
#include <stdint.h>

// Problem constants
#define Bq 4
#define Tq 2048
#define Cq 1024
#define Hq 16
#define Dq 64
#define BHq (Bq*Hq)

#define LOG2E 1.4426950408889634f

// ---------------------------------------------------------------------------
// Scratch (device globals, allocation-free). ONLY referenced from device code.
// Weights stored TRANSPOSED: [N][K] so GEMM B staging = vectorized row copies.
// ---------------------------------------------------------------------------
__device__ __nv_bfloat16 g_xh[(size_t)Bq*Tq*Cq];        // x split [M][K]
__device__ __nv_bfloat16 g_xl[(size_t)Bq*Tq*Cq];
__device__ __nv_bfloat16 g_wqh[(size_t)3*Cq*Cq];        // w_qkv^T split [3C][C]
__device__ __nv_bfloat16 g_wql[(size_t)3*Cq*Cq];
__device__ __nv_bfloat16 g_woh[(size_t)Cq*Cq];          // w_out^T split [C][C]
__device__ __nv_bfloat16 g_wol[(size_t)Cq*Cq];
__device__ __nv_bfloat16 g_qh[(size_t)BHq*Tq*Dq];       // Q/K/V split [BH][T][D]
__device__ __nv_bfloat16 g_ql[(size_t)BHq*Tq*Dq];
__device__ __nv_bfloat16 g_kh[(size_t)BHq*Tq*Dq];
__device__ __nv_bfloat16 g_kl[(size_t)BHq*Tq*Dq];
__device__ __nv_bfloat16 g_vh[(size_t)BHq*Tq*Dq];
__device__ __nv_bfloat16 g_vl[(size_t)BHq*Tq*Dq];
__device__ __nv_bfloat16 g_ctxh[(size_t)Bq*Tq*Cq];      // attention out split
__device__ __nv_bfloat16 g_ctxl[(size_t)Bq*Tq*Cq];
__device__ int g_len[Bq];

// ---------------------------------------------------------------------------
__device__ __forceinline__ void mma16816(float* d, const uint32_t* a, const uint32_t* b) {
    asm volatile(
        "mma.sync.aligned.m16n8k16.row.col.f32.bf16.bf16.f32 "
        "{%0,%1,%2,%3}, {%4,%5,%6,%7}, {%8,%9}, {%0,%1,%2,%3};\n"
        : "+f"(d[0]), "+f"(d[1]), "+f"(d[2]), "+f"(d[3])
        : "r"(a[0]), "r"(a[1]), "r"(a[2]), "r"(a[3]),
          "r"(b[0]), "r"(b[1]));
}

__device__ __forceinline__ void ldmx4(uint32_t& d0, uint32_t& d1, uint32_t& d2,
                                      uint32_t& d3, uint32_t addr) {
    asm volatile("ldmatrix.sync.aligned.m8n8.x4.shared.b16 {%0,%1,%2,%3}, [%4];"
        : "=r"(d0), "=r"(d1), "=r"(d2), "=r"(d3) : "r"(addr));
}
__device__ __forceinline__ void ldmx4t(uint32_t& d0, uint32_t& d1, uint32_t& d2,
                                       uint32_t& d3, uint32_t addr) {
    asm volatile("ldmatrix.sync.aligned.m8n8.x4.trans.shared.b16 {%0,%1,%2,%3}, [%4];"
        : "=r"(d0), "=r"(d1), "=r"(d2), "=r"(d3) : "r"(addr));
}

__device__ __forceinline__ void cp16(uint32_t dst, const void* src) {
    asm volatile("cp.async.cg.shared.global [%0], [%1], 16;\n" :: "r"(dst), "l"(src));
}
__device__ __forceinline__ void cp_commit() {
    asm volatile("cp.async.commit_group;\n");
}
template<int N>
__device__ __forceinline__ void cp_wait() {
    asm volatile("cp.async.wait_group %0;\n" :: "n"(N));
}

// pack two fp32 into bf16x2 hi and lo words (low half = first arg)
__device__ __forceinline__ void pack_split2(float a, float b, uint32_t& hi, uint32_t& lo) {
    __nv_bfloat16 ha = __float2bfloat16(a), hb = __float2bfloat16(b);
    __nv_bfloat16 la = __float2bfloat16(a - __bfloat162float(ha));
    __nv_bfloat16 lb = __float2bfloat16(b - __bfloat162float(hb));
    __nv_bfloat162 h2 = __halves2bfloat162(ha, hb);
    __nv_bfloat162 l2 = __halves2bfloat162(la, lb);
    hi = *reinterpret_cast<uint32_t*>(&h2);
    lo = *reinterpret_cast<uint32_t*>(&l2);
}

// ---------------------------------------------------------------------------
// x split (linear, no transpose): x -> g_xh/g_xl
// ---------------------------------------------------------------------------
__global__ void xsplit_kernel(const float* __restrict__ src, size_t n) {
    size_t i = ((size_t)blockIdx.x * blockDim.x + threadIdx.x) * 4;
    if (i >= n) return;
    float4 v = *(const float4*)(src + i);
    uint32_t h0, l0, h1, l1;
    pack_split2(v.x, v.y, h0, l0);
    pack_split2(v.z, v.w, h1, l1);
    *(uint32_t*)(g_xh + i)     = h0;
    *(uint32_t*)(g_xh + i + 2) = h1;
    *(uint32_t*)(g_xl + i)     = l0;
    *(uint32_t*)(g_xl + i + 2) = l1;
}

// ---------------------------------------------------------------------------
// Weight transpose + split: src [K=1024][N] fp32 -> dst [N][1024] bf16 hi/lo.
//   WHICH 1: w_qkv -> g_wqh/g_wql    WHICH 2: w_out -> g_woh/g_wol
// ---------------------------------------------------------------------------
template<int WHICH>
__global__ void wsplit_kernel(const float* __restrict__ src, int N) {
    __shared__ float t32[32][33];
    __nv_bfloat16* dh = (WHICH == 1) ? g_wqh : g_woh;
    __nv_bfloat16* dl = (WHICH == 1) ? g_wql : g_wol;
    const int k0 = blockIdx.y * 32, n0 = blockIdx.x * 32;
    const int tid = threadIdx.x;
    const int r0 = tid >> 5, c = tid & 31;
    #pragma unroll
    for (int rr = 0; rr < 4; rr++)
        t32[r0 + rr*8][c] = src[(size_t)(k0 + r0 + rr*8)*N + n0 + c];
    __syncthreads();
    const int n = tid >> 3, kq = (tid & 7) * 4;
    float v0 = t32[kq  ][n], v1 = t32[kq+1][n];
    float v2 = t32[kq+2][n], v3 = t32[kq+3][n];
    uint32_t h0, l0, h1, l1;
    pack_split2(v0, v1, h0, l0);
    pack_split2(v2, v3, h1, l1);
    size_t idx = (size_t)(n0 + n)*Cq + k0 + kq;
    *(uint2*)(dh + idx) = make_uint2(h0, h1);
    *(uint2*)(dl + idx) = make_uint2(l0, l1);
}

// ---------------------------------------------------------------------------
// Length kernel: robust to padding_mask being bool(u8), int32, or float32.
// ---------------------------------------------------------------------------
__global__ void len_kernel(const unsigned char* __restrict__ mraw) {
    __shared__ int code;
    __shared__ int partial[256];
    if (threadIdx.x == 0) {
        if (mraw[1] == 1) code = 0;
        else if (((const int*)mraw)[0] == 1) code = 1;
        else code = 2;
    }
    __syncthreads();
    const int c = code;
    const int b = blockIdx.x;
    int cnt = 0;
    for (int t = threadIdx.x; t < Tq; t += blockDim.x) {
        int idx = b * Tq + t;
        bool m;
        if (c == 0)      m = mraw[idx] != 0;
        else if (c == 1) m = ((const int*)mraw)[idx] != 0;
        else             m = ((const float*)mraw)[idx] != 0.0f;
        cnt += m ? 1 : 0;
    }
    partial[threadIdx.x] = cnt;
    __syncthreads();
    for (int s = 128; s > 0; s >>= 1) {
        if (threadIdx.x < s) partial[threadIdx.x] += partial[threadIdx.x + s];
        __syncthreads();
    }
    if (threadIdx.x == 0) g_len[b] = partial[0];
}

// ---------------------------------------------------------------------------
// Split-bf16 tensor-core GEMM, cp.async 2-stage pipeline, ldmatrix operands,
// 2 CTAs/SM (82KB smem + forced 128-reg cap) for latency hiding + tail halving.
//   MODE 0: qkv = x @ w_qkv, epilogue -> g_{q,k,v}{h,l}; skips fully-masked
//           K/V blocks.
//   MODE 3: out = ctx @ w_out + b_out (fp32 out to Cg)
// Dyn smem: 2 stages x (Ah,Al,Bh,Bl)[128][40] = 81920 B.
// ---------------------------------------------------------------------------
#define GP 40                        // smem pitch (bf16)
#define G_ARR (128*GP)               // 5120 elems per array
#define G_STAGE (4*G_ARR)            // 20480 elems per stage
#define GEMM_SMEM (2*G_STAGE*2)      // 81920 bytes

template<int MODE>
__global__ void __launch_bounds__(256, 2)
mma_gemm_bf(float* __restrict__ Cg, const float* __restrict__ bias,
            int M, int N, int K)
{
    extern __shared__ __nv_bfloat16 smg[];

    const int bm = blockIdx.y * 128;
    const int bn = blockIdx.x * 128;

    if (MODE == 0) {
        int part = bn >> 10;
        if (part >= 1 && (bm & (Tq - 1)) >= g_len[bm >> 11]) return;
    }

    const __nv_bfloat16* Agh = (MODE == 0) ? g_xh : g_ctxh;
    const __nv_bfloat16* Agl = (MODE == 0) ? g_xl : g_ctxl;
    const __nv_bfloat16* Bgh = (MODE == 0) ? g_wqh : g_woh;
    const __nv_bfloat16* Bgl = (MODE == 0) ? g_wql : g_wol;

    const int tid  = threadIdx.x;
    const int lane = tid & 31;
    const int warp = tid >> 5;
    const int wm   = warp >> 2;
    const int wn   = warp & 3;
    const int r4   = lane >> 2;
    const int c2   = (lane & 3) * 2;

    const uint32_t sb = (uint32_t)__cvta_generic_to_shared(smg);

    const uint32_t la = ((lane & 15) * GP + (lane >> 4) * 8) * 2;
    const uint32_t lb = (((lane & 7) + ((lane >> 4) << 3)) * GP + ((lane >> 3) & 1) * 8) * 2;

    auto issue = [&](int st, int k0) {
        #pragma unroll
        for (int i = tid; i < 2048; i += 256) {
            int arr = i >> 9, j = i & 511, r = j >> 2, c = j & 3;
            const __nv_bfloat16* src =
                (arr == 0) ? Agh + (size_t)(bm + r)*K + k0 + c*8 :
                (arr == 1) ? Agl + (size_t)(bm + r)*K + k0 + c*8 :
                (arr == 2) ? Bgh + (size_t)(bn + r)*K + k0 + c*8 :
                             Bgl + (size_t)(bn + r)*K + k0 + c*8;
            uint32_t dst = sb + (st*G_STAGE + arr*G_ARR + r*GP + c*8)*2;
            cp16(dst, src);
        }
        cp_commit();
    };

    float acc[4][4][4];
    #pragma unroll
    for (int i = 0; i < 4; i++)
        #pragma unroll
        for (int j = 0; j < 4; j++)
            #pragma unroll
            for (int r = 0; r < 4; r++) acc[i][j][r] = 0.0f;

    const int NS = K / 32;
    issue(0, 0);

    for (int s = 0; s < NS; s++) {
        if (s + 1 < NS) { issue((s + 1) & 1, (s + 1) * 32); cp_wait<1>(); }
        else            { cp_wait<0>(); }
        __syncthreads();

        const uint32_t stg = sb + (s & 1)*G_STAGE*2;
        const uint32_t Ahb = stg;
        const uint32_t Alb = stg + G_ARR*2;
        const uint32_t Bhb = stg + 2*G_ARR*2;
        const uint32_t Blb = stg + 3*G_ARR*2;

        #pragma unroll
        for (int ks = 0; ks < 2; ks++) {
            uint32_t ah[4][4], al[4][4], bh[4][2], bl[4][2];
            #pragma unroll
            for (int mt = 0; mt < 4; mt++) {
                const uint32_t off = ((wm*64 + mt*16)*GP + ks*16)*2;
                ldmx4(ah[mt][0], ah[mt][1], ah[mt][2], ah[mt][3], Ahb + la + off);
                ldmx4(al[mt][0], al[mt][1], al[mt][2], al[mt][3], Alb + la + off);
            }
            #pragma unroll
            for (int np = 0; np < 2; np++) {
                const uint32_t off = ((wn*32 + np*16)*GP + ks*16)*2;
                uint32_t d0, d1, d2, d3;
                ldmx4(d0, d1, d2, d3, Bhb + lb + off);
                bh[2*np][0] = d0; bh[2*np][1] = d1;
                bh[2*np+1][0] = d2; bh[2*np+1][1] = d3;
                ldmx4(d0, d1, d2, d3, Blb + lb + off);
                bl[2*np][0] = d0; bl[2*np][1] = d1;
                bl[2*np+1][0] = d2; bl[2*np+1][1] = d3;
            }
            #pragma unroll
            for (int mt = 0; mt < 4; mt++)
                #pragma unroll
                for (int nt = 0; nt < 4; nt++) {
                    mma16816(acc[mt][nt], ah[mt], bh[nt]);
                    mma16816(acc[mt][nt], ah[mt], bl[nt]);
                    mma16816(acc[mt][nt], al[mt], bh[nt]);
                }
        }
        __syncthreads();
    }

    #pragma unroll
    for (int mt = 0; mt < 4; mt++) {
        #pragma unroll
        for (int nt = 0; nt < 4; nt++) {
            int m0 = bm + wm*64 + mt*16 + r4;
            int n0 = bn + wn*32 + nt*8 + c2;
            const float* cr = acc[mt][nt];
            #pragma unroll
            for (int half = 0; half < 2; half++) {
                int m = m0 + half*8;
                float v0 = cr[half*2], v1 = cr[half*2+1];
                if (MODE == 0) {
                    int bb = m / Tq, t = m % Tq;
                    int part = n0 >> 10, hh = (n0 & 1023) >> 6, d = n0 & 63;
                    size_t idx = ((size_t)(bb*Hq + hh)*Tq + t)*Dq + d;
                    __nv_bfloat16* dsth = (part == 0) ? g_qh : (part == 1) ? g_kh : g_vh;
                    __nv_bfloat16* dstl = (part == 0) ? g_ql : (part == 1) ? g_kl : g_vl;
                    uint32_t hi, lo;
                    pack_split2(v0, v1, hi, lo);
                    *(uint32_t*)(dsth + idx) = hi;
                    *(uint32_t*)(dstl + idx) = lo;
                } else {
                    *(float2*)&Cg[(size_t)m*N + n0] =
                        make_float2(v0 + bias[n0], v1 + bias[n0+1]);
                }
            }
        }
    }
}

// ---------------------------------------------------------------------------
// Fused flash attention (unchanged from R12: 64-kv tiles, 2 CTAs/SM).
// Dyn smem: 2 stages x (Kh,Kl,Vh,Vl)[64][72] = 73728 B.
// ---------------------------------------------------------------------------
#define FP 72                         // smem pitch (bf16)
#define F_ARR (64*FP)                 // 4608 elems
#define F_STAGE (4*F_ARR)             // 18432 elems
#define FLASH_SMEM (2*F_STAGE*2)      // 73728 bytes

__global__ void __launch_bounds__(256, 2) flash_kernel() {
    extern __shared__ __nv_bfloat16 smf[];

    const int tid  = threadIdx.x;
    const int lane = tid & 31;
    const int warp = tid >> 5;
    const int r4   = lane >> 2;
    const int c2   = (lane & 3) * 2;
    const int bh   = blockIdx.y;
    const int b    = bh >> 4;
    const int qrow = blockIdx.x * 128 + warp * 16;
    const int len  = g_len[b];
    const int ntiles = (len + 63) >> 6;

    const size_t base = (size_t)bh * Tq * Dq;
    const uint32_t sb = (uint32_t)__cvta_generic_to_shared(smf);

    // per-thread ldmatrix byte offsets
    const uint32_t lk = ((((lane & 7) + ((lane >> 4) << 3)) * FP + ((lane >> 3) & 1) * 8)) * 2;
    const uint32_t lv = (((lane & 15) * FP + ((lane >> 4) << 3))) * 2;

    auto issue = [&](int s, int kv0) {
        #pragma unroll
        for (int i = tid; i < 2048; i += 256) {
            int arr = i >> 9, j = i & 511, r = j >> 3, c = j & 7;
            const __nv_bfloat16* src =
                (arr == 0) ? g_kh + base + (size_t)(kv0 + r)*Dq + c*8 :
                (arr == 1) ? g_kl + base + (size_t)(kv0 + r)*Dq + c*8 :
                (arr == 2) ? g_vh + base + (size_t)(kv0 + r)*Dq + c*8 :
                             g_vl + base + (size_t)(kv0 + r)*Dq + c*8;
            uint32_t dst = sb + (s*F_STAGE + arr*F_ARR + r*FP + c*8)*2;
            cp16(dst, src);
        }
        cp_commit();
    };

    // Q fragments, persistent in registers (A operand, K-dim = D = 64)
    uint32_t qh[4][4], ql[4][4];
    #pragma unroll
    for (int ks = 0; ks < 4; ks++) {
        int kc = ks*16 + c2;
        qh[ks][0] = *(const uint32_t*)&g_qh[base + (size_t)(qrow + r4    )*Dq + kc];
        qh[ks][1] = *(const uint32_t*)&g_qh[base + (size_t)(qrow + r4 + 8)*Dq + kc];
        qh[ks][2] = *(const uint32_t*)&g_qh[base + (size_t)(qrow + r4    )*Dq + kc + 8];
        qh[ks][3] = *(const uint32_t*)&g_qh[base + (size_t)(qrow + r4 + 8)*Dq + kc + 8];
        ql[ks][0] = *(const uint32_t*)&g_ql[base + (size_t)(qrow + r4    )*Dq + kc];
        ql[ks][1] = *(const uint32_t*)&g_ql[base + (size_t)(qrow + r4 + 8)*Dq + kc];
        ql[ks][2] = *(const uint32_t*)&g_ql[base + (size_t)(qrow + r4    )*Dq + kc + 8];
        ql[ks][3] = *(const uint32_t*)&g_ql[base + (size_t)(qrow + r4 + 8)*Dq + kc + 8];
    }

    float Oacc[8][4];
    #pragma unroll
    for (int i = 0; i < 8; i++)
        #pragma unroll
        for (int j = 0; j < 4; j++) Oacc[i][j] = 0.0f;
    float m_run[2] = {-CUDART_INF_F, -CUDART_INF_F};
    float l_run[2] = {0.0f, 0.0f};

    issue(0, 0);

    for (int kt = 0; kt < ntiles; kt++) {
        const int kv0 = kt * 64;
        if (kt + 1 < ntiles) { issue((kt + 1) & 1, kv0 + 64); cp_wait<1>(); }
        else                 { cp_wait<0>(); }
        __syncthreads();

        const uint32_t stg = sb + (kt & 1)*F_STAGE*2;
        const uint32_t Khb = stg;
        const uint32_t Klb = stg + F_ARR*2;
        const uint32_t Vhb = stg + 2*F_ARR*2;
        const uint32_t Vlb = stg + 3*F_ARR*2;

        // ---- S = Q K^T  (64 kv rows -> S[8][4]) ----
        float S[8][4];
        #pragma unroll
        for (int nt = 0; nt < 8; nt++)
            #pragma unroll
            for (int j = 0; j < 4; j++) S[nt][j] = 0.0f;
        #pragma unroll
        for (int ks = 0; ks < 4; ks++) {
            #pragma unroll
            for (int np = 0; np < 4; np++) {          // nt pairs
                const uint32_t off = (np*16*FP + ks*16)*2;
                uint32_t h0,h1,h2,h3, l0,l1,l2,l3;
                ldmx4(h0, h1, h2, h3, Khb + lk + off);
                ldmx4(l0, l1, l2, l3, Klb + lk + off);
                uint32_t bh0[2] = {h0, h1}, bh1[2] = {h2, h3};
                uint32_t bl0[2] = {l0, l1}, bl1[2] = {l2, l3};
                mma16816(S[2*np  ], qh[ks], bh0);
                mma16816(S[2*np  ], qh[ks], bl0);
                mma16816(S[2*np  ], ql[ks], bh0);
                mma16816(S[2*np+1], qh[ks], bh1);
                mma16816(S[2*np+1], qh[ks], bl1);
                mma16816(S[2*np+1], ql[ks], bh1);
            }
        }

        // ---- scale + mask + row max ----
        float rmax[2] = {-CUDART_INF_F, -CUDART_INF_F};
        #pragma unroll
        for (int nt = 0; nt < 8; nt++) {
            #pragma unroll
            for (int j = 0; j < 4; j++) {
                int kv = kv0 + nt*8 + c2 + (j & 1);
                float s = S[nt][j] * 0.125f;
                s = (kv < len) ? s : -CUDART_INF_F;
                S[nt][j] = s;
                rmax[j >> 1] = fmaxf(rmax[j >> 1], s);
            }
        }
        #pragma unroll
        for (int j = 0; j < 2; j++) {
            rmax[j] = fmaxf(rmax[j], __shfl_xor_sync(0xffffffffu, rmax[j], 1));
            rmax[j] = fmaxf(rmax[j], __shfl_xor_sync(0xffffffffu, rmax[j], 2));
        }

        float m_new[2], alpha[2];
        #pragma unroll
        for (int j = 0; j < 2; j++) {
            m_new[j] = fmaxf(m_run[j], rmax[j]);
            alpha[j] = exp2f((m_run[j] - m_new[j]) * LOG2E);
            m_run[j] = m_new[j];
        }

        // ---- exponentiate + row sum ----
        float rsum[2] = {0.0f, 0.0f};
        #pragma unroll
        for (int nt = 0; nt < 8; nt++) {
            #pragma unroll
            for (int j = 0; j < 4; j++) {
                float p = exp2f((S[nt][j] - m_new[j >> 1]) * LOG2E);
                S[nt][j] = p;
                rsum[j >> 1] += p;
            }
        }
        #pragma unroll
        for (int j = 0; j < 2; j++) {
            rsum[j] += __shfl_xor_sync(0xffffffffu, rsum[j], 1);
            rsum[j] += __shfl_xor_sync(0xffffffffu, rsum[j], 2);
            l_run[j] = l_run[j] * alpha[j] + rsum[j];
        }
        #pragma unroll
        for (int i = 0; i < 8; i++) {
            Oacc[i][0] *= alpha[0]; Oacc[i][1] *= alpha[0];
            Oacc[i][2] *= alpha[1]; Oacc[i][3] *= alpha[1];
        }

        // ---- O += P V : P frags from S in registers, V frags via ldmatrix.trans
        #pragma unroll
        for (int kk = 0; kk < 4; kk++) {              // 4 k16 steps (64 kv)
            uint32_t pah[4], pal[4];
            pack_split2(S[2*kk  ][0], S[2*kk  ][1], pah[0], pal[0]);
            pack_split2(S[2*kk  ][2], S[2*kk  ][3], pah[1], pal[1]);
            pack_split2(S[2*kk+1][0], S[2*kk+1][1], pah[2], pal[2]);
            pack_split2(S[2*kk+1][2], S[2*kk+1][3], pah[3], pal[3]);
            #pragma unroll
            for (int dp = 0; dp < 4; dp++) {          // d-block pairs
                const uint32_t off = (kk*16*FP + dp*16)*2;
                uint32_t h0,h1,h2,h3, l0,l1,l2,l3;
                ldmx4t(h0, h1, h2, h3, Vhb + lv + off);
                ldmx4t(l0, l1, l2, l3, Vlb + lv + off);
                uint32_t bh0[2] = {h0, h1}, bh1[2] = {h2, h3};
                uint32_t bl0[2] = {l0, l1}, bl1[2] = {l2, l3};
                mma16816(Oacc[2*dp  ], pah, bh0);
                mma16816(Oacc[2*dp  ], pah, bl0);
                mma16816(Oacc[2*dp  ], pal, bh0);
                mma16816(Oacc[2*dp+1], pah, bh1);
                mma16816(Oacc[2*dp+1], pah, bl1);
                mma16816(Oacc[2*dp+1], pal, bh1);
            }
        }
        __syncthreads();
    }

    // ---- finalize: O /= l, write ctx hi/lo bf16 [B,T,C] ----
    const float inv0 = 1.0f / l_run[0];
    const float inv1 = 1.0f / l_run[1];
    const int hh = bh & 15;
    const size_t base0 = ((size_t)(b*Tq + qrow + r4    ))*Cq + hh*Dq;
    const size_t base1 = ((size_t)(b*Tq + qrow + r4 + 8))*Cq + hh*Dq;
    #pragma unroll
    for (int ntd = 0; ntd < 8; ntd++) {
        int d0 = ntd*8 + c2;
        uint32_t hi, lo;
        pack_split2(Oacc[ntd][0]*inv0, Oacc[ntd][1]*inv0, hi, lo);
        *(uint32_t*)(g_ctxh + base0 + d0) = hi;
        *(uint32_t*)(g_ctxl + base0 + d0) = lo;
        pack_split2(Oacc[ntd][2]*inv1, Oacc[ntd][3]*inv1, hi, lo);
        *(uint32_t*)(g_ctxh + base1 + d0) = hi;
        *(uint32_t*)(g_ctxl + base1 + d0) = lo;
    }
}

// ---------------------------------------------------------------------------
extern "C" void kernel_launch(void* const* d_in, const int* in_sizes, int n_in,
                              void* d_out, int out_size)
{
    const float*         x     = (const float*)d_in[0];
    const unsigned char* mask  = (const unsigned char*)d_in[1];
    const float*         w_qkv = (const float*)d_in[2];
    const float*         w_out = (const float*)d_in[3];
    const float*         b_out = (const float*)d_in[4];
    float*               out   = (float*)d_out;

    // Launch order puts gemm0 at the ncu capture slot (previously len_kernel).
    // 0. x split + w_qkv split (both needed by gemm0)
    xsplit_kernel<<<(Bq*Tq*Cq)/1024, 256>>>(x, (size_t)Bq*Tq*Cq);
    wsplit_kernel<1><<<dim3(3*Cq/32, Cq/32), 256>>>(w_qkv, 3*Cq);

    // 1. lengths (gemm0 reads g_len for block skipping)
    len_kernel<<<Bq, 256>>>(mask);

    // 2. QKV projection -> Q/K/V hi/lo [BH,T,D]
    cudaFuncSetAttribute(mma_gemm_bf<0>,
                         cudaFuncAttributeMaxDynamicSharedMemorySize, GEMM_SMEM);
    mma_gemm_bf<0><<<dim3(3*Cq/128, Bq*Tq/128), 256, GEMM_SMEM>>>(
        nullptr, nullptr, Bq*Tq, 3*Cq, Cq);

    // 3. fused flash attention -> ctx hi/lo (2 CTAs/SM)
    cudaFuncSetAttribute(flash_kernel,
                         cudaFuncAttributeMaxDynamicSharedMemorySize, FLASH_SMEM);
    flash_kernel<<<dim3(Tq/128, BHq), 256, FLASH_SMEM>>>();

    // 4. w_out split (only needed by gemm3; moved late to free the capture slot)
    wsplit_kernel<2><<<dim3(Cq/32, Cq/32), 256>>>(w_out, Cq);

    // 5. output projection + bias
    cudaFuncSetAttribute(mma_gemm_bf<3>,
                         cudaFuncAttributeMaxDynamicSharedMemorySize, GEMM_SMEM);
    mma_gemm_bf<3><<<dim3(Cq/128, Bq*Tq/128), 256, GEMM_SMEM>>>(
        out, b_out, Bq*Tq, Cq, Cq);
}

// round 14
// speedup vs baseline: 4.6633x; 1.0119x over previous
#include <cuda_runtime.h>
#include <cuda_bf16.h>
#include <math_constants.h>
#include <stdint.h>

// Problem constants
#define Bq 4
#define Tq 2048
#define Cq 1024
#define Hq 16
#define Dq 64
#define BHq (Bq*Hq)

#define LOG2E 1.4426950408889634f

// ---------------------------------------------------------------------------
// Scratch (device globals, allocation-free). ONLY referenced from device code.
// Weights stored TRANSPOSED: [N][K] so GEMM B staging = vectorized row copies.
// ---------------------------------------------------------------------------
__device__ __nv_bfloat16 g_xh[(size_t)Bq*Tq*Cq];        // x split [M][K]
__device__ __nv_bfloat16 g_xl[(size_t)Bq*Tq*Cq];
__device__ __nv_bfloat16 g_wqh[(size_t)3*Cq*Cq];        // w_qkv^T split [3C][C]
__device__ __nv_bfloat16 g_wql[(size_t)3*Cq*Cq];
__device__ __nv_bfloat16 g_woh[(size_t)Cq*Cq];          // w_out^T split [C][C]
__device__ __nv_bfloat16 g_wol[(size_t)Cq*Cq];
__device__ __nv_bfloat16 g_qh[(size_t)BHq*Tq*Dq];       // Q/K/V split [BH][T][D]
__device__ __nv_bfloat16 g_ql[(size_t)BHq*Tq*Dq];
__device__ __nv_bfloat16 g_kh[(size_t)BHq*Tq*Dq];
__device__ __nv_bfloat16 g_kl[(size_t)BHq*Tq*Dq];
__device__ __nv_bfloat16 g_vh[(size_t)BHq*Tq*Dq];
__device__ __nv_bfloat16 g_vl[(size_t)BHq*Tq*Dq];
__device__ __nv_bfloat16 g_ctxh[(size_t)Bq*Tq*Cq];      // attention out split
__device__ __nv_bfloat16 g_ctxl[(size_t)Bq*Tq*Cq];
__device__ int g_len[Bq];

// ---------------------------------------------------------------------------
__device__ __forceinline__ void mma16816(float* d, const uint32_t* a, const uint32_t* b) {
    asm volatile(
        "mma.sync.aligned.m16n8k16.row.col.f32.bf16.bf16.f32 "
        "{%0,%1,%2,%3}, {%4,%5,%6,%7}, {%8,%9}, {%0,%1,%2,%3};\n"
        : "+f"(d[0]), "+f"(d[1]), "+f"(d[2]), "+f"(d[3])
        : "r"(a[0]), "r"(a[1]), "r"(a[2]), "r"(a[3]),
          "r"(b[0]), "r"(b[1]));
}

__device__ __forceinline__ void ldmx4(uint32_t& d0, uint32_t& d1, uint32_t& d2,
                                      uint32_t& d3, uint32_t addr) {
    asm volatile("ldmatrix.sync.aligned.m8n8.x4.shared.b16 {%0,%1,%2,%3}, [%4];"
        : "=r"(d0), "=r"(d1), "=r"(d2), "=r"(d3) : "r"(addr));
}
__device__ __forceinline__ void ldmx4t(uint32_t& d0, uint32_t& d1, uint32_t& d2,
                                       uint32_t& d3, uint32_t addr) {
    asm volatile("ldmatrix.sync.aligned.m8n8.x4.trans.shared.b16 {%0,%1,%2,%3}, [%4];"
        : "=r"(d0), "=r"(d1), "=r"(d2), "=r"(d3) : "r"(addr));
}

__device__ __forceinline__ void cp16(uint32_t dst, const void* src) {
    asm volatile("cp.async.cg.shared.global [%0], [%1], 16;\n" :: "r"(dst), "l"(src));
}
__device__ __forceinline__ void cp_commit() {
    asm volatile("cp.async.commit_group;\n");
}
template<int N>
__device__ __forceinline__ void cp_wait() {
    asm volatile("cp.async.wait_group %0;\n" :: "n"(N));
}

// pack two fp32 into bf16x2 hi and lo words (low half = first arg)
__device__ __forceinline__ void pack_split2(float a, float b, uint32_t& hi, uint32_t& lo) {
    __nv_bfloat16 ha = __float2bfloat16(a), hb = __float2bfloat16(b);
    __nv_bfloat16 la = __float2bfloat16(a - __bfloat162float(ha));
    __nv_bfloat16 lb = __float2bfloat16(b - __bfloat162float(hb));
    __nv_bfloat162 h2 = __halves2bfloat162(ha, hb);
    __nv_bfloat162 l2 = __halves2bfloat162(la, lb);
    hi = *reinterpret_cast<uint32_t*>(&h2);
    lo = *reinterpret_cast<uint32_t*>(&l2);
}

// ---------------------------------------------------------------------------
// x split (linear, no transpose): x -> g_xh/g_xl
// ---------------------------------------------------------------------------
__global__ void xsplit_kernel(const float* __restrict__ src, size_t n) {
    size_t i = ((size_t)blockIdx.x * blockDim.x + threadIdx.x) * 4;
    if (i >= n) return;
    float4 v = *(const float4*)(src + i);
    uint32_t h0, l0, h1, l1;
    pack_split2(v.x, v.y, h0, l0);
    pack_split2(v.z, v.w, h1, l1);
    *(uint32_t*)(g_xh + i)     = h0;
    *(uint32_t*)(g_xh + i + 2) = h1;
    *(uint32_t*)(g_xl + i)     = l0;
    *(uint32_t*)(g_xl + i + 2) = l1;
}

// ---------------------------------------------------------------------------
// Weight transpose + split: src [K=1024][N] fp32 -> dst [N][1024] bf16 hi/lo.
//   WHICH 1: w_qkv -> g_wqh/g_wql    WHICH 2: w_out -> g_woh/g_wol
// ---------------------------------------------------------------------------
template<int WHICH>
__global__ void wsplit_kernel(const float* __restrict__ src, int N) {
    __shared__ float t32[32][33];
    __nv_bfloat16* dh = (WHICH == 1) ? g_wqh : g_woh;
    __nv_bfloat16* dl = (WHICH == 1) ? g_wql : g_wol;
    const int k0 = blockIdx.y * 32, n0 = blockIdx.x * 32;
    const int tid = threadIdx.x;
    const int r0 = tid >> 5, c = tid & 31;
    #pragma unroll
    for (int rr = 0; rr < 4; rr++)
        t32[r0 + rr*8][c] = src[(size_t)(k0 + r0 + rr*8)*N + n0 + c];
    __syncthreads();
    const int n = tid >> 3, kq = (tid & 7) * 4;
    float v0 = t32[kq  ][n], v1 = t32[kq+1][n];
    float v2 = t32[kq+2][n], v3 = t32[kq+3][n];
    uint32_t h0, l0, h1, l1;
    pack_split2(v0, v1, h0, l0);
    pack_split2(v2, v3, h1, l1);
    size_t idx = (size_t)(n0 + n)*Cq + k0 + kq;
    *(uint2*)(dh + idx) = make_uint2(h0, h1);
    *(uint2*)(dl + idx) = make_uint2(l0, l1);
}

// ---------------------------------------------------------------------------
// Length kernel: robust to padding_mask being bool(u8), int32, or float32.
// ---------------------------------------------------------------------------
__global__ void len_kernel(const unsigned char* __restrict__ mraw) {
    __shared__ int code;
    __shared__ int partial[256];
    if (threadIdx.x == 0) {
        if (mraw[1] == 1) code = 0;
        else if (((const int*)mraw)[0] == 1) code = 1;
        else code = 2;
    }
    __syncthreads();
    const int c = code;
    const int b = blockIdx.x;
    int cnt = 0;
    for (int t = threadIdx.x; t < Tq; t += blockDim.x) {
        int idx = b * Tq + t;
        bool m;
        if (c == 0)      m = mraw[idx] != 0;
        else if (c == 1) m = ((const int*)mraw)[idx] != 0;
        else             m = ((const float*)mraw)[idx] != 0.0f;
        cnt += m ? 1 : 0;
    }
    partial[threadIdx.x] = cnt;
    __syncthreads();
    for (int s = 128; s > 0; s >>= 1) {
        if (threadIdx.x < s) partial[threadIdx.x] += partial[threadIdx.x + s];
        __syncthreads();
    }
    if (threadIdx.x == 0) g_len[b] = partial[0];
}

// ---------------------------------------------------------------------------
// Split-bf16 tensor-core GEMM, cp.async 2-stage pipeline, ldmatrix operands,
// 2 CTAs/SM. PASS-MAJOR MMA ordering: all 16 tiles get pass hh, then hl,
// then lh — RAW distance per accumulator 1 -> 16 (hides HMMA latency);
// per-accumulator accumulation order unchanged -> bit-identical numerics.
//   MODE 0: qkv = x @ w_qkv -> g_{q,k,v}{h,l}; skips fully-masked K/V blocks.
//   MODE 3: out = ctx @ w_out + b_out (fp32 out to Cg)
// Dyn smem: 2 stages x (Ah,Al,Bh,Bl)[128][40] = 81920 B.
// ---------------------------------------------------------------------------
#define GP 40                        // smem pitch (bf16)
#define G_ARR (128*GP)               // 5120 elems per array
#define G_STAGE (4*G_ARR)            // 20480 elems per stage
#define GEMM_SMEM (2*G_STAGE*2)      // 81920 bytes

template<int MODE>
__global__ void __launch_bounds__(256, 2)
mma_gemm_bf(float* __restrict__ Cg, const float* __restrict__ bias,
            int M, int N, int K)
{
    extern __shared__ __nv_bfloat16 smg[];

    const int bm = blockIdx.y * 128;
    const int bn = blockIdx.x * 128;

    if (MODE == 0) {
        int part = bn >> 10;
        if (part >= 1 && (bm & (Tq - 1)) >= g_len[bm >> 11]) return;
    }

    const __nv_bfloat16* Agh = (MODE == 0) ? g_xh : g_ctxh;
    const __nv_bfloat16* Agl = (MODE == 0) ? g_xl : g_ctxl;
    const __nv_bfloat16* Bgh = (MODE == 0) ? g_wqh : g_woh;
    const __nv_bfloat16* Bgl = (MODE == 0) ? g_wql : g_wol;

    const int tid  = threadIdx.x;
    const int lane = tid & 31;
    const int warp = tid >> 5;
    const int wm   = warp >> 2;
    const int wn   = warp & 3;
    const int r4   = lane >> 2;
    const int c2   = (lane & 3) * 2;

    const uint32_t sb = (uint32_t)__cvta_generic_to_shared(smg);

    const uint32_t la = ((lane & 15) * GP + (lane >> 4) * 8) * 2;
    const uint32_t lb = (((lane & 7) + ((lane >> 4) << 3)) * GP + ((lane >> 3) & 1) * 8) * 2;

    auto issue = [&](int st, int k0) {
        #pragma unroll
        for (int i = tid; i < 2048; i += 256) {
            int arr = i >> 9, j = i & 511, r = j >> 2, c = j & 3;
            const __nv_bfloat16* src =
                (arr == 0) ? Agh + (size_t)(bm + r)*K + k0 + c*8 :
                (arr == 1) ? Agl + (size_t)(bm + r)*K + k0 + c*8 :
                (arr == 2) ? Bgh + (size_t)(bn + r)*K + k0 + c*8 :
                             Bgl + (size_t)(bn + r)*K + k0 + c*8;
            uint32_t dst = sb + (st*G_STAGE + arr*G_ARR + r*GP + c*8)*2;
            cp16(dst, src);
        }
        cp_commit();
    };

    float acc[4][4][4];
    #pragma unroll
    for (int i = 0; i < 4; i++)
        #pragma unroll
        for (int j = 0; j < 4; j++)
            #pragma unroll
            for (int r = 0; r < 4; r++) acc[i][j][r] = 0.0f;

    const int NS = K / 32;
    issue(0, 0);

    for (int s = 0; s < NS; s++) {
        if (s + 1 < NS) { issue((s + 1) & 1, (s + 1) * 32); cp_wait<1>(); }
        else            { cp_wait<0>(); }
        __syncthreads();

        const uint32_t stg = sb + (s & 1)*G_STAGE*2;
        const uint32_t Ahb = stg;
        const uint32_t Alb = stg + G_ARR*2;
        const uint32_t Bhb = stg + 2*G_ARR*2;
        const uint32_t Blb = stg + 3*G_ARR*2;

        #pragma unroll
        for (int ks = 0; ks < 2; ks++) {
            uint32_t ah[4][4], al[4][4], bh[4][2], bl[4][2];
            #pragma unroll
            for (int mt = 0; mt < 4; mt++) {
                const uint32_t off = ((wm*64 + mt*16)*GP + ks*16)*2;
                ldmx4(ah[mt][0], ah[mt][1], ah[mt][2], ah[mt][3], Ahb + la + off);
                ldmx4(al[mt][0], al[mt][1], al[mt][2], al[mt][3], Alb + la + off);
            }
            #pragma unroll
            for (int np = 0; np < 2; np++) {
                const uint32_t off = ((wn*32 + np*16)*GP + ks*16)*2;
                uint32_t d0, d1, d2, d3;
                ldmx4(d0, d1, d2, d3, Bhb + lb + off);
                bh[2*np][0] = d0; bh[2*np][1] = d1;
                bh[2*np+1][0] = d2; bh[2*np+1][1] = d3;
                ldmx4(d0, d1, d2, d3, Blb + lb + off);
                bl[2*np][0] = d0; bl[2*np][1] = d1;
                bl[2*np+1][0] = d2; bl[2*np+1][1] = d3;
            }
            // pass-major: RAW distance per acc tile = 16 MMAs
            #pragma unroll
            for (int mt = 0; mt < 4; mt++)
                #pragma unroll
                for (int nt = 0; nt < 4; nt++)
                    mma16816(acc[mt][nt], ah[mt], bh[nt]);
            #pragma unroll
            for (int mt = 0; mt < 4; mt++)
                #pragma unroll
                for (int nt = 0; nt < 4; nt++)
                    mma16816(acc[mt][nt], ah[mt], bl[nt]);
            #pragma unroll
            for (int mt = 0; mt < 4; mt++)
                #pragma unroll
                for (int nt = 0; nt < 4; nt++)
                    mma16816(acc[mt][nt], al[mt], bh[nt]);
        }
        __syncthreads();
    }

    #pragma unroll
    for (int mt = 0; mt < 4; mt++) {
        #pragma unroll
        for (int nt = 0; nt < 4; nt++) {
            int m0 = bm + wm*64 + mt*16 + r4;
            int n0 = bn + wn*32 + nt*8 + c2;
            const float* cr = acc[mt][nt];
            #pragma unroll
            for (int half = 0; half < 2; half++) {
                int m = m0 + half*8;
                float v0 = cr[half*2], v1 = cr[half*2+1];
                if (MODE == 0) {
                    int bb = m / Tq, t = m % Tq;
                    int part = n0 >> 10, hh = (n0 & 1023) >> 6, d = n0 & 63;
                    size_t idx = ((size_t)(bb*Hq + hh)*Tq + t)*Dq + d;
                    __nv_bfloat16* dsth = (part == 0) ? g_qh : (part == 1) ? g_kh : g_vh;
                    __nv_bfloat16* dstl = (part == 0) ? g_ql : (part == 1) ? g_kl : g_vl;
                    uint32_t hi, lo;
                    pack_split2(v0, v1, hi, lo);
                    *(uint32_t*)(dsth + idx) = hi;
                    *(uint32_t*)(dstl + idx) = lo;
                } else {
                    *(float2*)&Cg[(size_t)m*N + n0] =
                        make_float2(v0 + bias[n0], v1 + bias[n0+1]);
                }
            }
        }
    }
}

// ---------------------------------------------------------------------------
// Fused flash attention (64-kv tiles, 2 CTAs/SM). MMA pairs interleaved
// pass-major (distance 1 -> 2) — per-acc order unchanged, bit-identical.
// Dyn smem: 2 stages x (Kh,Kl,Vh,Vl)[64][72] = 73728 B.
// ---------------------------------------------------------------------------
#define FP 72                         // smem pitch (bf16)
#define F_ARR (64*FP)                 // 4608 elems
#define F_STAGE (4*F_ARR)             // 18432 elems
#define FLASH_SMEM (2*F_STAGE*2)      // 73728 bytes

__global__ void __launch_bounds__(256, 2) flash_kernel() {
    extern __shared__ __nv_bfloat16 smf[];

    const int tid  = threadIdx.x;
    const int lane = tid & 31;
    const int warp = tid >> 5;
    const int r4   = lane >> 2;
    const int c2   = (lane & 3) * 2;
    const int bh   = blockIdx.y;
    const int b    = bh >> 4;
    const int qrow = blockIdx.x * 128 + warp * 16;
    const int len  = g_len[b];
    const int ntiles = (len + 63) >> 6;

    const size_t base = (size_t)bh * Tq * Dq;
    const uint32_t sb = (uint32_t)__cvta_generic_to_shared(smf);

    // per-thread ldmatrix byte offsets
    const uint32_t lk = ((((lane & 7) + ((lane >> 4) << 3)) * FP + ((lane >> 3) & 1) * 8)) * 2;
    const uint32_t lv = (((lane & 15) * FP + ((lane >> 4) << 3))) * 2;

    auto issue = [&](int s, int kv0) {
        #pragma unroll
        for (int i = tid; i < 2048; i += 256) {
            int arr = i >> 9, j = i & 511, r = j >> 3, c = j & 7;
            const __nv_bfloat16* src =
                (arr == 0) ? g_kh + base + (size_t)(kv0 + r)*Dq + c*8 :
                (arr == 1) ? g_kl + base + (size_t)(kv0 + r)*Dq + c*8 :
                (arr == 2) ? g_vh + base + (size_t)(kv0 + r)*Dq + c*8 :
                             g_vl + base + (size_t)(kv0 + r)*Dq + c*8;
            uint32_t dst = sb + (s*F_STAGE + arr*F_ARR + r*FP + c*8)*2;
            cp16(dst, src);
        }
        cp_commit();
    };

    // Q fragments, persistent in registers (A operand, K-dim = D = 64)
    uint32_t qh[4][4], ql[4][4];
    #pragma unroll
    for (int ks = 0; ks < 4; ks++) {
        int kc = ks*16 + c2;
        qh[ks][0] = *(const uint32_t*)&g_qh[base + (size_t)(qrow + r4    )*Dq + kc];
        qh[ks][1] = *(const uint32_t*)&g_qh[base + (size_t)(qrow + r4 + 8)*Dq + kc];
        qh[ks][2] = *(const uint32_t*)&g_qh[base + (size_t)(qrow + r4    )*Dq + kc + 8];
        qh[ks][3] = *(const uint32_t*)&g_qh[base + (size_t)(qrow + r4 + 8)*Dq + kc + 8];
        ql[ks][0] = *(const uint32_t*)&g_ql[base + (size_t)(qrow + r4    )*Dq + kc];
        ql[ks][1] = *(const uint32_t*)&g_ql[base + (size_t)(qrow + r4 + 8)*Dq + kc];
        ql[ks][2] = *(const uint32_t*)&g_ql[base + (size_t)(qrow + r4    )*Dq + kc + 8];
        ql[ks][3] = *(const uint32_t*)&g_ql[base + (size_t)(qrow + r4 + 8)*Dq + kc + 8];
    }

    float Oacc[8][4];
    #pragma unroll
    for (int i = 0; i < 8; i++)
        #pragma unroll
        for (int j = 0; j < 4; j++) Oacc[i][j] = 0.0f;
    float m_run[2] = {-CUDART_INF_F, -CUDART_INF_F};
    float l_run[2] = {0.0f, 0.0f};

    issue(0, 0);

    for (int kt = 0; kt < ntiles; kt++) {
        const int kv0 = kt * 64;
        if (kt + 1 < ntiles) { issue((kt + 1) & 1, kv0 + 64); cp_wait<1>(); }
        else                 { cp_wait<0>(); }
        __syncthreads();

        const uint32_t stg = sb + (kt & 1)*F_STAGE*2;
        const uint32_t Khb = stg;
        const uint32_t Klb = stg + F_ARR*2;
        const uint32_t Vhb = stg + 2*F_ARR*2;
        const uint32_t Vlb = stg + 3*F_ARR*2;

        // ---- S = Q K^T  (64 kv rows -> S[8][4]) ----
        float S[8][4];
        #pragma unroll
        for (int nt = 0; nt < 8; nt++)
            #pragma unroll
            for (int j = 0; j < 4; j++) S[nt][j] = 0.0f;
        #pragma unroll
        for (int ks = 0; ks < 4; ks++) {
            #pragma unroll
            for (int np = 0; np < 4; np++) {          // nt pairs
                const uint32_t off = (np*16*FP + ks*16)*2;
                uint32_t h0,h1,h2,h3, l0,l1,l2,l3;
                ldmx4(h0, h1, h2, h3, Khb + lk + off);
                ldmx4(l0, l1, l2, l3, Klb + lk + off);
                uint32_t bh0[2] = {h0, h1}, bh1[2] = {h2, h3};
                uint32_t bl0[2] = {l0, l1}, bl1[2] = {l2, l3};
                // pass-major interleave across the tile pair (distance 2)
                mma16816(S[2*np  ], qh[ks], bh0);
                mma16816(S[2*np+1], qh[ks], bh1);
                mma16816(S[2*np  ], qh[ks], bl0);
                mma16816(S[2*np+1], qh[ks], bl1);
                mma16816(S[2*np  ], ql[ks], bh0);
                mma16816(S[2*np+1], ql[ks], bh1);
            }
        }

        // ---- scale + mask + row max ----
        float rmax[2] = {-CUDART_INF_F, -CUDART_INF_F};
        #pragma unroll
        for (int nt = 0; nt < 8; nt++) {
            #pragma unroll
            for (int j = 0; j < 4; j++) {
                int kv = kv0 + nt*8 + c2 + (j & 1);
                float s = S[nt][j] * 0.125f;
                s = (kv < len) ? s : -CUDART_INF_F;
                S[nt][j] = s;
                rmax[j >> 1] = fmaxf(rmax[j >> 1], s);
            }
        }
        #pragma unroll
        for (int j = 0; j < 2; j++) {
            rmax[j] = fmaxf(rmax[j], __shfl_xor_sync(0xffffffffu, rmax[j], 1));
            rmax[j] = fmaxf(rmax[j], __shfl_xor_sync(0xffffffffu, rmax[j], 2));
        }

        float m_new[2], alpha[2];
        #pragma unroll
        for (int j = 0; j < 2; j++) {
            m_new[j] = fmaxf(m_run[j], rmax[j]);
            alpha[j] = exp2f((m_run[j] - m_new[j]) * LOG2E);
            m_run[j] = m_new[j];
        }

        // ---- exponentiate + row sum ----
        float rsum[2] = {0.0f, 0.0f};
        #pragma unroll
        for (int nt = 0; nt < 8; nt++) {
            #pragma unroll
            for (int j = 0; j < 4; j++) {
                float p = exp2f((S[nt][j] - m_new[j >> 1]) * LOG2E);
                S[nt][j] = p;
                rsum[j >> 1] += p;
            }
        }
        #pragma unroll
        for (int j = 0; j < 2; j++) {
            rsum[j] += __shfl_xor_sync(0xffffffffu, rsum[j], 1);
            rsum[j] += __shfl_xor_sync(0xffffffffu, rsum[j], 2);
            l_run[j] = l_run[j] * alpha[j] + rsum[j];
        }
        #pragma unroll
        for (int i = 0; i < 8; i++) {
            Oacc[i][0] *= alpha[0]; Oacc[i][1] *= alpha[0];
            Oacc[i][2] *= alpha[1]; Oacc[i][3] *= alpha[1];
        }

        // ---- O += P V : P frags from S in registers, V frags via ldmatrix.trans
        #pragma unroll
        for (int kk = 0; kk < 4; kk++) {              // 4 k16 steps (64 kv)
            uint32_t pah[4], pal[4];
            pack_split2(S[2*kk  ][0], S[2*kk  ][1], pah[0], pal[0]);
            pack_split2(S[2*kk  ][2], S[2*kk  ][3], pah[1], pal[1]);
            pack_split2(S[2*kk+1][0], S[2*kk+1][1], pah[2], pal[2]);
            pack_split2(S[2*kk+1][2], S[2*kk+1][3], pah[3], pal[3]);
            #pragma unroll
            for (int dp = 0; dp < 4; dp++) {          // d-block pairs
                const uint32_t off = (kk*16*FP + dp*16)*2;
                uint32_t h0,h1,h2,h3, l0,l1,l2,l3;
                ldmx4t(h0, h1, h2, h3, Vhb + lv + off);
                ldmx4t(l0, l1, l2, l3, Vlb + lv + off);
                uint32_t bh0[2] = {h0, h1}, bh1[2] = {h2, h3};
                uint32_t bl0[2] = {l0, l1}, bl1[2] = {l2, l3};
                // pass-major interleave across the tile pair (distance 2)
                mma16816(Oacc[2*dp  ], pah, bh0);
                mma16816(Oacc[2*dp+1], pah, bh1);
                mma16816(Oacc[2*dp  ], pah, bl0);
                mma16816(Oacc[2*dp+1], pah, bl1);
                mma16816(Oacc[2*dp  ], pal, bh0);
                mma16816(Oacc[2*dp+1], pal, bh1);
            }
        }
        __syncthreads();
    }

    // ---- finalize: O /= l, write ctx hi/lo bf16 [B,T,C] ----
    const float inv0 = 1.0f / l_run[0];
    const float inv1 = 1.0f / l_run[1];
    const int hh = bh & 15;
    const size_t base0 = ((size_t)(b*Tq + qrow + r4    ))*Cq + hh*Dq;
    const size_t base1 = ((size_t)(b*Tq + qrow + r4 + 8))*Cq + hh*Dq;
    #pragma unroll
    for (int ntd = 0; ntd < 8; ntd++) {
        int d0 = ntd*8 + c2;
        uint32_t hi, lo;
        pack_split2(Oacc[ntd][0]*inv0, Oacc[ntd][1]*inv0, hi, lo);
        *(uint32_t*)(g_ctxh + base0 + d0) = hi;
        *(uint32_t*)(g_ctxl + base0 + d0) = lo;
        pack_split2(Oacc[ntd][2]*inv1, Oacc[ntd][3]*inv1, hi, lo);
        *(uint32_t*)(g_ctxh + base1 + d0) = hi;
        *(uint32_t*)(g_ctxl + base1 + d0) = lo;
    }
}

// ---------------------------------------------------------------------------
extern "C" void kernel_launch(void* const* d_in, const int* in_sizes, int n_in,
                              void* d_out, int out_size)
{
    const float*         x     = (const float*)d_in[0];
    const unsigned char* mask  = (const unsigned char*)d_in[1];
    const float*         w_qkv = (const float*)d_in[2];
    const float*         w_out = (const float*)d_in[3];
    const float*         b_out = (const float*)d_in[4];
    float*               out   = (float*)d_out;

    // Same launch order as R13 (keeps gemm0 in the ncu capture slot).
    xsplit_kernel<<<(Bq*Tq*Cq)/1024, 256>>>(x, (size_t)Bq*Tq*Cq);
    wsplit_kernel<1><<<dim3(3*Cq/32, Cq/32), 256>>>(w_qkv, 3*Cq);
    len_kernel<<<Bq, 256>>>(mask);

    cudaFuncSetAttribute(mma_gemm_bf<0>,
                         cudaFuncAttributeMaxDynamicSharedMemorySize, GEMM_SMEM);
    mma_gemm_bf<0><<<dim3(3*Cq/128, Bq*Tq/128), 256, GEMM_SMEM>>>(
        nullptr, nullptr, Bq*Tq, 3*Cq, Cq);

    cudaFuncSetAttribute(flash_kernel,
                         cudaFuncAttributeMaxDynamicSharedMemorySize, FLASH_SMEM);
    flash_kernel<<<dim3(Tq/128, BHq), 256, FLASH_SMEM>>>();

    wsplit_kernel<2><<<dim3(Cq/32, Cq/32), 256>>>(w_out, Cq);

    cudaFuncSetAttribute(mma_gemm_bf<3>,
                         cudaFuncAttributeMaxDynamicSharedMemorySize, GEMM_SMEM);
    mma_gemm_bf<3><<<dim3(Cq/128, Bq*Tq/128), 256, GEMM_SMEM>>>(
        out, b_out, Bq*Tq, Cq, Cq);
}

// round 16
// speedup vs baseline: 5.4753x; 1.1741x over previous
#include <cuda_runtime.h>
#include <cuda_fp16.h>
#include <math_constants.h>
#include <stdint.h>

// Problem constants
#define Bq 4
#define Tq 2048
#define Cq 1024
#define Hq 16
#define Dq 64
#define BHq (Bq*Hq)

#define LOG2E 1.4426950408889634f

// ---------------------------------------------------------------------------
// Scratch (device globals, allocation-free). ONLY referenced from device code.
// All operands fp16 (11-bit mantissa): hi/lo split where 3/2-pass MMA needs it.
// Q and P are plain fp16 (their lo-pass is dropped: each costs ~1.5e-4).
// Weights stored TRANSPOSED: [N][K].
// ---------------------------------------------------------------------------
__device__ __half g_xh[(size_t)Bq*Tq*Cq];        // x split [M][K]
__device__ __half g_xl[(size_t)Bq*Tq*Cq];
__device__ __half g_wqh[(size_t)3*Cq*Cq];        // w_qkv^T split [3C][C]
__device__ __half g_wql[(size_t)3*Cq*Cq];
__device__ __half g_woh[(size_t)Cq*Cq];          // w_out^T split [C][C]
__device__ __half g_wol[(size_t)Cq*Cq];
__device__ __half g_qh[(size_t)BHq*Tq*Dq];       // Q plain fp16 [BH][T][D]
__device__ __half g_kh[(size_t)BHq*Tq*Dq];       // K split
__device__ __half g_kl[(size_t)BHq*Tq*Dq];
__device__ __half g_vh[(size_t)BHq*Tq*Dq];       // V split
__device__ __half g_vl[(size_t)BHq*Tq*Dq];
__device__ __half g_ctxh[(size_t)Bq*Tq*Cq];      // attention out split
__device__ __half g_ctxl[(size_t)Bq*Tq*Cq];
__device__ int g_len[Bq];

// ---------------------------------------------------------------------------
__device__ __forceinline__ void mma16816(float* d, const uint32_t* a, const uint32_t* b) {
    asm volatile(
        "mma.sync.aligned.m16n8k16.row.col.f32.f16.f16.f32 "
        "{%0,%1,%2,%3}, {%4,%5,%6,%7}, {%8,%9}, {%0,%1,%2,%3};\n"
        : "+f"(d[0]), "+f"(d[1]), "+f"(d[2]), "+f"(d[3])
        : "r"(a[0]), "r"(a[1]), "r"(a[2]), "r"(a[3]),
          "r"(b[0]), "r"(b[1]));
}

__device__ __forceinline__ void ldmx4(uint32_t& d0, uint32_t& d1, uint32_t& d2,
                                      uint32_t& d3, uint32_t addr) {
    asm volatile("ldmatrix.sync.aligned.m8n8.x4.shared.b16 {%0,%1,%2,%3}, [%4];"
        : "=r"(d0), "=r"(d1), "=r"(d2), "=r"(d3) : "r"(addr));
}
__device__ __forceinline__ void ldmx4t(uint32_t& d0, uint32_t& d1, uint32_t& d2,
                                       uint32_t& d3, uint32_t addr) {
    asm volatile("ldmatrix.sync.aligned.m8n8.x4.trans.shared.b16 {%0,%1,%2,%3}, [%4];"
        : "=r"(d0), "=r"(d1), "=r"(d2), "=r"(d3) : "r"(addr));
}

__device__ __forceinline__ void cp16(uint32_t dst, const void* src) {
    asm volatile("cp.async.cg.shared.global [%0], [%1], 16;\n" :: "r"(dst), "l"(src));
}
__device__ __forceinline__ void cp_commit() {
    asm volatile("cp.async.commit_group;\n");
}
template<int N>
__device__ __forceinline__ void cp_wait() {
    asm volatile("cp.async.wait_group %0;\n" :: "n"(N));
}

// pack two fp32 into fp16x2 hi and lo words (low half = first arg)
__device__ __forceinline__ void pack_split2(float a, float b, uint32_t& hi, uint32_t& lo) {
    __half ha = __float2half_rn(a), hb = __float2half_rn(b);
    __half la = __float2half_rn(a - __half2float(ha));
    __half lb = __float2half_rn(b - __half2float(hb));
    __half2 h2 = __halves2half2(ha, hb);
    __half2 l2 = __halves2half2(la, lb);
    hi = *reinterpret_cast<uint32_t*>(&h2);
    lo = *reinterpret_cast<uint32_t*>(&l2);
}

// pack two fp32 into ONE fp16x2 word (hi only — Q epilogue / P fragments)
__device__ __forceinline__ uint32_t pack_hi2(float a, float b) {
    __half2 h2 = __halves2half2(__float2half_rn(a), __float2half_rn(b));
    return *reinterpret_cast<uint32_t*>(&h2);
}

// ---------------------------------------------------------------------------
// x split (linear, no transpose): x -> g_xh/g_xl
// ---------------------------------------------------------------------------
__global__ void xsplit_kernel(const float* __restrict__ src, size_t n) {
    size_t i = ((size_t)blockIdx.x * blockDim.x + threadIdx.x) * 4;
    if (i >= n) return;
    float4 v = *(const float4*)(src + i);
    uint32_t h0, l0, h1, l1;
    pack_split2(v.x, v.y, h0, l0);
    pack_split2(v.z, v.w, h1, l1);
    *(uint32_t*)(g_xh + i)     = h0;
    *(uint32_t*)(g_xh + i + 2) = h1;
    *(uint32_t*)(g_xl + i)     = l0;
    *(uint32_t*)(g_xl + i + 2) = l1;
}

// ---------------------------------------------------------------------------
// Weight transpose + split: src [K=1024][N] fp32 -> dst [N][1024] fp16 hi/lo.
//   WHICH 1: w_qkv -> g_wqh/g_wql    WHICH 2: w_out -> g_woh/g_wol
// ---------------------------------------------------------------------------
template<int WHICH>
__global__ void wsplit_kernel(const float* __restrict__ src, int N) {
    __shared__ float t32[32][33];
    __half* dh = (WHICH == 1) ? g_wqh : g_woh;
    __half* dl = (WHICH == 1) ? g_wql : g_wol;
    const int k0 = blockIdx.y * 32, n0 = blockIdx.x * 32;
    const int tid = threadIdx.x;
    const int r0 = tid >> 5, c = tid & 31;
    #pragma unroll
    for (int rr = 0; rr < 4; rr++)
        t32[r0 + rr*8][c] = src[(size_t)(k0 + r0 + rr*8)*N + n0 + c];
    __syncthreads();
    const int n = tid >> 3, kq = (tid & 7) * 4;
    float v0 = t32[kq  ][n], v1 = t32[kq+1][n];
    float v2 = t32[kq+2][n], v3 = t32[kq+3][n];
    uint32_t h0, l0, h1, l1;
    pack_split2(v0, v1, h0, l0);
    pack_split2(v2, v3, h1, l1);
    size_t idx = (size_t)(n0 + n)*Cq + k0 + kq;
    *(uint2*)(dh + idx) = make_uint2(h0, h1);
    *(uint2*)(dl + idx) = make_uint2(l0, l1);
}

// ---------------------------------------------------------------------------
// Length kernel: robust to padding_mask being bool(u8), int32, or float32.
// ---------------------------------------------------------------------------
__global__ void len_kernel(const unsigned char* __restrict__ mraw) {
    __shared__ int code;
    __shared__ int partial[256];
    if (threadIdx.x == 0) {
        if (mraw[1] == 1) code = 0;
        else if (((const int*)mraw)[0] == 1) code = 1;
        else code = 2;
    }
    __syncthreads();
    const int c = code;
    const int b = blockIdx.x;
    int cnt = 0;
    for (int t = threadIdx.x; t < Tq; t += blockDim.x) {
        int idx = b * Tq + t;
        bool m;
        if (c == 0)      m = mraw[idx] != 0;
        else if (c == 1) m = ((const int*)mraw)[idx] != 0;
        else             m = ((const float*)mraw)[idx] != 0.0f;
        cnt += m ? 1 : 0;
    }
    partial[threadIdx.x] = cnt;
    __syncthreads();
    for (int s = 128; s > 0; s >>= 1) {
        if (threadIdx.x < s) partial[threadIdx.x] += partial[threadIdx.x + s];
        __syncthreads();
    }
    if (threadIdx.x == 0) g_len[b] = partial[0];
}

// ---------------------------------------------------------------------------
// Split-fp16 tensor-core GEMM (structure identical to R14: 2-stage cp.async,
// ldmatrix operands, 2 CTAs/SM, pass-major 3-pass MMA).
//   MODE 0: qkv = x @ w_qkv -> Q plain fp16, K/V hi+lo; skips masked K/V blocks.
//   MODE 3: out = ctx @ w_out + b_out (fp32 out to Cg)
// Dyn smem: 2 stages x (Ah,Al,Bh,Bl)[128][40] = 81920 B.
// ---------------------------------------------------------------------------
#define GP 40                        // smem pitch (fp16)
#define G_ARR (128*GP)               // 5120 elems per array
#define G_STAGE (4*G_ARR)            // 20480 elems per stage
#define GEMM_SMEM (2*G_STAGE*2)      // 81920 bytes

template<int MODE>
__global__ void __launch_bounds__(256, 2)
mma_gemm_bf(float* __restrict__ Cg, const float* __restrict__ bias,
            int M, int N, int K)
{
    extern __shared__ __half smg[];

    const int bm = blockIdx.y * 128;
    const int bn = blockIdx.x * 128;

    if (MODE == 0) {
        int part = bn >> 10;
        if (part >= 1 && (bm & (Tq - 1)) >= g_len[bm >> 11]) return;
    }

    const __half* Agh = (MODE == 0) ? g_xh : g_ctxh;
    const __half* Agl = (MODE == 0) ? g_xl : g_ctxl;
    const __half* Bgh = (MODE == 0) ? g_wqh : g_woh;
    const __half* Bgl = (MODE == 0) ? g_wql : g_wol;

    const int tid  = threadIdx.x;
    const int lane = tid & 31;
    const int warp = tid >> 5;
    const int wm   = warp >> 2;
    const int wn   = warp & 3;
    const int r4   = lane >> 2;
    const int c2   = (lane & 3) * 2;

    const uint32_t sb = (uint32_t)__cvta_generic_to_shared(smg);

    const uint32_t la = ((lane & 15) * GP + (lane >> 4) * 8) * 2;
    const uint32_t lb = (((lane & 7) + ((lane >> 4) << 3)) * GP + ((lane >> 3) & 1) * 8) * 2;

    auto issue = [&](int st, int k0) {
        #pragma unroll
        for (int i = tid; i < 2048; i += 256) {
            int arr = i >> 9, j = i & 511, r = j >> 2, c = j & 3;
            const __half* src =
                (arr == 0) ? Agh + (size_t)(bm + r)*K + k0 + c*8 :
                (arr == 1) ? Agl + (size_t)(bm + r)*K + k0 + c*8 :
                (arr == 2) ? Bgh + (size_t)(bn + r)*K + k0 + c*8 :
                             Bgl + (size_t)(bn + r)*K + k0 + c*8;
            uint32_t dst = sb + (st*G_STAGE + arr*G_ARR + r*GP + c*8)*2;
            cp16(dst, src);
        }
        cp_commit();
    };

    float acc[4][4][4];
    #pragma unroll
    for (int i = 0; i < 4; i++)
        #pragma unroll
        for (int j = 0; j < 4; j++)
            #pragma unroll
            for (int r = 0; r < 4; r++) acc[i][j][r] = 0.0f;

    const int NS = K / 32;
    issue(0, 0);

    for (int s = 0; s < NS; s++) {
        if (s + 1 < NS) { issue((s + 1) & 1, (s + 1) * 32); cp_wait<1>(); }
        else            { cp_wait<0>(); }
        __syncthreads();

        const uint32_t stg = sb + (s & 1)*G_STAGE*2;
        const uint32_t Ahb = stg;
        const uint32_t Alb = stg + G_ARR*2;
        const uint32_t Bhb = stg + 2*G_ARR*2;
        const uint32_t Blb = stg + 3*G_ARR*2;

        #pragma unroll
        for (int ks = 0; ks < 2; ks++) {
            uint32_t ah[4][4], al[4][4], bh[4][2], bl[4][2];
            #pragma unroll
            for (int mt = 0; mt < 4; mt++) {
                const uint32_t off = ((wm*64 + mt*16)*GP + ks*16)*2;
                ldmx4(ah[mt][0], ah[mt][1], ah[mt][2], ah[mt][3], Ahb + la + off);
                ldmx4(al[mt][0], al[mt][1], al[mt][2], al[mt][3], Alb + la + off);
            }
            #pragma unroll
            for (int np = 0; np < 2; np++) {
                const uint32_t off = ((wn*32 + np*16)*GP + ks*16)*2;
                uint32_t d0, d1, d2, d3;
                ldmx4(d0, d1, d2, d3, Bhb + lb + off);
                bh[2*np][0] = d0; bh[2*np][1] = d1;
                bh[2*np+1][0] = d2; bh[2*np+1][1] = d3;
                ldmx4(d0, d1, d2, d3, Blb + lb + off);
                bl[2*np][0] = d0; bl[2*np][1] = d1;
                bl[2*np+1][0] = d2; bl[2*np+1][1] = d3;
            }
            // pass-major 3-pass
            #pragma unroll
            for (int mt = 0; mt < 4; mt++)
                #pragma unroll
                for (int nt = 0; nt < 4; nt++)
                    mma16816(acc[mt][nt], ah[mt], bh[nt]);
            #pragma unroll
            for (int mt = 0; mt < 4; mt++)
                #pragma unroll
                for (int nt = 0; nt < 4; nt++)
                    mma16816(acc[mt][nt], ah[mt], bl[nt]);
            #pragma unroll
            for (int mt = 0; mt < 4; mt++)
                #pragma unroll
                for (int nt = 0; nt < 4; nt++)
                    mma16816(acc[mt][nt], al[mt], bh[nt]);
        }
        __syncthreads();
    }

    #pragma unroll
    for (int mt = 0; mt < 4; mt++) {
        #pragma unroll
        for (int nt = 0; nt < 4; nt++) {
            int m0 = bm + wm*64 + mt*16 + r4;
            int n0 = bn + wn*32 + nt*8 + c2;
            const float* cr = acc[mt][nt];
            #pragma unroll
            for (int half = 0; half < 2; half++) {
                int m = m0 + half*8;
                float v0 = cr[half*2], v1 = cr[half*2+1];
                if (MODE == 0) {
                    int bb = m / Tq, t = m % Tq;
                    int part = n0 >> 10, hh = (n0 & 1023) >> 6, d = n0 & 63;
                    size_t idx = ((size_t)(bb*Hq + hh)*Tq + t)*Dq + d;
                    if (part == 0) {
                        // Q: plain fp16 (lo-pass dropped in flash)
                        *(uint32_t*)(g_qh + idx) = pack_hi2(v0, v1);
                    } else {
                        __half* dsth = (part == 1) ? g_kh : g_vh;
                        __half* dstl = (part == 1) ? g_kl : g_vl;
                        uint32_t hi, lo;
                        pack_split2(v0, v1, hi, lo);
                        *(uint32_t*)(dsth + idx) = hi;
                        *(uint32_t*)(dstl + idx) = lo;
                    }
                } else {
                    *(float2*)&Cg[(size_t)m*N + n0] =
                        make_float2(v0 + bias[n0], v1 + bias[n0+1]);
                }
            }
        }
    }
}

// ---------------------------------------------------------------------------
// Fused flash attention (64-kv tiles, 2 CTAs/SM), fp16 2-pass:
//   QK^T: Qh·Kh + Qh·Kl   (Q lo dropped: ~1.5e-4)
//   PV:   Ph·Vh + Ph·Vl   (P lo dropped: ~1.5e-4)
// MMAs per warp per tile: 192 -> 128 (-33%); P pack halved; ql regs freed.
// Dyn smem: 2 stages x (Kh,Kl,Vh,Vl)[64][72] = 73728 B.
// ---------------------------------------------------------------------------
#define FP 72                         // smem pitch (fp16)
#define F_ARR (64*FP)                 // 4608 elems
#define F_STAGE (4*F_ARR)             // 18432 elems
#define FLASH_SMEM (2*F_STAGE*2)      // 73728 bytes

__global__ void __launch_bounds__(256, 2) flash_kernel() {
    extern __shared__ __half smf[];

    const int tid  = threadIdx.x;
    const int lane = tid & 31;
    const int warp = tid >> 5;
    const int r4   = lane >> 2;
    const int c2   = (lane & 3) * 2;
    const int bh   = blockIdx.y;
    const int b    = bh >> 4;
    const int qrow = blockIdx.x * 128 + warp * 16;
    const int len  = g_len[b];
    const int ntiles = (len + 63) >> 6;

    const size_t base = (size_t)bh * Tq * Dq;
    const uint32_t sb = (uint32_t)__cvta_generic_to_shared(smf);

    // per-thread ldmatrix byte offsets
    const uint32_t lk = ((((lane & 7) + ((lane >> 4) << 3)) * FP + ((lane >> 3) & 1) * 8)) * 2;
    const uint32_t lv = (((lane & 15) * FP + ((lane >> 4) << 3))) * 2;

    auto issue = [&](int s, int kv0) {
        #pragma unroll
        for (int i = tid; i < 2048; i += 256) {
            int arr = i >> 9, j = i & 511, r = j >> 3, c = j & 7;
            const __half* src =
                (arr == 0) ? g_kh + base + (size_t)(kv0 + r)*Dq + c*8 :
                (arr == 1) ? g_kl + base + (size_t)(kv0 + r)*Dq + c*8 :
                (arr == 2) ? g_vh + base + (size_t)(kv0 + r)*Dq + c*8 :
                             g_vl + base + (size_t)(kv0 + r)*Dq + c*8;
            uint32_t dst = sb + (s*F_STAGE + arr*F_ARR + r*FP + c*8)*2;
            cp16(dst, src);
        }
        cp_commit();
    };

    // Q fragments (plain fp16, A operand, K-dim = D = 64)
    uint32_t qh[4][4];
    #pragma unroll
    for (int ks = 0; ks < 4; ks++) {
        int kc = ks*16 + c2;
        qh[ks][0] = *(const uint32_t*)&g_qh[base + (size_t)(qrow + r4    )*Dq + kc];
        qh[ks][1] = *(const uint32_t*)&g_qh[base + (size_t)(qrow + r4 + 8)*Dq + kc];
        qh[ks][2] = *(const uint32_t*)&g_qh[base + (size_t)(qrow + r4    )*Dq + kc + 8];
        qh[ks][3] = *(const uint32_t*)&g_qh[base + (size_t)(qrow + r4 + 8)*Dq + kc + 8];
    }

    float Oacc[8][4];
    #pragma unroll
    for (int i = 0; i < 8; i++)
        #pragma unroll
        for (int j = 0; j < 4; j++) Oacc[i][j] = 0.0f;
    float m_run[2] = {-CUDART_INF_F, -CUDART_INF_F};
    float l_run[2] = {0.0f, 0.0f};

    issue(0, 0);

    for (int kt = 0; kt < ntiles; kt++) {
        const int kv0 = kt * 64;
        if (kt + 1 < ntiles) { issue((kt + 1) & 1, kv0 + 64); cp_wait<1>(); }
        else                 { cp_wait<0>(); }
        __syncthreads();

        const uint32_t stg = sb + (kt & 1)*F_STAGE*2;
        const uint32_t Khb = stg;
        const uint32_t Klb = stg + F_ARR*2;
        const uint32_t Vhb = stg + 2*F_ARR*2;
        const uint32_t Vlb = stg + 3*F_ARR*2;

        // ---- S = Q K^T  (2 passes: Qh·Kh + Qh·Kl) ----
        float S[8][4];
        #pragma unroll
        for (int nt = 0; nt < 8; nt++)
            #pragma unroll
            for (int j = 0; j < 4; j++) S[nt][j] = 0.0f;
        #pragma unroll
        for (int ks = 0; ks < 4; ks++) {
            #pragma unroll
            for (int np = 0; np < 4; np++) {          // nt pairs
                const uint32_t off = (np*16*FP + ks*16)*2;
                uint32_t h0,h1,h2,h3, l0,l1,l2,l3;
                ldmx4(h0, h1, h2, h3, Khb + lk + off);
                ldmx4(l0, l1, l2, l3, Klb + lk + off);
                uint32_t bh0[2] = {h0, h1}, bh1[2] = {h2, h3};
                uint32_t bl0[2] = {l0, l1}, bl1[2] = {l2, l3};
                mma16816(S[2*np  ], qh[ks], bh0);
                mma16816(S[2*np+1], qh[ks], bh1);
                mma16816(S[2*np  ], qh[ks], bl0);
                mma16816(S[2*np+1], qh[ks], bl1);
            }
        }

        // ---- scale + mask + row max ----
        float rmax[2] = {-CUDART_INF_F, -CUDART_INF_F};
        #pragma unroll
        for (int nt = 0; nt < 8; nt++) {
            #pragma unroll
            for (int j = 0; j < 4; j++) {
                int kv = kv0 + nt*8 + c2 + (j & 1);
                float s = S[nt][j] * 0.125f;
                s = (kv < len) ? s : -CUDART_INF_F;
                S[nt][j] = s;
                rmax[j >> 1] = fmaxf(rmax[j >> 1], s);
            }
        }
        #pragma unroll
        for (int j = 0; j < 2; j++) {
            rmax[j] = fmaxf(rmax[j], __shfl_xor_sync(0xffffffffu, rmax[j], 1));
            rmax[j] = fmaxf(rmax[j], __shfl_xor_sync(0xffffffffu, rmax[j], 2));
        }

        float m_new[2], alpha[2];
        #pragma unroll
        for (int j = 0; j < 2; j++) {
            m_new[j] = fmaxf(m_run[j], rmax[j]);
            alpha[j] = exp2f((m_run[j] - m_new[j]) * LOG2E);
            m_run[j] = m_new[j];
        }

        // ---- exponentiate + row sum ----
        float rsum[2] = {0.0f, 0.0f};
        #pragma unroll
        for (int nt = 0; nt < 8; nt++) {
            #pragma unroll
            for (int j = 0; j < 4; j++) {
                float p = exp2f((S[nt][j] - m_new[j >> 1]) * LOG2E);
                S[nt][j] = p;
                rsum[j >> 1] += p;
            }
        }
        #pragma unroll
        for (int j = 0; j < 2; j++) {
            rsum[j] += __shfl_xor_sync(0xffffffffu, rsum[j], 1);
            rsum[j] += __shfl_xor_sync(0xffffffffu, rsum[j], 2);
            l_run[j] = l_run[j] * alpha[j] + rsum[j];
        }
        #pragma unroll
        for (int i = 0; i < 8; i++) {
            Oacc[i][0] *= alpha[0]; Oacc[i][1] *= alpha[0];
            Oacc[i][2] *= alpha[1]; Oacc[i][3] *= alpha[1];
        }

        // ---- O += P V  (2 passes: Ph·Vh + Ph·Vl; P plain fp16) ----
        #pragma unroll
        for (int kk = 0; kk < 4; kk++) {              // 4 k16 steps (64 kv)
            uint32_t pah[4];
            pah[0] = pack_hi2(S[2*kk  ][0], S[2*kk  ][1]);
            pah[1] = pack_hi2(S[2*kk  ][2], S[2*kk  ][3]);
            pah[2] = pack_hi2(S[2*kk+1][0], S[2*kk+1][1]);
            pah[3] = pack_hi2(S[2*kk+1][2], S[2*kk+1][3]);
            #pragma unroll
            for (int dp = 0; dp < 4; dp++) {          // d-block pairs
                const uint32_t off = (kk*16*FP + dp*16)*2;
                uint32_t h0,h1,h2,h3, l0,l1,l2,l3;
                ldmx4t(h0, h1, h2, h3, Vhb + lv + off);
                ldmx4t(l0, l1, l2, l3, Vlb + lv + off);
                uint32_t bh0[2] = {h0, h1}, bh1[2] = {h2, h3};
                uint32_t bl0[2] = {l0, l1}, bl1[2] = {l2, l3};
                mma16816(Oacc[2*dp  ], pah, bh0);
                mma16816(Oacc[2*dp+1], pah, bh1);
                mma16816(Oacc[2*dp  ], pah, bl0);
                mma16816(Oacc[2*dp+1], pah, bl1);
            }
        }
        __syncthreads();
    }

    // ---- finalize: O /= l, write ctx hi/lo fp16 [B,T,C] ----
    const float inv0 = 1.0f / l_run[0];
    const float inv1 = 1.0f / l_run[1];
    const int hh = bh & 15;
    const size_t base0 = ((size_t)(b*Tq + qrow + r4    ))*Cq + hh*Dq;
    const size_t base1 = ((size_t)(b*Tq + qrow + r4 + 8))*Cq + hh*Dq;
    #pragma unroll
    for (int ntd = 0; ntd < 8; ntd++) {
        int d0 = ntd*8 + c2;
        uint32_t hi, lo;
        pack_split2(Oacc[ntd][0]*inv0, Oacc[ntd][1]*inv0, hi, lo);
        *(uint32_t*)(g_ctxh + base0 + d0) = hi;
        *(uint32_t*)(g_ctxl + base0 + d0) = lo;
        pack_split2(Oacc[ntd][2]*inv1, Oacc[ntd][3]*inv1, hi, lo);
        *(uint32_t*)(g_ctxh + base1 + d0) = hi;
        *(uint32_t*)(g_ctxl + base1 + d0) = lo;
    }
}

// ---------------------------------------------------------------------------
extern "C" void kernel_launch(void* const* d_in, const int* in_sizes, int n_in,
                              void* d_out, int out_size)
{
    const float*         x     = (const float*)d_in[0];
    const unsigned char* mask  = (const unsigned char*)d_in[1];
    const float*         w_qkv = (const float*)d_in[2];
    const float*         w_out = (const float*)d_in[3];
    const float*         b_out = (const float*)d_in[4];
    float*               out   = (float*)d_out;

    // Same launch order as R13/R14 (keeps gemm0 in the ncu capture slot).
    xsplit_kernel<<<(Bq*Tq*Cq)/1024, 256>>>(x, (size_t)Bq*Tq*Cq);
    wsplit_kernel<1><<<dim3(3*Cq/32, Cq/32), 256>>>(w_qkv, 3*Cq);
    len_kernel<<<Bq, 256>>>(mask);

    cudaFuncSetAttribute(mma_gemm_bf<0>,
                         cudaFuncAttributeMaxDynamicSharedMemorySize, GEMM_SMEM);
    mma_gemm_bf<0><<<dim3(3*Cq/128, Bq*Tq/128), 256, GEMM_SMEM>>>(
        nullptr, nullptr, Bq*Tq, 3*Cq, Cq);

    cudaFuncSetAttribute(flash_kernel,
                         cudaFuncAttributeMaxDynamicSharedMemorySize, FLASH_SMEM);
    flash_kernel<<<dim3(Tq/128, BHq), 256, FLASH_SMEM>>>();

    wsplit_kernel<2><<<dim3(Cq/32, Cq/32), 256>>>(w_out, Cq);

    cudaFuncSetAttribute(mma_gemm_bf<3>,
                         cudaFuncAttributeMaxDynamicSharedMemorySize, GEMM_SMEM);
    mma_gemm_bf<3><<<dim3(Cq/128, Bq*Tq/128), 256, GEMM_SMEM>>>(
        out, b_out, Bq*Tq, Cq, Cq);
}

// round 17
// speedup vs baseline: 6.7723x; 1.2369x over previous
#include <cuda_runtime.h>
#include <cuda_fp16.h>
#include <math_constants.h>
#include <stdint.h>

// Problem constants
#define Bq 4
#define Tq 2048
#define Cq 1024
#define Hq 16
#define Dq 64
#define BHq (Bq*Hq)

#define LOG2E 1.4426950408889634f

// ---------------------------------------------------------------------------
// Scratch (device globals, allocation-free). ONLY referenced from device code.
// fp16 operands. 2-pass split MMA everywhere: A plain fp16 (hi), B hi+lo.
// Per-pass drop cost calibrated at ~1.3e-4 (R15/R16); total budget ~3.7e-4.
// Weights stored TRANSPOSED: [N][K].
// ---------------------------------------------------------------------------
__device__ __half g_xh[(size_t)Bq*Tq*Cq];        // x plain fp16 [M][K]
__device__ __half g_wqh[(size_t)3*Cq*Cq];        // w_qkv^T split [3C][C]
__device__ __half g_wql[(size_t)3*Cq*Cq];
__device__ __half g_woh[(size_t)Cq*Cq];          // w_out^T split [C][C]
__device__ __half g_wol[(size_t)Cq*Cq];
__device__ __half g_qh[(size_t)BHq*Tq*Dq];       // Q plain fp16 [BH][T][D]
__device__ __half g_kh[(size_t)BHq*Tq*Dq];       // K split
__device__ __half g_kl[(size_t)BHq*Tq*Dq];
__device__ __half g_vh[(size_t)BHq*Tq*Dq];       // V split
__device__ __half g_vl[(size_t)BHq*Tq*Dq];
__device__ __half g_ctxh[(size_t)Bq*Tq*Cq];      // attention out plain fp16
__device__ int g_len[Bq];

// ---------------------------------------------------------------------------
__device__ __forceinline__ void mma16816(float* d, const uint32_t* a, const uint32_t* b) {
    asm volatile(
        "mma.sync.aligned.m16n8k16.row.col.f32.f16.f16.f32 "
        "{%0,%1,%2,%3}, {%4,%5,%6,%7}, {%8,%9}, {%0,%1,%2,%3};\n"
        : "+f"(d[0]), "+f"(d[1]), "+f"(d[2]), "+f"(d[3])
        : "r"(a[0]), "r"(a[1]), "r"(a[2]), "r"(a[3]),
          "r"(b[0]), "r"(b[1]));
}

__device__ __forceinline__ void ldmx4(uint32_t& d0, uint32_t& d1, uint32_t& d2,
                                      uint32_t& d3, uint32_t addr) {
    asm volatile("ldmatrix.sync.aligned.m8n8.x4.shared.b16 {%0,%1,%2,%3}, [%4];"
        : "=r"(d0), "=r"(d1), "=r"(d2), "=r"(d3) : "r"(addr));
}
__device__ __forceinline__ void ldmx4t(uint32_t& d0, uint32_t& d1, uint32_t& d2,
                                       uint32_t& d3, uint32_t addr) {
    asm volatile("ldmatrix.sync.aligned.m8n8.x4.trans.shared.b16 {%0,%1,%2,%3}, [%4];"
        : "=r"(d0), "=r"(d1), "=r"(d2), "=r"(d3) : "r"(addr));
}

__device__ __forceinline__ void cp16(uint32_t dst, const void* src) {
    asm volatile("cp.async.cg.shared.global [%0], [%1], 16;\n" :: "r"(dst), "l"(src));
}
__device__ __forceinline__ void cp_commit() {
    asm volatile("cp.async.commit_group;\n");
}
template<int N>
__device__ __forceinline__ void cp_wait() {
    asm volatile("cp.async.wait_group %0;\n" :: "n"(N));
}

// pack two fp32 into fp16x2 hi and lo words (low half = first arg)
__device__ __forceinline__ void pack_split2(float a, float b, uint32_t& hi, uint32_t& lo) {
    __half ha = __float2half_rn(a), hb = __float2half_rn(b);
    __half la = __float2half_rn(a - __half2float(ha));
    __half lb = __float2half_rn(b - __half2float(hb));
    __half2 h2 = __halves2half2(ha, hb);
    __half2 l2 = __halves2half2(la, lb);
    hi = *reinterpret_cast<uint32_t*>(&h2);
    lo = *reinterpret_cast<uint32_t*>(&l2);
}

// pack two fp32 into ONE fp16x2 word
__device__ __forceinline__ uint32_t pack_hi2(float a, float b) {
    __half2 h2 = __halves2half2(__float2half_rn(a), __float2half_rn(b));
    return *reinterpret_cast<uint32_t*>(&h2);
}

// ---------------------------------------------------------------------------
// x convert (plain fp16, no lo): x -> g_xh
// ---------------------------------------------------------------------------
__global__ void xsplit_kernel(const float* __restrict__ src, size_t n) {
    size_t i = ((size_t)blockIdx.x * blockDim.x + threadIdx.x) * 4;
    if (i >= n) return;
    float4 v = *(const float4*)(src + i);
    *(uint32_t*)(g_xh + i)     = pack_hi2(v.x, v.y);
    *(uint32_t*)(g_xh + i + 2) = pack_hi2(v.z, v.w);
}

// ---------------------------------------------------------------------------
// Weight transpose + split: src [K=1024][N] fp32 -> dst [N][1024] fp16 hi/lo.
//   WHICH 1: w_qkv -> g_wqh/g_wql    WHICH 2: w_out -> g_woh/g_wol
// ---------------------------------------------------------------------------
template<int WHICH>
__global__ void wsplit_kernel(const float* __restrict__ src, int N) {
    __shared__ float t32[32][33];
    __half* dh = (WHICH == 1) ? g_wqh : g_woh;
    __half* dl = (WHICH == 1) ? g_wql : g_wol;
    const int k0 = blockIdx.y * 32, n0 = blockIdx.x * 32;
    const int tid = threadIdx.x;
    const int r0 = tid >> 5, c = tid & 31;
    #pragma unroll
    for (int rr = 0; rr < 4; rr++)
        t32[r0 + rr*8][c] = src[(size_t)(k0 + r0 + rr*8)*N + n0 + c];
    __syncthreads();
    const int n = tid >> 3, kq = (tid & 7) * 4;
    float v0 = t32[kq  ][n], v1 = t32[kq+1][n];
    float v2 = t32[kq+2][n], v3 = t32[kq+3][n];
    uint32_t h0, l0, h1, l1;
    pack_split2(v0, v1, h0, l0);
    pack_split2(v2, v3, h1, l1);
    size_t idx = (size_t)(n0 + n)*Cq + k0 + kq;
    *(uint2*)(dh + idx) = make_uint2(h0, h1);
    *(uint2*)(dl + idx) = make_uint2(l0, l1);
}

// ---------------------------------------------------------------------------
// Length kernel: robust to padding_mask being bool(u8), int32, or float32.
// ---------------------------------------------------------------------------
__global__ void len_kernel(const unsigned char* __restrict__ mraw) {
    __shared__ int code;
    __shared__ int partial[256];
    if (threadIdx.x == 0) {
        if (mraw[1] == 1) code = 0;
        else if (((const int*)mraw)[0] == 1) code = 1;
        else code = 2;
    }
    __syncthreads();
    const int c = code;
    const int b = blockIdx.x;
    int cnt = 0;
    for (int t = threadIdx.x; t < Tq; t += blockDim.x) {
        int idx = b * Tq + t;
        bool m;
        if (c == 0)      m = mraw[idx] != 0;
        else if (c == 1) m = ((const int*)mraw)[idx] != 0;
        else             m = ((const float*)mraw)[idx] != 0.0f;
        cnt += m ? 1 : 0;
    }
    partial[threadIdx.x] = cnt;
    __syncthreads();
    for (int s = 128; s > 0; s >>= 1) {
        if (threadIdx.x < s) partial[threadIdx.x] += partial[threadIdx.x + s];
        __syncthreads();
    }
    if (threadIdx.x == 0) g_len[b] = partial[0];
}

// ---------------------------------------------------------------------------
// 2-pass fp16 tensor-core GEMM: acc += Ah·Bh + Ah·Bl (A-lo pass dropped,
// ~1.3e-4). A plain fp16, B hi+lo. 3 staged arrays (was 4): cp.async -25%,
// ldmatrix -25%, MMAs/k-chunk 48 -> 32. 2-stage pipeline, 2 CTAs/SM.
//   MODE 0: qkv = x @ w_qkv -> Q plain, K/V hi+lo; skips masked K/V blocks.
//   MODE 3: out = ctx @ w_out + b_out (fp32 out to Cg)
// Dyn smem: 2 stages x (Ah,Bh,Bl)[128][40] = 61440 B.
// ---------------------------------------------------------------------------
#define GP 40                        // smem pitch (fp16)
#define G_ARR (128*GP)               // 5120 elems per array
#define G_STAGE (3*G_ARR)            // 15360 elems per stage
#define GEMM_SMEM (2*G_STAGE*2)      // 61440 bytes

template<int MODE>
__global__ void __launch_bounds__(256, 2)
mma_gemm_bf(float* __restrict__ Cg, const float* __restrict__ bias,
            int M, int N, int K)
{
    extern __shared__ __half smg[];

    const int bm = blockIdx.y * 128;
    const int bn = blockIdx.x * 128;

    if (MODE == 0) {
        int part = bn >> 10;
        if (part >= 1 && (bm & (Tq - 1)) >= g_len[bm >> 11]) return;
    }

    const __half* Agh = (MODE == 0) ? g_xh : g_ctxh;
    const __half* Bgh = (MODE == 0) ? g_wqh : g_woh;
    const __half* Bgl = (MODE == 0) ? g_wql : g_wol;

    const int tid  = threadIdx.x;
    const int lane = tid & 31;
    const int warp = tid >> 5;
    const int wm   = warp >> 2;
    const int wn   = warp & 3;
    const int r4   = lane >> 2;
    const int c2   = (lane & 3) * 2;

    const uint32_t sb = (uint32_t)__cvta_generic_to_shared(smg);

    const uint32_t la = ((lane & 15) * GP + (lane >> 4) * 8) * 2;
    const uint32_t lb = (((lane & 7) + ((lane >> 4) << 3)) * GP + ((lane >> 3) & 1) * 8) * 2;

    auto issue = [&](int st, int k0) {
        #pragma unroll
        for (int i = tid; i < 1536; i += 256) {
            int arr = i >> 9, j = i & 511, r = j >> 2, c = j & 3;
            const __half* src =
                (arr == 0) ? Agh + (size_t)(bm + r)*K + k0 + c*8 :
                (arr == 1) ? Bgh + (size_t)(bn + r)*K + k0 + c*8 :
                             Bgl + (size_t)(bn + r)*K + k0 + c*8;
            uint32_t dst = sb + (st*G_STAGE + arr*G_ARR + r*GP + c*8)*2;
            cp16(dst, src);
        }
        cp_commit();
    };

    float acc[4][4][4];
    #pragma unroll
    for (int i = 0; i < 4; i++)
        #pragma unroll
        for (int j = 0; j < 4; j++)
            #pragma unroll
            for (int r = 0; r < 4; r++) acc[i][j][r] = 0.0f;

    const int NS = K / 32;
    issue(0, 0);

    for (int s = 0; s < NS; s++) {
        if (s + 1 < NS) { issue((s + 1) & 1, (s + 1) * 32); cp_wait<1>(); }
        else            { cp_wait<0>(); }
        __syncthreads();

        const uint32_t stg = sb + (s & 1)*G_STAGE*2;
        const uint32_t Ahb = stg;
        const uint32_t Bhb = stg + G_ARR*2;
        const uint32_t Blb = stg + 2*G_ARR*2;

        #pragma unroll
        for (int ks = 0; ks < 2; ks++) {
            uint32_t ah[4][4], bh[4][2], bl[4][2];
            #pragma unroll
            for (int mt = 0; mt < 4; mt++) {
                const uint32_t off = ((wm*64 + mt*16)*GP + ks*16)*2;
                ldmx4(ah[mt][0], ah[mt][1], ah[mt][2], ah[mt][3], Ahb + la + off);
            }
            #pragma unroll
            for (int np = 0; np < 2; np++) {
                const uint32_t off = ((wn*32 + np*16)*GP + ks*16)*2;
                uint32_t d0, d1, d2, d3;
                ldmx4(d0, d1, d2, d3, Bhb + lb + off);
                bh[2*np][0] = d0; bh[2*np][1] = d1;
                bh[2*np+1][0] = d2; bh[2*np+1][1] = d3;
                ldmx4(d0, d1, d2, d3, Blb + lb + off);
                bl[2*np][0] = d0; bl[2*np][1] = d1;
                bl[2*np+1][0] = d2; bl[2*np+1][1] = d3;
            }
            // pass-major 2-pass
            #pragma unroll
            for (int mt = 0; mt < 4; mt++)
                #pragma unroll
                for (int nt = 0; nt < 4; nt++)
                    mma16816(acc[mt][nt], ah[mt], bh[nt]);
            #pragma unroll
            for (int mt = 0; mt < 4; mt++)
                #pragma unroll
                for (int nt = 0; nt < 4; nt++)
                    mma16816(acc[mt][nt], ah[mt], bl[nt]);
        }
        __syncthreads();
    }

    #pragma unroll
    for (int mt = 0; mt < 4; mt++) {
        #pragma unroll
        for (int nt = 0; nt < 4; nt++) {
            int m0 = bm + wm*64 + mt*16 + r4;
            int n0 = bn + wn*32 + nt*8 + c2;
            const float* cr = acc[mt][nt];
            #pragma unroll
            for (int half = 0; half < 2; half++) {
                int m = m0 + half*8;
                float v0 = cr[half*2], v1 = cr[half*2+1];
                if (MODE == 0) {
                    int bb = m / Tq, t = m % Tq;
                    int part = n0 >> 10, hh = (n0 & 1023) >> 6, d = n0 & 63;
                    size_t idx = ((size_t)(bb*Hq + hh)*Tq + t)*Dq + d;
                    if (part == 0) {
                        *(uint32_t*)(g_qh + idx) = pack_hi2(v0, v1);
                    } else {
                        __half* dsth = (part == 1) ? g_kh : g_vh;
                        __half* dstl = (part == 1) ? g_kl : g_vl;
                        uint32_t hi, lo;
                        pack_split2(v0, v1, hi, lo);
                        *(uint32_t*)(dsth + idx) = hi;
                        *(uint32_t*)(dstl + idx) = lo;
                    }
                } else {
                    *(float2*)&Cg[(size_t)m*N + n0] =
                        make_float2(v0 + bias[n0], v1 + bias[n0+1]);
                }
            }
        }
    }
}

// ---------------------------------------------------------------------------
// Fused flash attention (64-kv tiles, 2 CTAs/SM), fp16 2-pass:
//   QK^T: Qh·Kh + Qh·Kl     PV: Ph·Vh + Ph·Vl
// Epilogue writes ctx as plain fp16 (ctx-lo dropped: gemm3 is 2-pass on A).
// Dyn smem: 2 stages x (Kh,Kl,Vh,Vl)[64][72] = 73728 B.
// ---------------------------------------------------------------------------
#define FP 72                         // smem pitch (fp16)
#define F_ARR (64*FP)                 // 4608 elems
#define F_STAGE (4*F_ARR)             // 18432 elems
#define FLASH_SMEM (2*F_STAGE*2)      // 73728 bytes

__global__ void __launch_bounds__(256, 2) flash_kernel() {
    extern __shared__ __half smf[];

    const int tid  = threadIdx.x;
    const int lane = tid & 31;
    const int warp = tid >> 5;
    const int r4   = lane >> 2;
    const int c2   = (lane & 3) * 2;
    const int bh   = blockIdx.y;
    const int b    = bh >> 4;
    const int qrow = blockIdx.x * 128 + warp * 16;
    const int len  = g_len[b];
    const int ntiles = (len + 63) >> 6;

    const size_t base = (size_t)bh * Tq * Dq;
    const uint32_t sb = (uint32_t)__cvta_generic_to_shared(smf);

    // per-thread ldmatrix byte offsets
    const uint32_t lk = ((((lane & 7) + ((lane >> 4) << 3)) * FP + ((lane >> 3) & 1) * 8)) * 2;
    const uint32_t lv = (((lane & 15) * FP + ((lane >> 4) << 3))) * 2;

    auto issue = [&](int s, int kv0) {
        #pragma unroll
        for (int i = tid; i < 2048; i += 256) {
            int arr = i >> 9, j = i & 511, r = j >> 3, c = j & 7;
            const __half* src =
                (arr == 0) ? g_kh + base + (size_t)(kv0 + r)*Dq + c*8 :
                (arr == 1) ? g_kl + base + (size_t)(kv0 + r)*Dq + c*8 :
                (arr == 2) ? g_vh + base + (size_t)(kv0 + r)*Dq + c*8 :
                             g_vl + base + (size_t)(kv0 + r)*Dq + c*8;
            uint32_t dst = sb + (s*F_STAGE + arr*F_ARR + r*FP + c*8)*2;
            cp16(dst, src);
        }
        cp_commit();
    };

    // Q fragments (plain fp16, A operand, K-dim = D = 64)
    uint32_t qh[4][4];
    #pragma unroll
    for (int ks = 0; ks < 4; ks++) {
        int kc = ks*16 + c2;
        qh[ks][0] = *(const uint32_t*)&g_qh[base + (size_t)(qrow + r4    )*Dq + kc];
        qh[ks][1] = *(const uint32_t*)&g_qh[base + (size_t)(qrow + r4 + 8)*Dq + kc];
        qh[ks][2] = *(const uint32_t*)&g_qh[base + (size_t)(qrow + r4    )*Dq + kc + 8];
        qh[ks][3] = *(const uint32_t*)&g_qh[base + (size_t)(qrow + r4 + 8)*Dq + kc + 8];
    }

    float Oacc[8][4];
    #pragma unroll
    for (int i = 0; i < 8; i++)
        #pragma unroll
        for (int j = 0; j < 4; j++) Oacc[i][j] = 0.0f;
    float m_run[2] = {-CUDART_INF_F, -CUDART_INF_F};
    float l_run[2] = {0.0f, 0.0f};

    issue(0, 0);

    for (int kt = 0; kt < ntiles; kt++) {
        const int kv0 = kt * 64;
        if (kt + 1 < ntiles) { issue((kt + 1) & 1, kv0 + 64); cp_wait<1>(); }
        else                 { cp_wait<0>(); }
        __syncthreads();

        const uint32_t stg = sb + (kt & 1)*F_STAGE*2;
        const uint32_t Khb = stg;
        const uint32_t Klb = stg + F_ARR*2;
        const uint32_t Vhb = stg + 2*F_ARR*2;
        const uint32_t Vlb = stg + 3*F_ARR*2;

        // ---- S = Q K^T  (2 passes: Qh·Kh + Qh·Kl) ----
        float S[8][4];
        #pragma unroll
        for (int nt = 0; nt < 8; nt++)
            #pragma unroll
            for (int j = 0; j < 4; j++) S[nt][j] = 0.0f;
        #pragma unroll
        for (int ks = 0; ks < 4; ks++) {
            #pragma unroll
            for (int np = 0; np < 4; np++) {          // nt pairs
                const uint32_t off = (np*16*FP + ks*16)*2;
                uint32_t h0,h1,h2,h3, l0,l1,l2,l3;
                ldmx4(h0, h1, h2, h3, Khb + lk + off);
                ldmx4(l0, l1, l2, l3, Klb + lk + off);
                uint32_t bh0[2] = {h0, h1}, bh1[2] = {h2, h3};
                uint32_t bl0[2] = {l0, l1}, bl1[2] = {l2, l3};
                mma16816(S[2*np  ], qh[ks], bh0);
                mma16816(S[2*np+1], qh[ks], bh1);
                mma16816(S[2*np  ], qh[ks], bl0);
                mma16816(S[2*np+1], qh[ks], bl1);
            }
        }

        // ---- scale + mask + row max ----
        float rmax[2] = {-CUDART_INF_F, -CUDART_INF_F};
        #pragma unroll
        for (int nt = 0; nt < 8; nt++) {
            #pragma unroll
            for (int j = 0; j < 4; j++) {
                int kv = kv0 + nt*8 + c2 + (j & 1);
                float s = S[nt][j] * 0.125f;
                s = (kv < len) ? s : -CUDART_INF_F;
                S[nt][j] = s;
                rmax[j >> 1] = fmaxf(rmax[j >> 1], s);
            }
        }
        #pragma unroll
        for (int j = 0; j < 2; j++) {
            rmax[j] = fmaxf(rmax[j], __shfl_xor_sync(0xffffffffu, rmax[j], 1));
            rmax[j] = fmaxf(rmax[j], __shfl_xor_sync(0xffffffffu, rmax[j], 2));
        }

        float m_new[2], alpha[2];
        #pragma unroll
        for (int j = 0; j < 2; j++) {
            m_new[j] = fmaxf(m_run[j], rmax[j]);
            alpha[j] = exp2f((m_run[j] - m_new[j]) * LOG2E);
            m_run[j] = m_new[j];
        }

        // ---- exponentiate + row sum ----
        float rsum[2] = {0.0f, 0.0f};
        #pragma unroll
        for (int nt = 0; nt < 8; nt++) {
            #pragma unroll
            for (int j = 0; j < 4; j++) {
                float p = exp2f((S[nt][j] - m_new[j >> 1]) * LOG2E);
                S[nt][j] = p;
                rsum[j >> 1] += p;
            }
        }
        #pragma unroll
        for (int j = 0; j < 2; j++) {
            rsum[j] += __shfl_xor_sync(0xffffffffu, rsum[j], 1);
            rsum[j] += __shfl_xor_sync(0xffffffffu, rsum[j], 2);
            l_run[j] = l_run[j] * alpha[j] + rsum[j];
        }
        #pragma unroll
        for (int i = 0; i < 8; i++) {
            Oacc[i][0] *= alpha[0]; Oacc[i][1] *= alpha[0];
            Oacc[i][2] *= alpha[1]; Oacc[i][3] *= alpha[1];
        }

        // ---- O += P V  (2 passes: Ph·Vh + Ph·Vl; P plain fp16) ----
        #pragma unroll
        for (int kk = 0; kk < 4; kk++) {              // 4 k16 steps (64 kv)
            uint32_t pah[4];
            pah[0] = pack_hi2(S[2*kk  ][0], S[2*kk  ][1]);
            pah[1] = pack_hi2(S[2*kk  ][2], S[2*kk  ][3]);
            pah[2] = pack_hi2(S[2*kk+1][0], S[2*kk+1][1]);
            pah[3] = pack_hi2(S[2*kk+1][2], S[2*kk+1][3]);
            #pragma unroll
            for (int dp = 0; dp < 4; dp++) {          // d-block pairs
                const uint32_t off = (kk*16*FP + dp*16)*2;
                uint32_t h0,h1,h2,h3, l0,l1,l2,l3;
                ldmx4t(h0, h1, h2, h3, Vhb + lv + off);
                ldmx4t(l0, l1, l2, l3, Vlb + lv + off);
                uint32_t bh0[2] = {h0, h1}, bh1[2] = {h2, h3};
                uint32_t bl0[2] = {l0, l1}, bl1[2] = {l2, l3};
                mma16816(Oacc[2*dp  ], pah, bh0);
                mma16816(Oacc[2*dp+1], pah, bh1);
                mma16816(Oacc[2*dp  ], pah, bl0);
                mma16816(Oacc[2*dp+1], pah, bl1);
            }
        }
        __syncthreads();
    }

    // ---- finalize: O /= l, write ctx plain fp16 [B,T,C] ----
    const float inv0 = 1.0f / l_run[0];
    const float inv1 = 1.0f / l_run[1];
    const int hh = bh & 15;
    const size_t base0 = ((size_t)(b*Tq + qrow + r4    ))*Cq + hh*Dq;
    const size_t base1 = ((size_t)(b*Tq + qrow + r4 + 8))*Cq + hh*Dq;
    #pragma unroll
    for (int ntd = 0; ntd < 8; ntd++) {
        int d0 = ntd*8 + c2;
        *(uint32_t*)(g_ctxh + base0 + d0) =
            pack_hi2(Oacc[ntd][0]*inv0, Oacc[ntd][1]*inv0);
        *(uint32_t*)(g_ctxh + base1 + d0) =
            pack_hi2(Oacc[ntd][2]*inv1, Oacc[ntd][3]*inv1);
    }
}

// ---------------------------------------------------------------------------
extern "C" void kernel_launch(void* const* d_in, const int* in_sizes, int n_in,
                              void* d_out, int out_size)
{
    const float*         x     = (const float*)d_in[0];
    const unsigned char* mask  = (const unsigned char*)d_in[1];
    const float*         w_qkv = (const float*)d_in[2];
    const float*         w_out = (const float*)d_in[3];
    const float*         b_out = (const float*)d_in[4];
    float*               out   = (float*)d_out;

    // Same launch order as R13..R16 (keeps gemm0 in the ncu capture slot).
    xsplit_kernel<<<(Bq*Tq*Cq)/1024, 256>>>(x, (size_t)Bq*Tq*Cq);
    wsplit_kernel<1><<<dim3(3*Cq/32, Cq/32), 256>>>(w_qkv, 3*Cq);
    len_kernel<<<Bq, 256>>>(mask);

    cudaFuncSetAttribute(mma_gemm_bf<0>,
                         cudaFuncAttributeMaxDynamicSharedMemorySize, GEMM_SMEM);
    mma_gemm_bf<0><<<dim3(3*Cq/128, Bq*Tq/128), 256, GEMM_SMEM>>>(
        nullptr, nullptr, Bq*Tq, 3*Cq, Cq);

    cudaFuncSetAttribute(flash_kernel,
                         cudaFuncAttributeMaxDynamicSharedMemorySize, FLASH_SMEM);
    flash_kernel<<<dim3(Tq/128, BHq), 256, FLASH_SMEM>>>();

    wsplit_kernel<2><<<dim3(Cq/32, Cq/32), 256>>>(w_out, Cq);

    cudaFuncSetAttribute(mma_gemm_bf<3>,
                         cudaFuncAttributeMaxDynamicSharedMemorySize, GEMM_SMEM);
    mma_gemm_bf<3><<<dim3(Cq/128, Bq*Tq/128), 256, GEMM_SMEM>>>(
        out, b_out, Bq*Tq, Cq, Cq);
}